// round 4
// baseline (speedup 1.0000x reference)
#include <cuda_runtime.h>
#include <math.h>

// ---------------------------------------------------------------------------
// PE_GatedBlock: B=8192, N0=128, N1=64, NS=128, NV=64
//
// Restructured as:
//   scalars[b, 0:192] = [sym-pair feats of x0 (8256) | sym-dot feats of x1 (2080)]
//                       @ WSC (10336 x 192)      (weights pre-folded w/ scales)
//   v111[b, w, k]     = cross feats (2016, antisym pairs) @ WVA (2016 x 64)
//   v011 via Z[b,v,w] = (1/128) * X0 @ w011 (viewed 128 x 4096), then
//                       v[b,w,k] += sum_v x1[b,v,k] * Z[b,v*64+w]
//   out = [silu(scalars[:,:128]) | (v111+v011) * sigmoid(scalars[:,128:])]
// ---------------------------------------------------------------------------

#define BATCH   8192
#define XDIM    320
#define NN0     128
#define NN1     64
#define NSV     192
#define NVD     64

#define NP0     8256                 // pairs u<=v over 128
#define NP1     2080                 // pairs u<=v over 64
#define NPA     2016                 // pairs u<v  over 64
#define KSC     (NP0 + NP1)          // 10336 = 323 * 32

// ---- static device scratch (allocation-free rule) -------------------------
__device__ float g_WSC[KSC * NSV];           // 7.9 MB folded scalar weights
__device__ float g_WVA[NPA * NVD];           // 0.5 MB folded antisym w111
__device__ unsigned short g_p0[NP0];
__device__ unsigned short g_p1[NP1];
__device__ unsigned short g_pa[NPA];
__device__ float g_Z[(size_t)BATCH * NN1 * NVD];   // 134 MB: Z[b, v*64+w]
__device__ float g_G[BATCH * NVD];                 // sigmoid gates

// ---- triangular index helpers ---------------------------------------------
__device__ __forceinline__ void tri_le(int p, int& u, int& v) {
    // (u<=v), p = v*(v+1)/2 + u
    int vv = (int)floorf((sqrtf(8.0f * (float)p + 1.0f) - 1.0f) * 0.5f);
    while ((vv + 1) * (vv + 2) / 2 <= p) vv++;
    while (vv * (vv + 1) / 2 > p) vv--;
    v = vv;
    u = p - vv * (vv + 1) / 2;
}
__device__ __forceinline__ void tri_lt(int p, int& u, int& v) {
    // (u<v), p = v*(v-1)/2 + u
    int vv = (int)floorf((1.0f + sqrtf(8.0f * (float)p + 1.0f)) * 0.5f);
    while ((vv + 1) * vv / 2 <= p) vv++;
    while (vv * (vv - 1) / 2 > p) vv--;
    v = vv;
    u = p - vv * (vv - 1) / 2;
}

// ---- weight folding kernels (run each launch; ~2M threads, trivial) -------
__global__ void build_wsc(const float* __restrict__ w000,
                          const float* __restrict__ w110) {
    int idx = blockIdx.x * blockDim.x + threadIdx.x;
    if (idx >= KSC * NSV) return;
    int p = idx / NSV;
    int w = idx - p * NSV;
    const float inv_sqrt2 = 0.7071067811865476f;
    if (p < NP0) {
        int u, v; tri_le(p, u, v);
        float val = w000[(u * NN0 + v) * NSV + w];
        if (u != v) val += w000[(v * NN0 + u) * NSV + w];
        g_WSC[idx] = (inv_sqrt2 / 128.0f) * val;             // (1/N0)*inv_sqrt2
        if (w == 0) g_p0[p] = (unsigned short)((u << 8) | v);
    } else {
        int q = p - NP0;
        int u, v; tri_le(q, u, v);
        float val = w110[(u * NN1 + v) * NSV + w];
        if (u != v) val += w110[(v * NN1 + u) * NSV + w];
        // (1/(N1*sqrt3)) * inv_sqrt2
        g_WSC[idx] = (inv_sqrt2 / (64.0f * 1.7320508075688772f)) * val;
        if (w == 0) g_p1[q] = (unsigned short)((u << 8) | v);
    }
}

__global__ void build_wva(const float* __restrict__ w111) {
    int idx = blockIdx.x * blockDim.x + threadIdx.x;
    if (idx >= NPA * NVD) return;
    int p = idx / NVD;
    int w = idx - p * NVD;
    int u, v; tri_lt(p, u, v);
    // (inv_sqrt2/N1) * inv_sqrt2 = 1/128
    g_WVA[idx] = (1.0f / 128.0f) *
                 (w111[(u * NN1 + v) * NVD + w] - w111[(v * NN1 + u) * NVD + w]);
    if (w == 0) g_pa[p] = (unsigned short)((u << 8) | v);
}

// ---- Z = (1/128) * X0 @ w011(128 x 4096) -----------------------------------
// grid (128, 32), 256 threads, BM=64, BN=128, K=128 (single chunk)
#define G3_SMEM ((64 * 132 + 128 * 132) * 4)
__global__ void __launch_bounds__(256) g3_kernel(const float* __restrict__ x,
                                                 const float* __restrict__ w011) {
    extern __shared__ float sm[];
    float* As = sm;                 // [64][132] (x0 tile, padded)
    float* Bs = sm + 64 * 132;      // [128][132]
    int t = threadIdx.x;
    int row0 = blockIdx.x * 64;
    int col0 = blockIdx.y * 128;

    for (int i = t; i < 2048; i += 256) {         // 64 rows x 32 float4
        int r = i >> 5, c4 = (i & 31) << 2;
        *(float4*)&As[r * 132 + c4] = *(const float4*)&x[(row0 + r) * XDIM + c4];
    }
    for (int i = t; i < 4096; i += 256) {         // 128 rows x 32 float4
        int k = i >> 5, c4 = (i & 31) << 2;
        *(float4*)&Bs[k * 132 + c4] = *(const float4*)&w011[k * 4096 + col0 + c4];
    }
    __syncthreads();

    int rg = t >> 4, cg = t & 15;
    int r0 = rg * 4, c0 = cg * 8;
    float acc[4][8];
#pragma unroll
    for (int i = 0; i < 4; i++)
#pragma unroll
        for (int j = 0; j < 8; j++) acc[i][j] = 0.0f;

#pragma unroll 4
    for (int k = 0; k < 128; k++) {
        float a[4];
#pragma unroll
        for (int i = 0; i < 4; i++) a[i] = As[(r0 + i) * 132 + k];
        float4 b0 = *(float4*)&Bs[k * 132 + c0];
        float4 b1 = *(float4*)&Bs[k * 132 + c0 + 4];
        float b[8] = {b0.x, b0.y, b0.z, b0.w, b1.x, b1.y, b1.z, b1.w};
#pragma unroll
        for (int i = 0; i < 4; i++)
#pragma unroll
            for (int j = 0; j < 8; j++) acc[i][j] += a[i] * b[j];
    }

    const float cz = 1.0f / 128.0f;   // inv_sqrt2 / sqrt(N0*N1)
#pragma unroll
    for (int i = 0; i < 4; i++) {
        float4 s0, s1;
        s0.x = acc[i][0] * cz; s0.y = acc[i][1] * cz;
        s0.z = acc[i][2] * cz; s0.w = acc[i][3] * cz;
        s1.x = acc[i][4] * cz; s1.y = acc[i][5] * cz;
        s1.z = acc[i][6] * cz; s1.w = acc[i][7] * cz;
        size_t base = (size_t)(row0 + r0 + i) * 4096 + col0 + c0;
        *(float4*)&g_Z[base]     = s0;
        *(float4*)&g_Z[base + 4] = s1;
    }
}

// ---- scalars: fused feature-build GEMM, (8192 x 10336) @ (10336 x 192) -----
// 256 blocks, 128 threads, BM=32, BN=192, BK=32, thread tile 8x6
#define A_SMEM ((32 * 321 + 32 * 32 + 32 * 192) * 4)   // 69,760 B
__global__ void __launch_bounds__(128) scalars_kernel(const float* __restrict__ x,
                                                      float* __restrict__ out) {
    extern __shared__ float sm[];
    float* Xs = sm;                  // [32][321]  full x rows (padded)
    float* As = sm + 32 * 321;       // [32 k][32 r]
    float* Bs = As + 32 * 32;        // [32 k][192 c]
    int t = threadIdx.x;
    int row0 = blockIdx.x * 32;

    for (int i = t; i < 32 * 320; i += 128) {
        int r = i / 320, c = i - r * 320;
        Xs[r * 321 + c] = x[(row0 + r) * XDIM + c];
    }
    __syncthreads();

    int rg = t >> 5, cg = t & 31;
    int r0 = rg * 8, c0 = cg * 6;
    float acc[8][6];
#pragma unroll
    for (int i = 0; i < 8; i++)
#pragma unroll
        for (int j = 0; j < 6; j++) acc[i][j] = 0.0f;

    for (int kc = 0; kc < 323; kc++) {
        int kb = kc * 32;
        // load weight tile: 32 x 192 floats = 1536 float4
        for (int i = t; i < 1536; i += 128) {
            int k = i / 48;
            int c = (i - k * 48) << 2;
            *(float4*)&Bs[k * 192 + c] = *(const float4*)&g_WSC[(kb + k) * 192 + c];
        }
        // build feature tile (1024 feats / 128 threads = 8 each)
        if (kb < NP0) {
#pragma unroll
            for (int i = 0; i < 8; i++) {
                int m = t + i * 128;
                int k = m >> 5, r = m & 31;
                unsigned int pk = g_p0[kb + k];
                As[k * 32 + r] = Xs[r * 321 + (pk >> 8)] * Xs[r * 321 + (pk & 255)];
            }
        } else {
            int qb = kb - NP0;
#pragma unroll
            for (int i = 0; i < 8; i++) {
                int m = t + i * 128;
                int k = m >> 5, r = m & 31;
                unsigned int pk = g_p1[qb + k];
                int u = pk >> 8, v = pk & 255;
                const float* xu = &Xs[r * 321 + 128 + 3 * u];
                const float* xv = &Xs[r * 321 + 128 + 3 * v];
                As[k * 32 + r] = xu[0] * xv[0] + xu[1] * xv[1] + xu[2] * xv[2];
            }
        }
        __syncthreads();

#pragma unroll 4
        for (int k = 0; k < 32; k++) {
            float4 a0 = *(float4*)&As[k * 32 + r0];
            float4 a1 = *(float4*)&As[k * 32 + r0 + 4];
            float a[8] = {a0.x, a0.y, a0.z, a0.w, a1.x, a1.y, a1.z, a1.w};
            float b[6];
#pragma unroll
            for (int j = 0; j < 6; j++) b[j] = Bs[k * 192 + c0 + j];
#pragma unroll
            for (int i = 0; i < 8; i++)
#pragma unroll
                for (int j = 0; j < 6; j++) acc[i][j] += a[i] * b[j];
        }
        __syncthreads();
    }

    // epilogue: silu for scalar outputs, sigmoid gates to g_G
#pragma unroll
    for (int i = 0; i < 8; i++) {
        int bi = row0 + r0 + i;
#pragma unroll
        for (int j = 0; j < 6; j++) {
            int c = c0 + j;
            float s = acc[i][j];
            float sg = 1.0f / (1.0f + __expf(-s));
            if (c < 128) out[bi * XDIM + c] = s * sg;
            else         g_G[bi * 64 + (c - 128)] = sg;
        }
    }
}

// ---- vectors: cross-feature GEMM + v011 contraction + gating ---------------
// 256 blocks, 128 threads, BM=32, outputs 64w x 3k; thread tile 8 rows x 2 w
__global__ void __launch_bounds__(128) vectors_kernel(const float* __restrict__ x,
                                                      float* __restrict__ out) {
    __shared__ float Xs[32 * 193];                        // x1 rows (192, padded)
    __shared__ __align__(16) float As0[1024];             // cross comp 0 [p][r]
    __shared__ __align__(16) float As1[1024];
    __shared__ __align__(16) float As2[1024];
    __shared__ __align__(16) float Bs[32 * 64];
    int t = threadIdx.x;
    int row0 = blockIdx.x * 32;

    for (int i = t; i < 32 * 192; i += 128) {
        int r = i / 192, c = i - r * 192;
        Xs[r * 193 + c] = x[(row0 + r) * XDIM + 128 + c];
    }
    __syncthreads();

    int rg = t >> 5, cg = t & 31;
    int r0 = rg * 8, w0 = cg * 2;
    float acc[8][2][3];
#pragma unroll
    for (int i = 0; i < 8; i++)
#pragma unroll
        for (int j = 0; j < 2; j++)
#pragma unroll
            for (int k = 0; k < 3; k++) acc[i][j][k] = 0.0f;

    for (int kc = 0; kc < 63; kc++) {       // 2016 / 32
        int kb = kc * 32;
        for (int i = t; i < 512; i += 128) {   // 32 x 64 floats = 512 float4
            int p = i >> 4, c = (i & 15) << 2;
            *(float4*)&Bs[p * 64 + c] = *(const float4*)&g_WVA[(kb + p) * 64 + c];
        }
#pragma unroll
        for (int i = 0; i < 8; i++) {
            int m = t + i * 128;
            int p = m >> 5, r = m & 31;
            unsigned int pk = g_pa[kb + p];
            int u = pk >> 8, v = pk & 255;
            const float* xu = &Xs[r * 193 + 3 * u];
            const float* xv = &Xs[r * 193 + 3 * v];
            float ax = xu[0], ay = xu[1], az = xu[2];
            float bx = xv[0], by = xv[1], bz = xv[2];
            As0[p * 32 + r] = ay * bz - az * by;
            As1[p * 32 + r] = az * bx - ax * bz;
            As2[p * 32 + r] = ax * by - ay * bx;
        }
        __syncthreads();

#pragma unroll 2
        for (int p = 0; p < 32; p++) {
            float2 b = *(float2*)&Bs[p * 64 + w0];
            float4 q00 = *(float4*)&As0[p * 32 + r0];
            float4 q01 = *(float4*)&As0[p * 32 + r0 + 4];
            float4 q10 = *(float4*)&As1[p * 32 + r0];
            float4 q11 = *(float4*)&As1[p * 32 + r0 + 4];
            float4 q20 = *(float4*)&As2[p * 32 + r0];
            float4 q21 = *(float4*)&As2[p * 32 + r0 + 4];
            float a0[8] = {q00.x, q00.y, q00.z, q00.w, q01.x, q01.y, q01.z, q01.w};
            float a1[8] = {q10.x, q10.y, q10.z, q10.w, q11.x, q11.y, q11.z, q11.w};
            float a2[8] = {q20.x, q20.y, q20.z, q20.w, q21.x, q21.y, q21.z, q21.w};
#pragma unroll
            for (int i = 0; i < 8; i++) {
                acc[i][0][0] += a0[i] * b.x;  acc[i][1][0] += a0[i] * b.y;
                acc[i][0][1] += a1[i] * b.x;  acc[i][1][1] += a1[i] * b.y;
                acc[i][0][2] += a2[i] * b.x;  acc[i][1][2] += a2[i] * b.y;
            }
        }
        __syncthreads();
    }

    // v011 contraction from Z + gating + store
#pragma unroll
    for (int i = 0; i < 8; i++) {
        int bi = row0 + r0 + i;
        const float* Zr = &g_Z[(size_t)bi * 4096];
        const float* Xr = &Xs[(r0 + i) * 193];
        for (int n = 0; n < 64; n++) {
            float2 z = *(const float2*)&Zr[n * 64 + w0];
            float xa = Xr[3 * n], xb = Xr[3 * n + 1], xc = Xr[3 * n + 2];
            acc[i][0][0] += xa * z.x; acc[i][0][1] += xb * z.x; acc[i][0][2] += xc * z.x;
            acc[i][1][0] += xa * z.y; acc[i][1][1] += xb * z.y; acc[i][1][2] += xc * z.y;
        }
        float g0 = g_G[bi * 64 + w0];
        float g1 = g_G[bi * 64 + w0 + 1];
#pragma unroll
        for (int k = 0; k < 3; k++) {
            out[bi * XDIM + 128 + w0 * 3 + k]       = acc[i][0][k] * g0;
            out[bi * XDIM + 128 + (w0 + 1) * 3 + k] = acc[i][1][k] * g1;
        }
    }
}

// ---------------------------------------------------------------------------
extern "C" void kernel_launch(void* const* d_in, const int* in_sizes, int n_in,
                              void* d_out, int out_size) {
    const float* x = 0;
    const float* w000 = 0;
    const float* w110 = 0;
    const float* w011 = 0;
    const float* w111 = 0;
    // identify inputs by (distinct) element counts; fall back to position
    for (int i = 0; i < n_in; i++) {
        switch (in_sizes[i]) {
            case BATCH * XDIM:       x    = (const float*)d_in[i]; break;
            case NN0 * NN0 * NSV:    w000 = (const float*)d_in[i]; break;
            case NN1 * NN1 * NSV:    w110 = (const float*)d_in[i]; break;
            case NN0 * NN1 * NVD:    w011 = (const float*)d_in[i]; break;
            case NN1 * NN1 * NVD:    w111 = (const float*)d_in[i]; break;
            default: break;
        }
    }
    if (!x)    x    = (const float*)d_in[0];
    if (!w000) w000 = (const float*)d_in[1];
    if (!w110) w110 = (const float*)d_in[2];
    if (!w011) w011 = (const float*)d_in[3];
    if (!w111) w111 = (const float*)d_in[4];
    float* out = (float*)d_out;

    cudaFuncSetAttribute(scalars_kernel,
                         cudaFuncAttributeMaxDynamicSharedMemorySize, A_SMEM);
    cudaFuncSetAttribute(g3_kernel,
                         cudaFuncAttributeMaxDynamicSharedMemorySize, G3_SMEM);

    build_wsc<<<(KSC * NSV + 255) / 256, 256>>>(w000, w110);
    build_wva<<<(NPA * NVD + 255) / 256, 256>>>(w111);
    g3_kernel<<<dim3(BATCH / 64, 4096 / 128), 256, G3_SMEM>>>(x, w011);
    scalars_kernel<<<BATCH / 32, 128, A_SMEM>>>(x, out);
    vectors_kernel<<<BATCH / 32, 128>>>(x, out);
}

// round 5
// speedup vs baseline: 1.2442x; 1.2442x over previous
#include <cuda_runtime.h>
#include <cuda_bf16.h>
#include <math.h>
#include <stdint.h>

// ---------------------------------------------------------------------------
// PE_GatedBlock: B=8192, N0=128, N1=64, NS=128, NV=64
//
//   scalars[b, 0:192] = [sym-pair feats of x0 (8256) | sym-dot feats of x1 (2080)]
//                       @ WSC (10336 x 192)   -- TENSOR CORES (bf16 hi/lo x3)
//   v111[b, w, k]     = cross feats (2016, antisym pairs) @ WVA (2016 x 64)
//   v011 via Z[b,v,w] = (1/128) * X0 @ w011 (128 x 4096), then
//                       v[b,w,k] += sum_v x1[b,v,k] * Z[b,v*64+w]
//   out = [silu(scalars[:,:128]) | (v111+v011) * sigmoid(scalars[:,128:])]
// ---------------------------------------------------------------------------

#define BATCH   8192
#define XDIM    320
#define NN0     128
#define NN1     64
#define NSV     192
#define NVD     64

#define NP0     8256                 // pairs u<=v over 128
#define NP1     2080                 // pairs u<=v over 64
#define NPA     2016                 // pairs u<v  over 64
#define KSC     (NP0 + NP1)          // 10336
#define KSC_PAD 10368                // 162 * 64 (zero-padded weights)

// ---- static device scratch (allocation-free rule) -------------------------
__device__ __nv_bfloat16 g_WSCh[KSC_PAD * NSV];     // folded scalar weights, hi
__device__ __nv_bfloat16 g_WSCl[KSC_PAD * NSV];     // folded scalar weights, lo
__device__ float g_WVA[NPA * NVD];                  // folded antisym w111
__device__ unsigned short g_sp[KSC_PAD];            // pair list (u<<8|v)
__device__ unsigned short g_pa[NPA];
__device__ float g_Z[(size_t)BATCH * NN1 * NVD];    // Z[b, v*64+w]
__device__ float g_G[BATCH * NVD];                  // sigmoid gates

// ---- triangular index helpers ---------------------------------------------
__device__ __forceinline__ void tri_le(int p, int& u, int& v) {
    int vv = (int)floorf((sqrtf(8.0f * (float)p + 1.0f) - 1.0f) * 0.5f);
    while ((vv + 1) * (vv + 2) / 2 <= p) vv++;
    while (vv * (vv + 1) / 2 > p) vv--;
    v = vv;
    u = p - vv * (vv + 1) / 2;
}
__device__ __forceinline__ void tri_lt(int p, int& u, int& v) {
    int vv = (int)floorf((1.0f + sqrtf(8.0f * (float)p + 1.0f)) * 0.5f);
    while ((vv + 1) * vv / 2 <= p) vv++;
    while (vv * (vv - 1) / 2 > p) vv--;
    v = vv;
    u = p - vv * (vv - 1) / 2;
}

// ---- weight folding: fp32 fold -> bf16 hi/lo split -------------------------
__global__ void build_wsc(const float* __restrict__ w000,
                          const float* __restrict__ w110) {
    int idx = blockIdx.x * blockDim.x + threadIdx.x;
    if (idx >= KSC_PAD * NSV) return;
    int p = idx / NSV;
    int w = idx - p * NSV;
    const float inv_sqrt2 = 0.7071067811865476f;
    float f = 0.0f;
    unsigned short pk = 0;
    if (p < NP0) {
        int u, v; tri_le(p, u, v);
        float val = w000[(u * NN0 + v) * NSV + w];
        if (u != v) val += w000[(v * NN0 + u) * NSV + w];
        f = (inv_sqrt2 / 128.0f) * val;
        pk = (unsigned short)((u << 8) | v);
    } else if (p < KSC) {
        int q = p - NP0;
        int u, v; tri_le(q, u, v);
        float val = w110[(u * NN1 + v) * NSV + w];
        if (u != v) val += w110[(v * NN1 + u) * NSV + w];
        f = (inv_sqrt2 / (64.0f * 1.7320508075688772f)) * val;
        pk = (unsigned short)((u << 8) | v);
    }
    __nv_bfloat16 h = __float2bfloat16(f);
    g_WSCh[idx] = h;
    g_WSCl[idx] = __float2bfloat16(f - __bfloat162float(h));
    if (w == 0) g_sp[p] = pk;
}

__global__ void build_wva(const float* __restrict__ w111) {
    int idx = blockIdx.x * blockDim.x + threadIdx.x;
    if (idx >= NPA * NVD) return;
    int p = idx / NVD;
    int w = idx - p * NVD;
    int u, v; tri_lt(p, u, v);
    g_WVA[idx] = (1.0f / 128.0f) *
                 (w111[(u * NN1 + v) * NVD + w] - w111[(v * NN1 + u) * NVD + w]);
    if (w == 0) g_pa[p] = (unsigned short)((u << 8) | v);
}

// ---- Z = (1/128) * X0 @ w011(128 x 4096) -----------------------------------
#define G3_SMEM ((64 * 132 + 128 * 132) * 4)
__global__ void __launch_bounds__(256) g3_kernel(const float* __restrict__ x,
                                                 const float* __restrict__ w011) {
    extern __shared__ float sm[];
    float* As = sm;                 // [64][132]
    float* Bs = sm + 64 * 132;      // [128][132]
    int t = threadIdx.x;
    int row0 = blockIdx.x * 64;
    int col0 = blockIdx.y * 128;

    for (int i = t; i < 2048; i += 256) {
        int r = i >> 5, c4 = (i & 31) << 2;
        *(float4*)&As[r * 132 + c4] = *(const float4*)&x[(row0 + r) * XDIM + c4];
    }
    for (int i = t; i < 4096; i += 256) {
        int k = i >> 5, c4 = (i & 31) << 2;
        *(float4*)&Bs[k * 132 + c4] = *(const float4*)&w011[k * 4096 + col0 + c4];
    }
    __syncthreads();

    int rg = t >> 4, cg = t & 15;
    int r0 = rg * 4, c0 = cg * 8;
    float acc[4][8];
#pragma unroll
    for (int i = 0; i < 4; i++)
#pragma unroll
        for (int j = 0; j < 8; j++) acc[i][j] = 0.0f;

#pragma unroll 4
    for (int k = 0; k < 128; k++) {
        float a[4];
#pragma unroll
        for (int i = 0; i < 4; i++) a[i] = As[(r0 + i) * 132 + k];
        float4 b0 = *(float4*)&Bs[k * 132 + c0];
        float4 b1 = *(float4*)&Bs[k * 132 + c0 + 4];
        float b[8] = {b0.x, b0.y, b0.z, b0.w, b1.x, b1.y, b1.z, b1.w};
#pragma unroll
        for (int i = 0; i < 4; i++)
#pragma unroll
            for (int j = 0; j < 8; j++) acc[i][j] += a[i] * b[j];
    }

    const float cz = 1.0f / 128.0f;
#pragma unroll
    for (int i = 0; i < 4; i++) {
        float4 s0, s1;
        s0.x = acc[i][0] * cz; s0.y = acc[i][1] * cz;
        s0.z = acc[i][2] * cz; s0.w = acc[i][3] * cz;
        s1.x = acc[i][4] * cz; s1.y = acc[i][5] * cz;
        s1.z = acc[i][6] * cz; s1.w = acc[i][7] * cz;
        size_t base = (size_t)(row0 + r0 + i) * 4096 + col0 + c0;
        *(float4*)&g_Z[base]     = s0;
        *(float4*)&g_Z[base + 4] = s1;
    }
}

// ---- scalars on tensor cores ------------------------------------------------
// C[8192x192] = feat[8192x10368] @ WSC[10368x192], bf16 hi/lo split (3 products)
// BM=64, BN=192, BK=64; 128 blocks x 256 threads; warp grid 2(M) x 4(N);
// warp tile 32x48 -> 2 m-tiles x 6 n-tiles of m16n8k16.

#define XS_STRIDE 324
#define AS_STRIDE 72      // bf16 elems; 144B rows -> ldmatrix conflict-free
#define BS_STRIDE 216     // bf16 elems; 432B rows -> ldmatrix conflict-free

#define SM_XS   0
#define SM_ASH  (SM_XS + 64 * XS_STRIDE * 4)            // 82944
#define SM_ASL  (SM_ASH + 64 * AS_STRIDE * 2)           // +9216
#define SM_BSH  (SM_ASL + 64 * AS_STRIDE * 2)           // +9216
#define SM_BSL  (SM_BSH + 64 * BS_STRIDE * 2)           // +27648
#define SM_SP   (SM_BSL + 64 * BS_STRIDE * 2)           // +27648
#define TC_SMEM (SM_SP + KSC_PAD * 2)                   // +20736 = 177408

__device__ __forceinline__ void mma_bf16(float* d, const uint32_t* a, const uint32_t* b) {
    asm volatile(
        "mma.sync.aligned.m16n8k16.row.col.f32.bf16.bf16.f32 "
        "{%0,%1,%2,%3}, {%4,%5,%6,%7}, {%8,%9}, {%0,%1,%2,%3};\n"
        : "+f"(d[0]), "+f"(d[1]), "+f"(d[2]), "+f"(d[3])
        : "r"(a[0]), "r"(a[1]), "r"(a[2]), "r"(a[3]), "r"(b[0]), "r"(b[1]));
}
__device__ __forceinline__ void ldsm_x4(uint32_t* r, uint32_t addr) {
    asm volatile("ldmatrix.sync.aligned.m8n8.x4.shared.b16 {%0,%1,%2,%3}, [%4];"
                 : "=r"(r[0]), "=r"(r[1]), "=r"(r[2]), "=r"(r[3]) : "r"(addr));
}
__device__ __forceinline__ void ldsm_x2t(uint32_t* r, uint32_t addr) {
    asm volatile("ldmatrix.sync.aligned.m8n8.x2.trans.shared.b16 {%0,%1}, [%2];"
                 : "=r"(r[0]), "=r"(r[1]) : "r"(addr));
}
// pack f0(low)/f1(high) to bf16x2, plus exact Dekker residual
__device__ __forceinline__ void split_pack(float f0, float f1,
                                           uint32_t& hp, uint32_t& lp) {
    asm("cvt.rn.satfinite.bf16x2.f32 %0, %1, %2;" : "=r"(hp) : "f"(f1), "f"(f0));
    float l0 = f0 - __uint_as_float(hp << 16);
    float l1 = f1 - __uint_as_float(hp & 0xffff0000u);
    asm("cvt.rn.satfinite.bf16x2.f32 %0, %1, %2;" : "=r"(lp) : "f"(l1), "f"(l0));
}

__global__ void __launch_bounds__(256) scalars_tc(const float* __restrict__ x,
                                                  float* __restrict__ out) {
    extern __shared__ char smr[];
    float* Xs = (float*)(smr + SM_XS);
    __nv_bfloat16* As_h = (__nv_bfloat16*)(smr + SM_ASH);
    __nv_bfloat16* As_l = (__nv_bfloat16*)(smr + SM_ASL);
    __nv_bfloat16* Bs_h = (__nv_bfloat16*)(smr + SM_BSH);
    __nv_bfloat16* Bs_l = (__nv_bfloat16*)(smr + SM_BSL);
    unsigned short* sp  = (unsigned short*)(smr + SM_SP);

    const int t = threadIdx.x;
    const int lane = t & 31, warp = t >> 5;
    const int wm = warp & 1, wn = warp >> 1;
    const int row0 = blockIdx.x * 64;

    // load x tile (64 rows x 320 floats)
    for (int i = t; i < 64 * 80; i += 256) {
        int r = i / 80, c4 = (i - r * 80) * 4;
        *(float4*)&Xs[r * XS_STRIDE + c4] =
            *(const float4*)&x[(size_t)(row0 + r) * XDIM + c4];
    }
    // load pair list
    for (int i = t; i < KSC_PAD / 2; i += 256)
        ((uint32_t*)sp)[i] = ((const uint32_t*)g_sp)[i];
    __syncthreads();

    float acc[2][6][4];
#pragma unroll
    for (int mt = 0; mt < 2; mt++)
#pragma unroll
        for (int nt = 0; nt < 6; nt++)
#pragma unroll
            for (int q = 0; q < 4; q++) acc[mt][nt][q] = 0.0f;

    const uint32_t ash_b = (uint32_t)__cvta_generic_to_shared(As_h);
    const uint32_t asl_b = (uint32_t)__cvta_generic_to_shared(As_l);
    const uint32_t bsh_b = (uint32_t)__cvta_generic_to_shared(Bs_h);
    const uint32_t bsl_b = (uint32_t)__cvta_generic_to_shared(Bs_l);

    const int kk2 = (t & 31) * 2;      // feature k-pair within chunk
    const int mg  = (t >> 5) * 8;      // feature row group

    // ldmatrix element offsets
    const int a_off = (wm * 32 + (lane & 15)) * AS_STRIDE + (lane >> 4) * 8;
    const int b_off = (lane & 15) * BS_STRIDE + wn * 48;

    for (int kb = 0; kb < 162; kb++) {
        const int k0g = kb * 64;
        // ---- B tile: 64 rows x 192 bf16, hi & lo
        for (int i = t; i < 1536; i += 256) {
            int r = i / 24, c8 = (i - r * 24) * 8;
            size_t gi = (size_t)(k0g + r) * NSV + c8;
            *(float4*)&Bs_h[r * BS_STRIDE + c8] = *(const float4*)&g_WSCh[gi];
            *(float4*)&Bs_l[r * BS_STRIDE + c8] = *(const float4*)&g_WSCl[gi];
        }
        // ---- feature tile: 64 rows x 64 k, fp32 -> bf16 hi/lo
        {
            int kg = k0g + kk2;
            unsigned int pk0 = sp[kg], pk1 = sp[kg + 1];
            int u0 = pk0 >> 8, v0 = pk0 & 255;
            int u1 = pk1 >> 8, v1 = pk1 & 255;
            if (kg < NP0) {
#pragma unroll
                for (int j = 0; j < 8; j++) {
                    int m = mg + j;
                    const float* Xr = &Xs[m * XS_STRIDE];
                    float f0 = Xr[u0] * Xr[v0];
                    float f1 = Xr[u1] * Xr[v1];
                    uint32_t hp, lp;
                    split_pack(f0, f1, hp, lp);
                    *(uint32_t*)&As_h[m * AS_STRIDE + kk2] = hp;
                    *(uint32_t*)&As_l[m * AS_STRIDE + kk2] = lp;
                }
            } else {
#pragma unroll
                for (int j = 0; j < 8; j++) {
                    int m = mg + j;
                    const float* Xr = &Xs[m * XS_STRIDE + 128];
                    const float* a0 = Xr + 3 * u0; const float* b0 = Xr + 3 * v0;
                    const float* a1 = Xr + 3 * u1; const float* b1 = Xr + 3 * v1;
                    float f0 = a0[0] * b0[0] + a0[1] * b0[1] + a0[2] * b0[2];
                    float f1 = a1[0] * b1[0] + a1[1] * b1[1] + a1[2] * b1[2];
                    uint32_t hp, lp;
                    split_pack(f0, f1, hp, lp);
                    *(uint32_t*)&As_h[m * AS_STRIDE + kk2] = hp;
                    *(uint32_t*)&As_l[m * AS_STRIDE + kk2] = lp;
                }
            }
        }
        __syncthreads();

        // ---- MMA over the 64-wide chunk (4 k16 steps)
#pragma unroll
        for (int ks = 0; ks < 4; ks++) {
            uint32_t ah[2][4], al[2][4];
#pragma unroll
            for (int mt = 0; mt < 2; mt++) {
                uint32_t eoff = (uint32_t)(a_off + mt * 16 * AS_STRIDE + ks * 16) * 2;
                ldsm_x4(ah[mt], ash_b + eoff);
                ldsm_x4(al[mt], asl_b + eoff);
            }
            uint32_t bh[6][2], bl[6][2];
#pragma unroll
            for (int nt = 0; nt < 6; nt++) {
                uint32_t eoff = (uint32_t)(b_off + ks * 16 * BS_STRIDE + nt * 8) * 2;
                ldsm_x2t(bh[nt], bsh_b + eoff);
                ldsm_x2t(bl[nt], bsl_b + eoff);
            }
#pragma unroll
            for (int mt = 0; mt < 2; mt++)
#pragma unroll
                for (int nt = 0; nt < 6; nt++) {
                    mma_bf16(acc[mt][nt], ah[mt], bh[nt]);
                    mma_bf16(acc[mt][nt], ah[mt], bl[nt]);
                    mma_bf16(acc[mt][nt], al[mt], bh[nt]);
                }
        }
        __syncthreads();
    }

    // ---- epilogue: silu -> out[:, :128], sigmoid -> g_G
#pragma unroll
    for (int mt = 0; mt < 2; mt++) {
#pragma unroll
        for (int nt = 0; nt < 6; nt++) {
            int r = row0 + wm * 32 + mt * 16 + (lane >> 2);
            int c = wn * 48 + nt * 8 + (lane & 3) * 2;
#pragma unroll
            for (int q = 0; q < 4; q++) {
                int rr = r + (q >> 1) * 8;
                int cc = c + (q & 1);
                float s = acc[mt][nt][q];
                float sg = 1.0f / (1.0f + __expf(-s));
                if (cc < 128) out[(size_t)rr * XDIM + cc] = s * sg;
                else          g_G[rr * 64 + (cc - 128)] = sg;
            }
        }
    }
}

// ---- vectors: cross-feature GEMM + v011 contraction + gating ---------------
__global__ void __launch_bounds__(128) vectors_kernel(const float* __restrict__ x,
                                                      float* __restrict__ out) {
    __shared__ float Xs[32 * 193];
    __shared__ __align__(16) float As0[1024];
    __shared__ __align__(16) float As1[1024];
    __shared__ __align__(16) float As2[1024];
    __shared__ __align__(16) float Bs[32 * 64];
    int t = threadIdx.x;
    int row0 = blockIdx.x * 32;

    for (int i = t; i < 32 * 192; i += 128) {
        int r = i / 192, c = i - r * 192;
        Xs[r * 193 + c] = x[(row0 + r) * XDIM + 128 + c];
    }
    __syncthreads();

    int rg = t >> 5, cg = t & 31;
    int r0 = rg * 8, w0 = cg * 2;
    float acc[8][2][3];
#pragma unroll
    for (int i = 0; i < 8; i++)
#pragma unroll
        for (int j = 0; j < 2; j++)
#pragma unroll
            for (int k = 0; k < 3; k++) acc[i][j][k] = 0.0f;

    for (int kc = 0; kc < 63; kc++) {
        int kb = kc * 32;
        for (int i = t; i < 512; i += 128) {
            int p = i >> 4, c = (i & 15) << 2;
            *(float4*)&Bs[p * 64 + c] = *(const float4*)&g_WVA[(kb + p) * 64 + c];
        }
#pragma unroll
        for (int i = 0; i < 8; i++) {
            int m = t + i * 128;
            int p = m >> 5, r = m & 31;
            unsigned int pk = g_pa[kb + p];
            int u = pk >> 8, v = pk & 255;
            const float* xu = &Xs[r * 193 + 3 * u];
            const float* xv = &Xs[r * 193 + 3 * v];
            float ax = xu[0], ay = xu[1], az = xu[2];
            float bx = xv[0], by = xv[1], bz = xv[2];
            As0[p * 32 + r] = ay * bz - az * by;
            As1[p * 32 + r] = az * bx - ax * bz;
            As2[p * 32 + r] = ax * by - ay * bx;
        }
        __syncthreads();

#pragma unroll 2
        for (int p = 0; p < 32; p++) {
            float2 b = *(float2*)&Bs[p * 64 + w0];
            float4 q00 = *(float4*)&As0[p * 32 + r0];
            float4 q01 = *(float4*)&As0[p * 32 + r0 + 4];
            float4 q10 = *(float4*)&As1[p * 32 + r0];
            float4 q11 = *(float4*)&As1[p * 32 + r0 + 4];
            float4 q20 = *(float4*)&As2[p * 32 + r0];
            float4 q21 = *(float4*)&As2[p * 32 + r0 + 4];
            float a0[8] = {q00.x, q00.y, q00.z, q00.w, q01.x, q01.y, q01.z, q01.w};
            float a1[8] = {q10.x, q10.y, q10.z, q10.w, q11.x, q11.y, q11.z, q11.w};
            float a2[8] = {q20.x, q20.y, q20.z, q20.w, q21.x, q21.y, q21.z, q21.w};
#pragma unroll
            for (int i = 0; i < 8; i++) {
                acc[i][0][0] += a0[i] * b.x;  acc[i][1][0] += a0[i] * b.y;
                acc[i][0][1] += a1[i] * b.x;  acc[i][1][1] += a1[i] * b.y;
                acc[i][0][2] += a2[i] * b.x;  acc[i][1][2] += a2[i] * b.y;
            }
        }
        __syncthreads();
    }

#pragma unroll
    for (int i = 0; i < 8; i++) {
        int bi = row0 + r0 + i;
        const float* Zr = &g_Z[(size_t)bi * 4096];
        const float* Xr = &Xs[(r0 + i) * 193];
        for (int n = 0; n < 64; n++) {
            float2 z = *(const float2*)&Zr[n * 64 + w0];
            float xa = Xr[3 * n], xb = Xr[3 * n + 1], xc = Xr[3 * n + 2];
            acc[i][0][0] += xa * z.x; acc[i][0][1] += xb * z.x; acc[i][0][2] += xc * z.x;
            acc[i][1][0] += xa * z.y; acc[i][1][1] += xb * z.y; acc[i][1][2] += xc * z.y;
        }
        float g0 = g_G[bi * 64 + w0];
        float g1 = g_G[bi * 64 + w0 + 1];
#pragma unroll
        for (int k = 0; k < 3; k++) {
            out[bi * XDIM + 128 + w0 * 3 + k]       = acc[i][0][k] * g0;
            out[bi * XDIM + 128 + (w0 + 1) * 3 + k] = acc[i][1][k] * g1;
        }
    }
}

// ---------------------------------------------------------------------------
extern "C" void kernel_launch(void* const* d_in, const int* in_sizes, int n_in,
                              void* d_out, int out_size) {
    const float* x = 0;
    const float* w000 = 0;
    const float* w110 = 0;
    const float* w011 = 0;
    const float* w111 = 0;
    for (int i = 0; i < n_in; i++) {
        switch (in_sizes[i]) {
            case BATCH * XDIM:       x    = (const float*)d_in[i]; break;
            case NN0 * NN0 * NSV:    w000 = (const float*)d_in[i]; break;
            case NN1 * NN1 * NSV:    w110 = (const float*)d_in[i]; break;
            case NN0 * NN1 * NVD:    w011 = (const float*)d_in[i]; break;
            case NN1 * NN1 * NVD:    w111 = (const float*)d_in[i]; break;
            default: break;
        }
    }
    if (!x)    x    = (const float*)d_in[0];
    if (!w000) w000 = (const float*)d_in[1];
    if (!w110) w110 = (const float*)d_in[2];
    if (!w011) w011 = (const float*)d_in[3];
    if (!w111) w111 = (const float*)d_in[4];
    float* out = (float*)d_out;

    cudaFuncSetAttribute(scalars_tc,
                         cudaFuncAttributeMaxDynamicSharedMemorySize, TC_SMEM);
    cudaFuncSetAttribute(g3_kernel,
                         cudaFuncAttributeMaxDynamicSharedMemorySize, G3_SMEM);

    build_wsc<<<(KSC_PAD * NSV + 255) / 256, 256>>>(w000, w110);
    build_wva<<<(NPA * NVD + 255) / 256, 256>>>(w111);
    g3_kernel<<<dim3(BATCH / 64, 4096 / 128), 256, G3_SMEM>>>(x, w011);
    scalars_tc<<<BATCH / 64, 256, TC_SMEM>>>(x, out);
    vectors_kernel<<<BATCH / 32, 128>>>(x, out);
}

// round 9
// speedup vs baseline: 1.6028x; 1.2882x over previous
#include <cuda_runtime.h>
#include <cuda_bf16.h>
#include <math.h>
#include <stdint.h>

// ---------------------------------------------------------------------------
// PE_GatedBlock: B=8192, N0=128, N1=64, NS=128, NV=64
//   scalars = [sym-pair feats x0 | sym-dot feats x1] @ WSC
//             (mma.sync bf16 hi/lo x3, cp.async double-buffered pipeline)
//   v111    = cross feats @ WVA (fp32 CUDA cores)
//   v011 via Z = (1/128) x0 @ w011, then per-row contraction with x1
//   out = [silu(s[:,:128]) | (v111+v011)*sigmoid(s[:,128:])]
// NOTE: harness ptxas targets sm_103 (no 'a') -> tcgen05 unavailable; use mma.sync.
// R8 bugfix: fetch_B loaded only 768/1536 16B chunks (cols 96..191 garbage -> NaN).
// ---------------------------------------------------------------------------

#define BATCH   8192
#define XDIM    320
#define NN0     128
#define NN1     64
#define NSV     192
#define NVD     64

#define NP0     8256
#define NP1     2080
#define NPA     2016
#define KSC     (NP0 + NP1)          // 10336
#define KSC_PAD 10368                // 162*64 ; NP0 = 129*64 exactly
#define NCHUNK  162
#define NCH0    129                  // chunks 0..128 are x0-pairs, 129.. are x1-dots

// ---- static device scratch -------------------------------------------------
__device__ __align__(16) __nv_bfloat16 g_WSCh[KSC_PAD * NSV];   // [k][n] hi
__device__ __align__(16) __nv_bfloat16 g_WSCl[KSC_PAD * NSV];   // [k][n] lo
__device__ float g_WVA[NPA * NVD];
__device__ __align__(4) unsigned short g_sp[KSC_PAD];
__device__ unsigned short g_pa[NPA];
__device__ float g_Z[(size_t)BATCH * NN1 * NVD];
__device__ float g_G[BATCH * NVD];

// ---- triangular index helpers ----------------------------------------------
__device__ __forceinline__ void tri_le(int p, int& u, int& v) {
    int vv = (int)floorf((sqrtf(8.0f * (float)p + 1.0f) - 1.0f) * 0.5f);
    while ((vv + 1) * (vv + 2) / 2 <= p) vv++;
    while (vv * (vv + 1) / 2 > p) vv--;
    v = vv;
    u = p - vv * (vv + 1) / 2;
}
__device__ __forceinline__ void tri_lt(int p, int& u, int& v) {
    int vv = (int)floorf((1.0f + sqrtf(8.0f * (float)p + 1.0f)) * 0.5f);
    while ((vv + 1) * vv / 2 <= p) vv++;
    while (vv * (vv - 1) / 2 > p) vv--;
    v = vv;
    u = p - vv * (vv - 1) / 2;
}

// ---- weight folding: fp32 fold -> bf16 hi/lo split, k-major [k][192] --------
__global__ void build_wsc(const float* __restrict__ w000,
                          const float* __restrict__ w110) {
    int idx = blockIdx.x * blockDim.x + threadIdx.x;
    if (idx >= KSC_PAD * NSV) return;
    int p = idx / NSV;
    int w = idx - p * NSV;
    const float inv_sqrt2 = 0.7071067811865476f;
    float f = 0.0f;
    unsigned short pk = 0;
    if (p < NP0) {
        int u, v; tri_le(p, u, v);
        float val = w000[(u * NN0 + v) * NSV + w];
        if (u != v) val += w000[(v * NN0 + u) * NSV + w];
        f = (inv_sqrt2 / 128.0f) * val;
        pk = (unsigned short)((u << 8) | v);
    } else if (p < KSC) {
        int q = p - NP0;
        int u, v; tri_le(q, u, v);
        float val = w110[(u * NN1 + v) * NSV + w];
        if (u != v) val += w110[(v * NN1 + u) * NSV + w];
        f = (inv_sqrt2 / (64.0f * 1.7320508075688772f)) * val;
        pk = (unsigned short)((u << 8) | v);
    }
    __nv_bfloat16 h = __float2bfloat16(f);
    g_WSCh[idx] = h;
    g_WSCl[idx] = __float2bfloat16(f - __bfloat162float(h));
    if (w == 0) g_sp[p] = pk;
}

__global__ void build_wva(const float* __restrict__ w111) {
    int idx = blockIdx.x * blockDim.x + threadIdx.x;
    if (idx >= NPA * NVD) return;
    int p = idx / NVD;
    int w = idx - p * NVD;
    int u, v; tri_lt(p, u, v);
    g_WVA[idx] = (1.0f / 128.0f) *
                 (w111[(u * NN1 + v) * NVD + w] - w111[(v * NN1 + u) * NVD + w]);
    if (w == 0) g_pa[p] = (unsigned short)((u << 8) | v);
}

// ---- Z = (1/128) * X0 @ w011(128 x 4096) ------------------------------------
#define G3_SMEM ((64 * 132 + 128 * 132) * 4)
__global__ void __launch_bounds__(256) g3_kernel(const float* __restrict__ x,
                                                 const float* __restrict__ w011) {
    extern __shared__ float g3sm[];
    float* As = g3sm;
    float* Bs = g3sm + 64 * 132;
    int t = threadIdx.x;
    int row0 = blockIdx.x * 64;
    int col0 = blockIdx.y * 128;

    for (int i = t; i < 2048; i += 256) {
        int r = i >> 5, c4 = (i & 31) << 2;
        *(float4*)&As[r * 132 + c4] = *(const float4*)&x[(row0 + r) * XDIM + c4];
    }
    for (int i = t; i < 4096; i += 256) {
        int k = i >> 5, c4 = (i & 31) << 2;
        *(float4*)&Bs[k * 132 + c4] = *(const float4*)&w011[k * 4096 + col0 + c4];
    }
    __syncthreads();

    int rg = t >> 4, cg = t & 15;
    int r0 = rg * 4, c0 = cg * 8;
    float acc[4][8];
#pragma unroll
    for (int i = 0; i < 4; i++)
#pragma unroll
        for (int j = 0; j < 8; j++) acc[i][j] = 0.0f;

#pragma unroll 4
    for (int k = 0; k < 128; k++) {
        float a[4];
#pragma unroll
        for (int i = 0; i < 4; i++) a[i] = As[(r0 + i) * 132 + k];
        float4 b0 = *(float4*)&Bs[k * 132 + c0];
        float4 b1 = *(float4*)&Bs[k * 132 + c0 + 4];
        float b[8] = {b0.x, b0.y, b0.z, b0.w, b1.x, b1.y, b1.z, b1.w};
#pragma unroll
        for (int i = 0; i < 4; i++)
#pragma unroll
            for (int j = 0; j < 8; j++) acc[i][j] += a[i] * b[j];
    }

    const float cz = 1.0f / 128.0f;
#pragma unroll
    for (int i = 0; i < 4; i++) {
        float4 s0, s1;
        s0.x = acc[i][0] * cz; s0.y = acc[i][1] * cz;
        s0.z = acc[i][2] * cz; s0.w = acc[i][3] * cz;
        s1.x = acc[i][4] * cz; s1.y = acc[i][5] * cz;
        s1.z = acc[i][6] * cz; s1.w = acc[i][7] * cz;
        size_t base = (size_t)(row0 + r0 + i) * 4096 + col0 + c0;
        *(float4*)&g_Z[base]     = s0;
        *(float4*)&g_Z[base + 4] = s1;
    }
}

// ---- scalars: pipelined mma.sync GEMM ---------------------------------------
// C[8192x192] = feat[8192x10368] @ WSC[10368x192], bf16 hi/lo (3 products)
// BM=64, BN=192, BK=64; 128 CTAs x 256 thr; warp grid 2(M)x4(N); warp tile 32x48.
// Pipeline: cp.async B (2-stage) + double-buffered feature tile; 1 bar/chunk.

#define AS_STRIDE 72      // bf16; 144B rows -> ldmatrix conflict-free
#define BS_STRIDE 216     // bf16; 432B rows -> ldmatrix conflict-free

#define SM_XS   0                           // p1: 64x132 f32; p2: 64x196 f32
#define SM_AH0  50176
#define SM_AL0  59392
#define SM_AH1  68608
#define SM_AL1  77824
#define SM_BH0  87040
#define SM_BL0  114688
#define SM_BH1  142336
#define SM_BL1  169984
#define TC_SMEM 197632

__device__ __forceinline__ void mma_bf16(float* d, const uint32_t* a, const uint32_t* b) {
    asm volatile(
        "mma.sync.aligned.m16n8k16.row.col.f32.bf16.bf16.f32 "
        "{%0,%1,%2,%3}, {%4,%5,%6,%7}, {%8,%9}, {%0,%1,%2,%3};\n"
        : "+f"(d[0]), "+f"(d[1]), "+f"(d[2]), "+f"(d[3])
        : "r"(a[0]), "r"(a[1]), "r"(a[2]), "r"(a[3]), "r"(b[0]), "r"(b[1]));
}
__device__ __forceinline__ void ldsm_x4(uint32_t* r, uint32_t addr) {
    asm volatile("ldmatrix.sync.aligned.m8n8.x4.shared.b16 {%0,%1,%2,%3}, [%4];"
                 : "=r"(r[0]), "=r"(r[1]), "=r"(r[2]), "=r"(r[3]) : "r"(addr));
}
__device__ __forceinline__ void ldsm_x2t(uint32_t* r, uint32_t addr) {
    asm volatile("ldmatrix.sync.aligned.m8n8.x2.trans.shared.b16 {%0,%1}, [%2];"
                 : "=r"(r[0]), "=r"(r[1]) : "r"(addr));
}
__device__ __forceinline__ void cp16(uint32_t dst, const void* src) {
    asm volatile("cp.async.cg.shared.global [%0], [%1], 16;"
                 :: "r"(dst), "l"(src) : "memory");
}
// pack f0(low half)/f1(high half) to bf16x2 + exact Dekker residual
__device__ __forceinline__ void split_pack(float f0, float f1,
                                           uint32_t& hp, uint32_t& lp) {
    asm("cvt.rn.satfinite.bf16x2.f32 %0, %1, %2;" : "=r"(hp) : "f"(f1), "f"(f0));
    float l0 = f0 - __uint_as_float(hp << 16);
    float l1 = f1 - __uint_as_float(hp & 0xffff0000u);
    asm("cvt.rn.satfinite.bf16x2.f32 %0, %1, %2;" : "=r"(lp) : "f"(l1), "f"(l0));
}

__global__ void __launch_bounds__(256) scalars_tc8(const float* __restrict__ x,
                                                   float* __restrict__ out) {
    extern __shared__ char tcsm[];
    float* Xs = (float*)(tcsm + SM_XS);
    const int t = threadIdx.x;
    const int lane = t & 31, warp = t >> 5;
    const int wm = warp & 1, wn = warp >> 1;
    const int row0 = blockIdx.x * 64;

    uint32_t sb;
    asm("{ .reg .u64 u; cvta.to.shared.u64 u, %1; cvt.u32.u64 %0, u; }"
        : "=r"(sb) : "l"(tcsm));

    const uint32_t AH[2] = {sb + SM_AH0, sb + SM_AH1};
    const uint32_t AL[2] = {sb + SM_AL0, sb + SM_AL1};
    const uint32_t BH[2] = {sb + SM_BH0, sb + SM_BH1};
    const uint32_t BL[2] = {sb + SM_BL0, sb + SM_BL1};

    // ---- phase-1 x tile: x0 (64 rows x 128 f32, stride 132)
    for (int i = t; i < 64 * 32; i += 256) {
        int r = i >> 5, c4 = (i & 31) << 2;
        *(float4*)&Xs[r * 132 + c4] =
            *(const float4*)&x[(size_t)(row0 + r) * XDIM + c4];
    }
    __syncthreads();

    // per-thread feature-build coordinates: 2 k's (lane), 8 m rows (warp)
    const int kk2 = lane * 2;
    const int mg = warp * 8;

    // A-tile builder (chunk c into stage st)
    auto build_A = [&](int c, int st) {
        char* ah = tcsm + (st ? SM_AH1 : SM_AH0);
        char* al = tcsm + (st ? SM_AL1 : SM_AL0);
        int kg = c * 64 + kk2;
        uint32_t pk = __ldg((const uint32_t*)&g_sp[kg]);
        int u0 = (pk >> 8) & 255, v0 = pk & 255;
        int u1 = pk >> 24,       v1 = (pk >> 16) & 255;
        if (c < NCH0) {
#pragma unroll
            for (int j = 0; j < 8; j++) {
                int m = mg + j;
                const float* Xr = Xs + m * 132;
                float f0 = Xr[u0] * Xr[v0];
                float f1 = Xr[u1] * Xr[v1];
                uint32_t hp, lp; split_pack(f0, f1, hp, lp);
                *(uint32_t*)(ah + m * (AS_STRIDE * 2) + kk2 * 2) = hp;
                *(uint32_t*)(al + m * (AS_STRIDE * 2) + kk2 * 2) = lp;
            }
        } else {
#pragma unroll
            for (int j = 0; j < 8; j++) {
                int m = mg + j;
                const float* Xr = Xs + m * 196;
                const float* a0 = Xr + 3 * u0; const float* b0 = Xr + 3 * v0;
                const float* a1 = Xr + 3 * u1; const float* b1 = Xr + 3 * v1;
                float f0 = a0[0] * b0[0] + a0[1] * b0[1] + a0[2] * b0[2];
                float f1 = a1[0] * b1[0] + a1[1] * b1[1] + a1[2] * b1[2];
                uint32_t hp, lp; split_pack(f0, f1, hp, lp);
                *(uint32_t*)(ah + m * (AS_STRIDE * 2) + kk2 * 2) = hp;
                *(uint32_t*)(al + m * (AS_STRIDE * 2) + kk2 * 2) = lp;
            }
        }
    };
    // B tile: 64 rows x 192 bf16 = 1536 16B-chunks per buffer (hi & lo)
    auto fetch_B = [&](int c, int st) {
        const uint32_t bh = BH[st], bl = BL[st];
        const int k0 = c * 64;
#pragma unroll
        for (int j = 0; j < 6; j++) {
            int i = t + j * 256;                     // 0..1535
            int r = i / 24, cc = (i - r * 24) * 8;   // row 0..63, col-elem 0..184
            uint32_t doff = (uint32_t)(r * (BS_STRIDE * 2) + cc * 2);
            size_t gi = (size_t)(k0 + r) * NSV + cc;
            cp16(bh + doff, g_WSCh + gi);
            cp16(bl + doff, g_WSCl + gi);
        }
        asm volatile("cp.async.commit_group;" ::: "memory");
    };

    float acc[2][6][4];
#pragma unroll
    for (int mt = 0; mt < 2; mt++)
#pragma unroll
        for (int nt = 0; nt < 6; nt++)
#pragma unroll
            for (int q = 0; q < 4; q++) acc[mt][nt][q] = 0.0f;

    // ldmatrix element offsets (within a stage tile)
    const uint32_t a_eoff = (uint32_t)((wm * 32 + (lane & 15)) * AS_STRIDE +
                                       (lane >> 4) * 8) * 2;
    const uint32_t b_eoff = (uint32_t)((lane & 15) * BS_STRIDE + wn * 48) * 2;

    // ---- prologue: stage 0 = chunk 0
    fetch_B(0, 0);
    build_A(0, 0);
    asm volatile("cp.async.wait_group 0;" ::: "memory");
    __syncthreads();

    for (int i = 0; i < NCHUNK; i++) {
        const int s = i & 1;
        // prefetch chunk i+1 into stage s^1
        if (i + 1 < NCHUNK) {
            if (i + 1 == NCH0) {
                // switch x tile to x1 (64 rows x 192 f32, stride 196);
                // all reads of the x0 tile finished before last chunk's sync
                for (int j = t; j < 64 * 48; j += 256) {
                    int r = j / 48, c4 = (j - r * 48) << 2;
                    *(float4*)&Xs[r * 196 + c4] =
                        *(const float4*)&x[(size_t)(row0 + r) * XDIM + 128 + c4];
                }
                __syncthreads();
            }
            fetch_B(i + 1, s ^ 1);
            build_A(i + 1, s ^ 1);
        }

        // ---- MMA chunk i from stage s (4 k16 steps x 3 split products)
#pragma unroll
        for (int ks = 0; ks < 4; ks++) {
            uint32_t ah[2][4], al[2][4];
#pragma unroll
            for (int mt = 0; mt < 2; mt++) {
                uint32_t eo = a_eoff + (uint32_t)(mt * 16 * AS_STRIDE + ks * 16) * 2;
                ldsm_x4(ah[mt], AH[s] + eo);
                ldsm_x4(al[mt], AL[s] + eo);
            }
            uint32_t bh[6][2], bl[6][2];
#pragma unroll
            for (int nt = 0; nt < 6; nt++) {
                uint32_t eo = b_eoff + (uint32_t)(ks * 16 * BS_STRIDE + nt * 8) * 2;
                ldsm_x2t(bh[nt], BH[s] + eo);
                ldsm_x2t(bl[nt], BL[s] + eo);
            }
#pragma unroll
            for (int mt = 0; mt < 2; mt++)
#pragma unroll
                for (int nt = 0; nt < 6; nt++) {
                    mma_bf16(acc[mt][nt], ah[mt], bh[nt]);
                    mma_bf16(acc[mt][nt], ah[mt], bl[nt]);
                    mma_bf16(acc[mt][nt], al[mt], bh[nt]);
                }
        }

        if (i + 1 < NCHUNK) {
            asm volatile("cp.async.wait_group 0;" ::: "memory");
            __syncthreads();
        }
    }

    // ---- epilogue: silu -> out[:, :128], sigmoid -> g_G
#pragma unroll
    for (int mt = 0; mt < 2; mt++) {
#pragma unroll
        for (int nt = 0; nt < 6; nt++) {
            int r = row0 + wm * 32 + mt * 16 + (lane >> 2);
            int c = wn * 48 + nt * 8 + (lane & 3) * 2;
#pragma unroll
            for (int q = 0; q < 4; q++) {
                int rr = r + (q >> 1) * 8;
                int cc = c + (q & 1);
                float s = acc[mt][nt][q];
                float sg = 1.0f / (1.0f + __expf(-s));
                if (cc < 128) out[(size_t)rr * XDIM + cc] = s * sg;
                else          g_G[rr * 64 + (cc - 128)] = sg;
            }
        }
    }
}

// ---- vectors: cross-feature GEMM + v011 contraction + gating ----------------
__global__ void __launch_bounds__(128) vectors_kernel(const float* __restrict__ x,
                                                      float* __restrict__ out) {
    __shared__ float Xs[32 * 193];
    __shared__ __align__(16) float As0[1024];
    __shared__ __align__(16) float As1[1024];
    __shared__ __align__(16) float As2[1024];
    __shared__ __align__(16) float Bs[32 * 64];
    int t = threadIdx.x;
    int row0 = blockIdx.x * 32;

    for (int i = t; i < 32 * 192; i += 128) {
        int r = i / 192, c = i - r * 192;
        Xs[r * 193 + c] = x[(row0 + r) * XDIM + 128 + c];
    }
    __syncthreads();

    int rg = t >> 5, cg = t & 31;
    int r0 = rg * 8, w0 = cg * 2;
    float acc[8][2][3];
#pragma unroll
    for (int i = 0; i < 8; i++)
#pragma unroll
        for (int j = 0; j < 2; j++)
#pragma unroll
            for (int k = 0; k < 3; k++) acc[i][j][k] = 0.0f;

    for (int kc = 0; kc < 63; kc++) {
        int kb = kc * 32;
        for (int i = t; i < 512; i += 128) {
            int p = i >> 4, c = (i & 15) << 2;
            *(float4*)&Bs[p * 64 + c] = *(const float4*)&g_WVA[(kb + p) * 64 + c];
        }
#pragma unroll
        for (int i = 0; i < 8; i++) {
            int m = t + i * 128;
            int p = m >> 5, r = m & 31;
            unsigned int pk = g_pa[kb + p];
            int u = pk >> 8, v = pk & 255;
            const float* xu = &Xs[r * 193 + 3 * u];
            const float* xv = &Xs[r * 193 + 3 * v];
            float ax = xu[0], ay = xu[1], az = xu[2];
            float bx = xv[0], by = xv[1], bz = xv[2];
            As0[p * 32 + r] = ay * bz - az * by;
            As1[p * 32 + r] = az * bx - ax * bz;
            As2[p * 32 + r] = ax * by - ay * bx;
        }
        __syncthreads();

#pragma unroll 2
        for (int p = 0; p < 32; p++) {
            float2 b = *(float2*)&Bs[p * 64 + w0];
            float4 q00 = *(float4*)&As0[p * 32 + r0];
            float4 q01 = *(float4*)&As0[p * 32 + r0 + 4];
            float4 q10 = *(float4*)&As1[p * 32 + r0];
            float4 q11 = *(float4*)&As1[p * 32 + r0 + 4];
            float4 q20 = *(float4*)&As2[p * 32 + r0];
            float4 q21 = *(float4*)&As2[p * 32 + r0 + 4];
            float a0[8] = {q00.x, q00.y, q00.z, q00.w, q01.x, q01.y, q01.z, q01.w};
            float a1[8] = {q10.x, q10.y, q10.z, q10.w, q11.x, q11.y, q11.z, q11.w};
            float a2[8] = {q20.x, q20.y, q20.z, q20.w, q21.x, q21.y, q21.z, q21.w};
#pragma unroll
            for (int i = 0; i < 8; i++) {
                acc[i][0][0] += a0[i] * b.x;  acc[i][1][0] += a0[i] * b.y;
                acc[i][0][1] += a1[i] * b.x;  acc[i][1][1] += a1[i] * b.y;
                acc[i][0][2] += a2[i] * b.x;  acc[i][1][2] += a2[i] * b.y;
            }
        }
        __syncthreads();
    }

#pragma unroll
    for (int i = 0; i < 8; i++) {
        int bi = row0 + r0 + i;
        const float* Zr = &g_Z[(size_t)bi * 4096];
        const float* Xr = &Xs[(r0 + i) * 193];
        for (int n = 0; n < 64; n++) {
            float2 z = *(const float2*)&Zr[n * 64 + w0];
            float xa = Xr[3 * n], xb = Xr[3 * n + 1], xc = Xr[3 * n + 2];
            acc[i][0][0] += xa * z.x; acc[i][0][1] += xb * z.x; acc[i][0][2] += xc * z.x;
            acc[i][1][0] += xa * z.y; acc[i][1][1] += xb * z.y; acc[i][1][2] += xc * z.y;
        }
        float g0 = g_G[bi * 64 + w0];
        float g1 = g_G[bi * 64 + w0 + 1];
#pragma unroll
        for (int k = 0; k < 3; k++) {
            out[bi * XDIM + 128 + w0 * 3 + k]       = acc[i][0][k] * g0;
            out[bi * XDIM + 128 + (w0 + 1) * 3 + k] = acc[i][1][k] * g1;
        }
    }
}

// ---------------------------------------------------------------------------
extern "C" void kernel_launch(void* const* d_in, const int* in_sizes, int n_in,
                              void* d_out, int out_size) {
    const float* x = 0;
    const float* w000 = 0;
    const float* w110 = 0;
    const float* w011 = 0;
    const float* w111 = 0;
    for (int i = 0; i < n_in; i++) {
        switch (in_sizes[i]) {
            case BATCH * XDIM:       x    = (const float*)d_in[i]; break;
            case NN0 * NN0 * NSV:    w000 = (const float*)d_in[i]; break;
            case NN1 * NN1 * NSV:    w110 = (const float*)d_in[i]; break;
            case NN0 * NN1 * NVD:    w011 = (const float*)d_in[i]; break;
            case NN1 * NN1 * NVD:    w111 = (const float*)d_in[i]; break;
            default: break;
        }
    }
    if (!x)    x    = (const float*)d_in[0];
    if (!w000) w000 = (const float*)d_in[1];
    if (!w110) w110 = (const float*)d_in[2];
    if (!w011) w011 = (const float*)d_in[3];
    if (!w111) w111 = (const float*)d_in[4];
    float* out = (float*)d_out;

    cudaFuncSetAttribute(scalars_tc8,
                         cudaFuncAttributeMaxDynamicSharedMemorySize, TC_SMEM);
    cudaFuncSetAttribute(g3_kernel,
                         cudaFuncAttributeMaxDynamicSharedMemorySize, G3_SMEM);

    build_wsc<<<(KSC_PAD * NSV + 255) / 256, 256>>>(w000, w110);
    build_wva<<<(NPA * NVD + 255) / 256, 256>>>(w111);
    g3_kernel<<<dim3(BATCH / 64, 4096 / 128), 256, G3_SMEM>>>(x, w011);
    scalars_tc8<<<BATCH / 64, 256, TC_SMEM>>>(x, out);
    vectors_kernel<<<BATCH / 32, 128>>>(x, out);
}

// round 10
// speedup vs baseline: 2.1548x; 1.3444x over previous
#include <cuda_runtime.h>
#include <cuda_bf16.h>
#include <math.h>
#include <stdint.h>

// ---------------------------------------------------------------------------
// PE_GatedBlock: B=8192, N0=128, N1=64, NS=128, NV=64
//   scalars = [sym-pair feats x0 | sym-dot feats x1] @ WSC
//             (mma.sync bf16 hi/lo x3, cp.async double-buffered, 512 thr)
//   Z = (1/128) x0 @ w011  (tensor-core bf16 hi/lo x3, K=128 single pass)
//   v111 = cross feats @ WVA (fp32 CUDA cores) ; v011 from Z contraction
//   out = [silu(s[:,:128]) | (v111+v011)*sigmoid(s[:,128:])]
// NOTE: harness ptxas targets sm_103 (no 'a') -> tcgen05 unavailable; mma.sync.
// ---------------------------------------------------------------------------

#define BATCH   8192
#define XDIM    320
#define NN0     128
#define NN1     64
#define NSV     192
#define NVD     64

#define NP0     8256
#define NP1     2080
#define NPA     2016
#define KSC     (NP0 + NP1)          // 10336
#define KSC_PAD 10368                // 162*64 ; NP0 = 129*64 exactly
#define NCHUNK  162
#define NCH0    129                  // chunks 0..128 are x0-pairs, 129.. x1-dots

// ---- static device scratch -------------------------------------------------
__device__ __align__(16) __nv_bfloat16 g_WSCh[KSC_PAD * NSV];   // [k][n] hi
__device__ __align__(16) __nv_bfloat16 g_WSCl[KSC_PAD * NSV];   // [k][n] lo
__device__ __align__(16) __nv_bfloat16 g_W3h[NN0 * NN1 * NVD];  // [u][v*64+w] hi
__device__ __align__(16) __nv_bfloat16 g_W3l[NN0 * NN1 * NVD];  // lo
__device__ float g_WVA[NPA * NVD];
__device__ __align__(4) unsigned short g_sp[KSC_PAD];
__device__ unsigned short g_pa[NPA];
__device__ float g_Z[(size_t)BATCH * NN1 * NVD];
__device__ float g_G[BATCH * NVD];

// ---- triangular index helpers ----------------------------------------------
__device__ __forceinline__ void tri_le(int p, int& u, int& v) {
    int vv = (int)floorf((sqrtf(8.0f * (float)p + 1.0f) - 1.0f) * 0.5f);
    while ((vv + 1) * (vv + 2) / 2 <= p) vv++;
    while (vv * (vv + 1) / 2 > p) vv--;
    v = vv;
    u = p - vv * (vv + 1) / 2;
}
__device__ __forceinline__ void tri_lt(int p, int& u, int& v) {
    int vv = (int)floorf((1.0f + sqrtf(8.0f * (float)p + 1.0f)) * 0.5f);
    while ((vv + 1) * vv / 2 <= p) vv++;
    while (vv * (vv - 1) / 2 > p) vv--;
    v = vv;
    u = p - vv * (vv - 1) / 2;
}

// pack f0(low)/f1(high) to bf16x2 + exact Dekker residual
__device__ __forceinline__ void split_pack(float f0, float f1,
                                           uint32_t& hp, uint32_t& lp) {
    asm("cvt.rn.satfinite.bf16x2.f32 %0, %1, %2;" : "=r"(hp) : "f"(f1), "f"(f0));
    float l0 = f0 - __uint_as_float(hp << 16);
    float l1 = f1 - __uint_as_float(hp & 0xffff0000u);
    asm("cvt.rn.satfinite.bf16x2.f32 %0, %1, %2;" : "=r"(lp) : "f"(l1), "f"(l0));
}

// ---- weight folding ----------------------------------------------------------
__global__ void build_wsc(const float* __restrict__ w000,
                          const float* __restrict__ w110) {
    int idx = blockIdx.x * blockDim.x + threadIdx.x;
    if (idx >= KSC_PAD * NSV) return;
    int p = idx / NSV;
    int w = idx - p * NSV;
    const float inv_sqrt2 = 0.7071067811865476f;
    float f = 0.0f;
    unsigned short pk = 0;
    if (p < NP0) {
        int u, v; tri_le(p, u, v);
        float val = w000[(u * NN0 + v) * NSV + w];
        if (u != v) val += w000[(v * NN0 + u) * NSV + w];
        f = (inv_sqrt2 / 128.0f) * val;
        pk = (unsigned short)((u << 8) | v);
    } else if (p < KSC) {
        int q = p - NP0;
        int u, v; tri_le(q, u, v);
        float val = w110[(u * NN1 + v) * NSV + w];
        if (u != v) val += w110[(v * NN1 + u) * NSV + w];
        f = (inv_sqrt2 / (64.0f * 1.7320508075688772f)) * val;
        pk = (unsigned short)((u << 8) | v);
    }
    __nv_bfloat16 h = __float2bfloat16(f);
    g_WSCh[idx] = h;
    g_WSCl[idx] = __float2bfloat16(f - __bfloat162float(h));
    if (w == 0) g_sp[p] = pk;
}

__global__ void build_wva(const float* __restrict__ w111) {
    int idx = blockIdx.x * blockDim.x + threadIdx.x;
    if (idx >= NPA * NVD) return;
    int p = idx / NVD;
    int w = idx - p * NVD;
    int u, v; tri_lt(p, u, v);
    g_WVA[idx] = (1.0f / 128.0f) *
                 (w111[(u * NN1 + v) * NVD + w] - w111[(v * NN1 + u) * NVD + w]);
    if (w == 0) g_pa[p] = (unsigned short)((u << 8) | v);
}

__global__ void build_w3(const float* __restrict__ w011) {
    int idx = blockIdx.x * blockDim.x + threadIdx.x;
    if (idx >= NN0 * NN1 * NVD) return;
    float f = w011[idx] * (1.0f / 128.0f);   // inv_sqrt2 / sqrt(N0*N1)
    __nv_bfloat16 h = __float2bfloat16(f);
    g_W3h[idx] = h;
    g_W3l[idx] = __float2bfloat16(f - __bfloat162float(h));
}

// ---- mma.sync helpers --------------------------------------------------------
__device__ __forceinline__ void mma_bf16(float* d, const uint32_t* a, const uint32_t* b) {
    asm volatile(
        "mma.sync.aligned.m16n8k16.row.col.f32.bf16.bf16.f32 "
        "{%0,%1,%2,%3}, {%4,%5,%6,%7}, {%8,%9}, {%0,%1,%2,%3};\n"
        : "+f"(d[0]), "+f"(d[1]), "+f"(d[2]), "+f"(d[3])
        : "r"(a[0]), "r"(a[1]), "r"(a[2]), "r"(a[3]), "r"(b[0]), "r"(b[1]));
}
__device__ __forceinline__ void ldsm_x4(uint32_t* r, uint32_t addr) {
    asm volatile("ldmatrix.sync.aligned.m8n8.x4.shared.b16 {%0,%1,%2,%3}, [%4];"
                 : "=r"(r[0]), "=r"(r[1]), "=r"(r[2]), "=r"(r[3]) : "r"(addr));
}
__device__ __forceinline__ void ldsm_x2t(uint32_t* r, uint32_t addr) {
    asm volatile("ldmatrix.sync.aligned.m8n8.x2.trans.shared.b16 {%0,%1}, [%2];"
                 : "=r"(r[0]), "=r"(r[1]) : "r"(addr));
}
__device__ __forceinline__ void cp16(uint32_t dst, const void* src) {
    asm volatile("cp.async.cg.shared.global [%0], [%1], 16;"
                 :: "r"(dst), "l"(src) : "memory");
}

// ---- g3 on tensor cores: g_Z = x0[8192x128] @ W3[128x4096] -------------------
// BM=64, BN=128, K=128 (single pass). 8 warps 2Mx4N, warp tile 32x32.
// strides 136 elem = 272B (== 16 mod 128 -> ldmatrix conflict-free)
#define G3_AS  136
#define G3_BS  136
#define G3_AH  0
#define G3_AL  17408
#define G3_BH  34816
#define G3_BL  69632
#define G3T_SMEM 104448

__global__ void __launch_bounds__(256) g3_tc(const float* __restrict__ x) {
    extern __shared__ char g3m[];
    const int t = threadIdx.x;
    const int lane = t & 31, warp = t >> 5;
    const int wm = warp & 1, wn = warp >> 1;
    const int row0 = blockIdx.x * 64;
    const int col0 = blockIdx.y * 128;

    uint32_t sb;
    asm("{ .reg .u64 u; cvta.to.shared.u64 u, %1; cvt.u32.u64 %0, u; }"
        : "=r"(sb) : "l"(g3m));

    // B tile via cp.async: 128 k-rows x 128 n-cols bf16, hi & lo
#pragma unroll
    for (int j = 0; j < 8; j++) {
        int i = t + j * 256;                   // 0..2047 (16B chunks)
        int r = i >> 4, cc = (i & 15) * 8;
        uint32_t doff = (uint32_t)(r * (G3_BS * 2) + cc * 2);
        size_t gi = (size_t)r * 4096 + col0 + cc;
        cp16(sb + G3_BH + doff, g_W3h + gi);
        cp16(sb + G3_BL + doff, g_W3l + gi);
    }
    asm volatile("cp.async.commit_group;" ::: "memory");

    // A tile: 64 rows x 128 k fp32 -> bf16 hi/lo
    for (int i = t; i < 4096; i += 256) {      // 2-elem groups
        int r = i >> 6, c2 = (i & 63) * 2;
        const float* xp = x + (size_t)(row0 + r) * XDIM + c2;
        uint32_t hp, lp; split_pack(xp[0], xp[1], hp, lp);
        *(uint32_t*)(g3m + G3_AH + r * (G3_AS * 2) + c2 * 2) = hp;
        *(uint32_t*)(g3m + G3_AL + r * (G3_AS * 2) + c2 * 2) = lp;
    }
    asm volatile("cp.async.wait_group 0;" ::: "memory");
    __syncthreads();

    float acc[2][4][4];
#pragma unroll
    for (int mt = 0; mt < 2; mt++)
#pragma unroll
        for (int nt = 0; nt < 4; nt++)
#pragma unroll
            for (int q = 0; q < 4; q++) acc[mt][nt][q] = 0.0f;

    const uint32_t a_eoff = (uint32_t)((wm * 32 + (lane & 15)) * G3_AS +
                                       (lane >> 4) * 8) * 2;
    const uint32_t b_eoff = (uint32_t)((lane & 15) * G3_BS + wn * 32) * 2;

#pragma unroll
    for (int ks = 0; ks < 8; ks++) {
        uint32_t ah[2][4], al[2][4];
#pragma unroll
        for (int mt = 0; mt < 2; mt++) {
            uint32_t eo = a_eoff + (uint32_t)(mt * 16 * G3_AS + ks * 16) * 2;
            ldsm_x4(ah[mt], sb + G3_AH + eo);
            ldsm_x4(al[mt], sb + G3_AL + eo);
        }
        uint32_t bh[4][2], bl[4][2];
#pragma unroll
        for (int nt = 0; nt < 4; nt++) {
            uint32_t eo = b_eoff + (uint32_t)(ks * 16 * G3_BS + nt * 8) * 2;
            ldsm_x2t(bh[nt], sb + G3_BH + eo);
            ldsm_x2t(bl[nt], sb + G3_BL + eo);
        }
#pragma unroll
        for (int mt = 0; mt < 2; mt++)
#pragma unroll
            for (int nt = 0; nt < 4; nt++) {
                mma_bf16(acc[mt][nt], ah[mt], bh[nt]);
                mma_bf16(acc[mt][nt], ah[mt], bl[nt]);
                mma_bf16(acc[mt][nt], al[mt], bh[nt]);
            }
    }

    // store fp32 Z (float2 per q-pair)
#pragma unroll
    for (int mt = 0; mt < 2; mt++)
#pragma unroll
        for (int nt = 0; nt < 4; nt++) {
            int r = row0 + wm * 32 + mt * 16 + (lane >> 2);
            int c = col0 + wn * 32 + nt * 8 + (lane & 3) * 2;
            float2 v0 = {acc[mt][nt][0], acc[mt][nt][1]};
            float2 v1 = {acc[mt][nt][2], acc[mt][nt][3]};
            *(float2*)&g_Z[(size_t)r * 4096 + c]       = v0;
            *(float2*)&g_Z[(size_t)(r + 8) * 4096 + c] = v1;
        }
}

// ---- scalars: pipelined mma.sync GEMM, 512 threads ----------------------------
// C[8192x192] = feat[8192x10368] @ WSC[10368x192], bf16 hi/lo (3 products)
// BM=64, BN=192, BK=64; 128 CTAs x 512 thr; warp grid 2(M)x8(N); warp tile 32x24.
#define AS_STRIDE 72      // bf16; 144B rows -> ldmatrix conflict-free
#define BS_STRIDE 216     // bf16; 432B rows -> ldmatrix conflict-free

#define SM_XS   0                           // p1: 64x132 f32; p2: 64x196 f32
#define SM_AH0  50176
#define SM_AL0  59392
#define SM_AH1  68608
#define SM_AL1  77824
#define SM_BH0  87040
#define SM_BL0  114688
#define SM_BH1  142336
#define SM_BL1  169984
#define TC_SMEM 197632

__global__ void __launch_bounds__(512) scalars_tc9(const float* __restrict__ x,
                                                   float* __restrict__ out) {
    extern __shared__ char tcsm[];
    float* Xs = (float*)(tcsm + SM_XS);
    const int t = threadIdx.x;
    const int lane = t & 31, warp = t >> 5;        // warp 0..15
    const int wm = warp & 1, wn = warp >> 1;       // 2 x 8
    const int row0 = blockIdx.x * 64;

    uint32_t sb;
    asm("{ .reg .u64 u; cvta.to.shared.u64 u, %1; cvt.u32.u64 %0, u; }"
        : "=r"(sb) : "l"(tcsm));

    const uint32_t AH[2] = {sb + SM_AH0, sb + SM_AH1};
    const uint32_t AL[2] = {sb + SM_AL0, sb + SM_AL1};
    const uint32_t BH[2] = {sb + SM_BH0, sb + SM_BH1};
    const uint32_t BL[2] = {sb + SM_BL0, sb + SM_BL1};

    // phase-1 x tile: x0 (64 rows x 128 f32, stride 132)
    for (int i = t; i < 64 * 32; i += 512) {
        int r = i >> 5, c4 = (i & 31) << 2;
        *(float4*)&Xs[r * 132 + c4] =
            *(const float4*)&x[(size_t)(row0 + r) * XDIM + c4];
    }
    __syncthreads();

    const int kk2 = lane * 2;     // 2 k's per lane
    const int mg = warp * 4;      // 4 m rows per warp

    auto build_A = [&](int c, int st) {
        char* ah = tcsm + (st ? SM_AH1 : SM_AH0);
        char* al = tcsm + (st ? SM_AL1 : SM_AL0);
        int kg = c * 64 + kk2;
        uint32_t pk = __ldg((const uint32_t*)&g_sp[kg]);
        int u0 = (pk >> 8) & 255, v0 = pk & 255;
        int u1 = pk >> 24,       v1 = (pk >> 16) & 255;
        if (c < NCH0) {
#pragma unroll
            for (int j = 0; j < 4; j++) {
                int m = mg + j;
                const float* Xr = Xs + m * 132;
                float f0 = Xr[u0] * Xr[v0];
                float f1 = Xr[u1] * Xr[v1];
                uint32_t hp, lp; split_pack(f0, f1, hp, lp);
                *(uint32_t*)(ah + m * (AS_STRIDE * 2) + kk2 * 2) = hp;
                *(uint32_t*)(al + m * (AS_STRIDE * 2) + kk2 * 2) = lp;
            }
        } else {
#pragma unroll
            for (int j = 0; j < 4; j++) {
                int m = mg + j;
                const float* Xr = Xs + m * 196;
                const float* a0 = Xr + 3 * u0; const float* b0 = Xr + 3 * v0;
                const float* a1 = Xr + 3 * u1; const float* b1 = Xr + 3 * v1;
                float f0 = a0[0] * b0[0] + a0[1] * b0[1] + a0[2] * b0[2];
                float f1 = a1[0] * b1[0] + a1[1] * b1[1] + a1[2] * b1[2];
                uint32_t hp, lp; split_pack(f0, f1, hp, lp);
                *(uint32_t*)(ah + m * (AS_STRIDE * 2) + kk2 * 2) = hp;
                *(uint32_t*)(al + m * (AS_STRIDE * 2) + kk2 * 2) = lp;
            }
        }
    };
    // B tile: 64 rows x 192 bf16 = 1536 16B-chunks per buffer (hi & lo)
    auto fetch_B = [&](int c, int st) {
        const uint32_t bh = BH[st], bl = BL[st];
        const int k0 = c * 64;
#pragma unroll
        for (int j = 0; j < 3; j++) {
            int i = t + j * 512;                     // 0..1535
            int r = i / 24, cc = (i - r * 24) * 8;   // row 0..63, col 0..184
            uint32_t doff = (uint32_t)(r * (BS_STRIDE * 2) + cc * 2);
            size_t gi = (size_t)(k0 + r) * NSV + cc;
            cp16(bh + doff, g_WSCh + gi);
            cp16(bl + doff, g_WSCl + gi);
        }
        asm volatile("cp.async.commit_group;" ::: "memory");
    };

    float acc[2][3][4];
#pragma unroll
    for (int mt = 0; mt < 2; mt++)
#pragma unroll
        for (int nt = 0; nt < 3; nt++)
#pragma unroll
            for (int q = 0; q < 4; q++) acc[mt][nt][q] = 0.0f;

    const uint32_t a_eoff = (uint32_t)((wm * 32 + (lane & 15)) * AS_STRIDE +
                                       (lane >> 4) * 8) * 2;
    const uint32_t b_eoff = (uint32_t)((lane & 15) * BS_STRIDE + wn * 24) * 2;

    // prologue: stage 0 = chunk 0
    fetch_B(0, 0);
    build_A(0, 0);
    asm volatile("cp.async.wait_group 0;" ::: "memory");
    __syncthreads();

    for (int i = 0; i < NCHUNK; i++) {
        const int s = i & 1;
        if (i + 1 < NCHUNK) {
            if (i + 1 == NCH0) {
                // switch x tile to x1 (64 rows x 192 f32, stride 196)
                for (int j = t; j < 64 * 48; j += 512) {
                    int r = j / 48, c4 = (j - r * 48) << 2;
                    *(float4*)&Xs[r * 196 + c4] =
                        *(const float4*)&x[(size_t)(row0 + r) * XDIM + 128 + c4];
                }
                __syncthreads();
            }
            fetch_B(i + 1, s ^ 1);
            build_A(i + 1, s ^ 1);
        }

        // MMA chunk i from stage s (4 k16 steps x 3 split products)
#pragma unroll
        for (int ks = 0; ks < 4; ks++) {
            uint32_t ah[2][4], al[2][4];
#pragma unroll
            for (int mt = 0; mt < 2; mt++) {
                uint32_t eo = a_eoff + (uint32_t)(mt * 16 * AS_STRIDE + ks * 16) * 2;
                ldsm_x4(ah[mt], AH[s] + eo);
                ldsm_x4(al[mt], AL[s] + eo);
            }
            uint32_t bh[3][2], bl[3][2];
#pragma unroll
            for (int nt = 0; nt < 3; nt++) {
                uint32_t eo = b_eoff + (uint32_t)(ks * 16 * BS_STRIDE + nt * 8) * 2;
                ldsm_x2t(bh[nt], BH[s] + eo);
                ldsm_x2t(bl[nt], BL[s] + eo);
            }
#pragma unroll
            for (int mt = 0; mt < 2; mt++)
#pragma unroll
                for (int nt = 0; nt < 3; nt++) {
                    mma_bf16(acc[mt][nt], ah[mt], bh[nt]);
                    mma_bf16(acc[mt][nt], ah[mt], bl[nt]);
                    mma_bf16(acc[mt][nt], al[mt], bh[nt]);
                }
        }

        if (i + 1 < NCHUNK) {
            asm volatile("cp.async.wait_group 0;" ::: "memory");
            __syncthreads();
        }
    }

    // epilogue: silu -> out[:, :128], sigmoid -> g_G
#pragma unroll
    for (int mt = 0; mt < 2; mt++) {
#pragma unroll
        for (int nt = 0; nt < 3; nt++) {
            int r = row0 + wm * 32 + mt * 16 + (lane >> 2);
            int c = wn * 24 + nt * 8 + (lane & 3) * 2;
#pragma unroll
            for (int q = 0; q < 4; q++) {
                int rr = r + (q >> 1) * 8;
                int cc = c + (q & 1);
                float s = acc[mt][nt][q];
                float sg = 1.0f / (1.0f + __expf(-s));
                if (cc < 128) out[(size_t)rr * XDIM + cc] = s * sg;
                else          g_G[rr * 64 + (cc - 128)] = sg;
            }
        }
    }
}

// ---- vectors: cross-feature GEMM + v011 contraction + gating ------------------
__global__ void __launch_bounds__(128) vectors_kernel(const float* __restrict__ x,
                                                      float* __restrict__ out) {
    __shared__ float Xs[32 * 193];
    __shared__ __align__(16) float As0[1024];
    __shared__ __align__(16) float As1[1024];
    __shared__ __align__(16) float As2[1024];
    __shared__ __align__(16) float Bs[32 * 64];
    int t = threadIdx.x;
    int row0 = blockIdx.x * 32;

    for (int i = t; i < 32 * 192; i += 128) {
        int r = i / 192, c = i - r * 192;
        Xs[r * 193 + c] = x[(row0 + r) * XDIM + 128 + c];
    }
    __syncthreads();

    int rg = t >> 5, cg = t & 31;
    int r0 = rg * 8, w0 = cg * 2;
    float acc[8][2][3];
#pragma unroll
    for (int i = 0; i < 8; i++)
#pragma unroll
        for (int j = 0; j < 2; j++)
#pragma unroll
            for (int k = 0; k < 3; k++) acc[i][j][k] = 0.0f;

    for (int kc = 0; kc < 63; kc++) {
        int kb = kc * 32;
        for (int i = t; i < 512; i += 128) {
            int p = i >> 4, c = (i & 15) << 2;
            *(float4*)&Bs[p * 64 + c] = *(const float4*)&g_WVA[(kb + p) * 64 + c];
        }
#pragma unroll
        for (int i = 0; i < 8; i++) {
            int m = t + i * 128;
            int p = m >> 5, r = m & 31;
            unsigned int pk = g_pa[kb + p];
            int u = pk >> 8, v = pk & 255;
            const float* xu = &Xs[r * 193 + 3 * u];
            const float* xv = &Xs[r * 193 + 3 * v];
            float ax = xu[0], ay = xu[1], az = xu[2];
            float bx = xv[0], by = xv[1], bz = xv[2];
            As0[p * 32 + r] = ay * bz - az * by;
            As1[p * 32 + r] = az * bx - ax * bz;
            As2[p * 32 + r] = ax * by - ay * bx;
        }
        __syncthreads();

#pragma unroll 2
        for (int p = 0; p < 32; p++) {
            float2 b = *(float2*)&Bs[p * 64 + w0];
            float4 q00 = *(float4*)&As0[p * 32 + r0];
            float4 q01 = *(float4*)&As0[p * 32 + r0 + 4];
            float4 q10 = *(float4*)&As1[p * 32 + r0];
            float4 q11 = *(float4*)&As1[p * 32 + r0 + 4];
            float4 q20 = *(float4*)&As2[p * 32 + r0];
            float4 q21 = *(float4*)&As2[p * 32 + r0 + 4];
            float a0[8] = {q00.x, q00.y, q00.z, q00.w, q01.x, q01.y, q01.z, q01.w};
            float a1[8] = {q10.x, q10.y, q10.z, q10.w, q11.x, q11.y, q11.z, q11.w};
            float a2[8] = {q20.x, q20.y, q20.z, q20.w, q21.x, q21.y, q21.z, q21.w};
#pragma unroll
            for (int i = 0; i < 8; i++) {
                acc[i][0][0] += a0[i] * b.x;  acc[i][1][0] += a0[i] * b.y;
                acc[i][0][1] += a1[i] * b.x;  acc[i][1][1] += a1[i] * b.y;
                acc[i][0][2] += a2[i] * b.x;  acc[i][1][2] += a2[i] * b.y;
            }
        }
        __syncthreads();
    }

#pragma unroll
    for (int i = 0; i < 8; i++) {
        int bi = row0 + r0 + i;
        const float* Zr = &g_Z[(size_t)bi * 4096];
        const float* Xr = &Xs[(r0 + i) * 193];
        for (int n = 0; n < 64; n++) {
            float2 z = *(const float2*)&Zr[n * 64 + w0];
            float xa = Xr[3 * n], xb = Xr[3 * n + 1], xc = Xr[3 * n + 2];
            acc[i][0][0] += xa * z.x; acc[i][0][1] += xb * z.x; acc[i][0][2] += xc * z.x;
            acc[i][1][0] += xa * z.y; acc[i][1][1] += xb * z.y; acc[i][1][2] += xc * z.y;
        }
        float g0 = g_G[bi * 64 + w0];
        float g1 = g_G[bi * 64 + w0 + 1];
#pragma unroll
        for (int k = 0; k < 3; k++) {
            out[bi * XDIM + 128 + w0 * 3 + k]       = acc[i][0][k] * g0;
            out[bi * XDIM + 128 + (w0 + 1) * 3 + k] = acc[i][1][k] * g1;
        }
    }
}

// ---------------------------------------------------------------------------
extern "C" void kernel_launch(void* const* d_in, const int* in_sizes, int n_in,
                              void* d_out, int out_size) {
    const float* x = 0;
    const float* w000 = 0;
    const float* w110 = 0;
    const float* w011 = 0;
    const float* w111 = 0;
    for (int i = 0; i < n_in; i++) {
        switch (in_sizes[i]) {
            case BATCH * XDIM:       x    = (const float*)d_in[i]; break;
            case NN0 * NN0 * NSV:    w000 = (const float*)d_in[i]; break;
            case NN1 * NN1 * NSV:    w110 = (const float*)d_in[i]; break;
            case NN0 * NN1 * NVD:    w011 = (const float*)d_in[i]; break;
            case NN1 * NN1 * NVD:    w111 = (const float*)d_in[i]; break;
            default: break;
        }
    }
    if (!x)    x    = (const float*)d_in[0];
    if (!w000) w000 = (const float*)d_in[1];
    if (!w110) w110 = (const float*)d_in[2];
    if (!w011) w011 = (const float*)d_in[3];
    if (!w111) w111 = (const float*)d_in[4];
    float* out = (float*)d_out;

    cudaFuncSetAttribute(scalars_tc9,
                         cudaFuncAttributeMaxDynamicSharedMemorySize, TC_SMEM);
    cudaFuncSetAttribute(g3_tc,
                         cudaFuncAttributeMaxDynamicSharedMemorySize, G3T_SMEM);

    build_wsc<<<(KSC_PAD * NSV + 255) / 256, 256>>>(w000, w110);
    build_wva<<<(NPA * NVD + 255) / 256, 256>>>(w111);
    build_w3<<<(NN0 * NN1 * NVD + 255) / 256, 256>>>(w011);
    g3_tc<<<dim3(BATCH / 64, 4096 / 128), 256, G3T_SMEM>>>(x);
    scalars_tc9<<<BATCH / 64, 512, TC_SMEM>>>(x, out);
    vectors_kernel<<<BATCH / 32, 128>>>(x, out);
}

// round 11
// speedup vs baseline: 2.6917x; 1.2492x over previous
#include <cuda_runtime.h>
#include <cuda_bf16.h>
#include <math.h>
#include <stdint.h>

// ---------------------------------------------------------------------------
// PE_GatedBlock: B=8192, N0=128, N1=64, NS=128, NV=64
//   scalars = [sym-pair feats x0 | sym-dot feats x1] @ WSC   (mma.sync hi/lo x3)
//   Z = (1/128) x0 @ w011                                    (mma.sync hi/lo x3)
//   v111 = cross feats @ WVA                                 (mma.sync hi/lo x3)
//   v011 from Z contraction (fp32 epilogue), gating fused.
//   out = [silu(s[:,:128]) | (v111+v011)*sigmoid(s[:,128:])]
// NOTE: harness ptxas targets sm_103 (no 'a') -> tcgen05 unavailable; mma.sync.
// ---------------------------------------------------------------------------

#define BATCH   8192
#define XDIM    320
#define NN0     128
#define NN1     64
#define NSV     192
#define NVD     64

#define NP0     8256
#define NP1     2080
#define NPA     2016
#define NPA_PAD 2048                 // 32*64 (zero-padded)
#define NCHV    32
#define KSC     (NP0 + NP1)          // 10336
#define KSC_PAD 10368                // 162*64 ; NP0 = 129*64 exactly
#define NCHUNK  162
#define NCH0    129                  // chunks 0..128 are x0-pairs, 129.. x1-dots

// ---- static device scratch -------------------------------------------------
__device__ __align__(16) __nv_bfloat16 g_WSCh[KSC_PAD * NSV];   // [k][n] hi
__device__ __align__(16) __nv_bfloat16 g_WSCl[KSC_PAD * NSV];   // [k][n] lo
__device__ __align__(16) __nv_bfloat16 g_W3h[NN0 * NN1 * NVD];  // [u][v*64+w] hi
__device__ __align__(16) __nv_bfloat16 g_W3l[NN0 * NN1 * NVD];  // lo
__device__ __align__(16) __nv_bfloat16 g_WVAh[NPA_PAD * NVD];   // [p][w] hi
__device__ __align__(16) __nv_bfloat16 g_WVAl[NPA_PAD * NVD];   // lo
__device__ __align__(4) unsigned short g_sp[KSC_PAD];
__device__ __align__(4) unsigned short g_pa[NPA_PAD];
__device__ float g_Z[(size_t)BATCH * NN1 * NVD];
__device__ float g_G[BATCH * NVD];

// ---- triangular index helpers ----------------------------------------------
__device__ __forceinline__ void tri_le(int p, int& u, int& v) {
    int vv = (int)floorf((sqrtf(8.0f * (float)p + 1.0f) - 1.0f) * 0.5f);
    while ((vv + 1) * (vv + 2) / 2 <= p) vv++;
    while (vv * (vv + 1) / 2 > p) vv--;
    v = vv;
    u = p - vv * (vv + 1) / 2;
}
__device__ __forceinline__ void tri_lt(int p, int& u, int& v) {
    int vv = (int)floorf((1.0f + sqrtf(8.0f * (float)p + 1.0f)) * 0.5f);
    while ((vv + 1) * vv / 2 <= p) vv++;
    while (vv * (vv - 1) / 2 > p) vv--;
    v = vv;
    u = p - vv * (vv - 1) / 2;
}

// pack f0(low)/f1(high) to bf16x2 + exact Dekker residual
__device__ __forceinline__ void split_pack(float f0, float f1,
                                           uint32_t& hp, uint32_t& lp) {
    asm("cvt.rn.satfinite.bf16x2.f32 %0, %1, %2;" : "=r"(hp) : "f"(f1), "f"(f0));
    float l0 = f0 - __uint_as_float(hp << 16);
    float l1 = f1 - __uint_as_float(hp & 0xffff0000u);
    asm("cvt.rn.satfinite.bf16x2.f32 %0, %1, %2;" : "=r"(lp) : "f"(l1), "f"(l0));
}

// ---- weight folding ----------------------------------------------------------
__global__ void build_wsc(const float* __restrict__ w000,
                          const float* __restrict__ w110) {
    int idx = blockIdx.x * blockDim.x + threadIdx.x;
    if (idx >= KSC_PAD * NSV) return;
    int p = idx / NSV;
    int w = idx - p * NSV;
    const float inv_sqrt2 = 0.7071067811865476f;
    float f = 0.0f;
    unsigned short pk = 0;
    if (p < NP0) {
        int u, v; tri_le(p, u, v);
        float val = w000[(u * NN0 + v) * NSV + w];
        if (u != v) val += w000[(v * NN0 + u) * NSV + w];
        f = (inv_sqrt2 / 128.0f) * val;
        pk = (unsigned short)((u << 8) | v);
    } else if (p < KSC) {
        int q = p - NP0;
        int u, v; tri_le(q, u, v);
        float val = w110[(u * NN1 + v) * NSV + w];
        if (u != v) val += w110[(v * NN1 + u) * NSV + w];
        f = (inv_sqrt2 / (64.0f * 1.7320508075688772f)) * val;
        pk = (unsigned short)((u << 8) | v);
    }
    __nv_bfloat16 h = __float2bfloat16(f);
    g_WSCh[idx] = h;
    g_WSCl[idx] = __float2bfloat16(f - __bfloat162float(h));
    if (w == 0) g_sp[p] = pk;
}

__global__ void build_wva(const float* __restrict__ w111) {
    int idx = blockIdx.x * blockDim.x + threadIdx.x;
    if (idx >= NPA_PAD * NVD) return;
    int p = idx / NVD;
    int w = idx - p * NVD;
    float f = 0.0f;
    unsigned short pk = 0;
    if (p < NPA) {
        int u, v; tri_lt(p, u, v);
        f = (1.0f / 128.0f) *
            (w111[(u * NN1 + v) * NVD + w] - w111[(v * NN1 + u) * NVD + w]);
        pk = (unsigned short)((u << 8) | v);
    }
    __nv_bfloat16 h = __float2bfloat16(f);
    g_WVAh[idx] = h;
    g_WVAl[idx] = __float2bfloat16(f - __bfloat162float(h));
    if (w == 0) g_pa[p] = pk;
}

__global__ void build_w3(const float* __restrict__ w011) {
    int idx = blockIdx.x * blockDim.x + threadIdx.x;
    if (idx >= NN0 * NN1 * NVD) return;
    float f = w011[idx] * (1.0f / 128.0f);   // inv_sqrt2 / sqrt(N0*N1)
    __nv_bfloat16 h = __float2bfloat16(f);
    g_W3h[idx] = h;
    g_W3l[idx] = __float2bfloat16(f - __bfloat162float(h));
}

// ---- mma.sync helpers --------------------------------------------------------
__device__ __forceinline__ void mma_bf16(float* d, const uint32_t* a, const uint32_t* b) {
    asm volatile(
        "mma.sync.aligned.m16n8k16.row.col.f32.bf16.bf16.f32 "
        "{%0,%1,%2,%3}, {%4,%5,%6,%7}, {%8,%9}, {%0,%1,%2,%3};\n"
        : "+f"(d[0]), "+f"(d[1]), "+f"(d[2]), "+f"(d[3])
        : "r"(a[0]), "r"(a[1]), "r"(a[2]), "r"(a[3]), "r"(b[0]), "r"(b[1]));
}
__device__ __forceinline__ void ldsm_x4(uint32_t* r, uint32_t addr) {
    asm volatile("ldmatrix.sync.aligned.m8n8.x4.shared.b16 {%0,%1,%2,%3}, [%4];"
                 : "=r"(r[0]), "=r"(r[1]), "=r"(r[2]), "=r"(r[3]) : "r"(addr));
}
__device__ __forceinline__ void ldsm_x2t(uint32_t* r, uint32_t addr) {
    asm volatile("ldmatrix.sync.aligned.m8n8.x2.trans.shared.b16 {%0,%1}, [%2];"
                 : "=r"(r[0]), "=r"(r[1]) : "r"(addr));
}
__device__ __forceinline__ void cp16(uint32_t dst, const void* src) {
    asm volatile("cp.async.cg.shared.global [%0], [%1], 16;"
                 :: "r"(dst), "l"(src) : "memory");
}

// ---- g3 on tensor cores: g_Z = x0[8192x128] @ W3[128x4096] -------------------
#define G3_AS  136
#define G3_BS  136
#define G3_AH  0
#define G3_AL  17408
#define G3_BH  34816
#define G3_BL  69632
#define G3T_SMEM 104448

__global__ void __launch_bounds__(256) g3_tc(const float* __restrict__ x) {
    extern __shared__ char g3m[];
    const int t = threadIdx.x;
    const int lane = t & 31, warp = t >> 5;
    const int wm = warp & 1, wn = warp >> 1;
    const int row0 = blockIdx.x * 64;
    const int col0 = blockIdx.y * 128;

    uint32_t sb;
    asm("{ .reg .u64 u; cvta.to.shared.u64 u, %1; cvt.u32.u64 %0, u; }"
        : "=r"(sb) : "l"(g3m));

#pragma unroll
    for (int j = 0; j < 8; j++) {
        int i = t + j * 256;
        int r = i >> 4, cc = (i & 15) * 8;
        uint32_t doff = (uint32_t)(r * (G3_BS * 2) + cc * 2);
        size_t gi = (size_t)r * 4096 + col0 + cc;
        cp16(sb + G3_BH + doff, g_W3h + gi);
        cp16(sb + G3_BL + doff, g_W3l + gi);
    }
    asm volatile("cp.async.commit_group;" ::: "memory");

    for (int i = t; i < 4096; i += 256) {
        int r = i >> 6, c2 = (i & 63) * 2;
        const float* xp = x + (size_t)(row0 + r) * XDIM + c2;
        uint32_t hp, lp; split_pack(xp[0], xp[1], hp, lp);
        *(uint32_t*)(g3m + G3_AH + r * (G3_AS * 2) + c2 * 2) = hp;
        *(uint32_t*)(g3m + G3_AL + r * (G3_AS * 2) + c2 * 2) = lp;
    }
    asm volatile("cp.async.wait_group 0;" ::: "memory");
    __syncthreads();

    float acc[2][4][4];
#pragma unroll
    for (int mt = 0; mt < 2; mt++)
#pragma unroll
        for (int nt = 0; nt < 4; nt++)
#pragma unroll
            for (int q = 0; q < 4; q++) acc[mt][nt][q] = 0.0f;

    const uint32_t a_eoff = (uint32_t)((wm * 32 + (lane & 15)) * G3_AS +
                                       (lane >> 4) * 8) * 2;
    const uint32_t b_eoff = (uint32_t)((lane & 15) * G3_BS + wn * 32) * 2;

#pragma unroll
    for (int ks = 0; ks < 8; ks++) {
        uint32_t ah[2][4], al[2][4];
#pragma unroll
        for (int mt = 0; mt < 2; mt++) {
            uint32_t eo = a_eoff + (uint32_t)(mt * 16 * G3_AS + ks * 16) * 2;
            ldsm_x4(ah[mt], sb + G3_AH + eo);
            ldsm_x4(al[mt], sb + G3_AL + eo);
        }
        uint32_t bh[4][2], bl[4][2];
#pragma unroll
        for (int nt = 0; nt < 4; nt++) {
            uint32_t eo = b_eoff + (uint32_t)(ks * 16 * G3_BS + nt * 8) * 2;
            ldsm_x2t(bh[nt], sb + G3_BH + eo);
            ldsm_x2t(bl[nt], sb + G3_BL + eo);
        }
#pragma unroll
        for (int mt = 0; mt < 2; mt++)
#pragma unroll
            for (int nt = 0; nt < 4; nt++) {
                mma_bf16(acc[mt][nt], ah[mt], bh[nt]);
                mma_bf16(acc[mt][nt], ah[mt], bl[nt]);
                mma_bf16(acc[mt][nt], al[mt], bh[nt]);
            }
    }

#pragma unroll
    for (int mt = 0; mt < 2; mt++)
#pragma unroll
        for (int nt = 0; nt < 4; nt++) {
            int r = row0 + wm * 32 + mt * 16 + (lane >> 2);
            int c = col0 + wn * 32 + nt * 8 + (lane & 3) * 2;
            float2 v0 = {acc[mt][nt][0], acc[mt][nt][1]};
            float2 v1 = {acc[mt][nt][2], acc[mt][nt][3]};
            *(float2*)&g_Z[(size_t)r * 4096 + c]       = v0;
            *(float2*)&g_Z[(size_t)(r + 8) * 4096 + c] = v1;
        }
}

// ---- scalars: pipelined mma.sync GEMM, 512 threads ----------------------------
#define AS_STRIDE 72      // bf16; 144B rows -> ldmatrix conflict-free
#define BS_STRIDE 216     // bf16; 432B rows -> ldmatrix conflict-free

#define SM_XS   0
#define SM_AH0  50176
#define SM_AL0  59392
#define SM_AH1  68608
#define SM_AL1  77824
#define SM_BH0  87040
#define SM_BL0  114688
#define SM_BH1  142336
#define SM_BL1  169984
#define TC_SMEM 197632

__global__ void __launch_bounds__(512) scalars_tc9(const float* __restrict__ x,
                                                   float* __restrict__ out) {
    extern __shared__ char tcsm[];
    float* Xs = (float*)(tcsm + SM_XS);
    const int t = threadIdx.x;
    const int lane = t & 31, warp = t >> 5;
    const int wm = warp & 1, wn = warp >> 1;       // 2 x 8
    const int row0 = blockIdx.x * 64;

    uint32_t sb;
    asm("{ .reg .u64 u; cvta.to.shared.u64 u, %1; cvt.u32.u64 %0, u; }"
        : "=r"(sb) : "l"(tcsm));

    const uint32_t AH[2] = {sb + SM_AH0, sb + SM_AH1};
    const uint32_t AL[2] = {sb + SM_AL0, sb + SM_AL1};
    const uint32_t BH[2] = {sb + SM_BH0, sb + SM_BH1};
    const uint32_t BL[2] = {sb + SM_BL0, sb + SM_BL1};

    for (int i = t; i < 64 * 32; i += 512) {
        int r = i >> 5, c4 = (i & 31) << 2;
        *(float4*)&Xs[r * 132 + c4] =
            *(const float4*)&x[(size_t)(row0 + r) * XDIM + c4];
    }
    __syncthreads();

    const int kk2 = lane * 2;
    const int mg = warp * 4;

    auto build_A = [&](int c, int st) {
        char* ah = tcsm + (st ? SM_AH1 : SM_AH0);
        char* al = tcsm + (st ? SM_AL1 : SM_AL0);
        int kg = c * 64 + kk2;
        uint32_t pk = __ldg((const uint32_t*)&g_sp[kg]);
        int u0 = (pk >> 8) & 255, v0 = pk & 255;
        int u1 = pk >> 24,       v1 = (pk >> 16) & 255;
        if (c < NCH0) {
#pragma unroll
            for (int j = 0; j < 4; j++) {
                int m = mg + j;
                const float* Xr = Xs + m * 132;
                float f0 = Xr[u0] * Xr[v0];
                float f1 = Xr[u1] * Xr[v1];
                uint32_t hp, lp; split_pack(f0, f1, hp, lp);
                *(uint32_t*)(ah + m * (AS_STRIDE * 2) + kk2 * 2) = hp;
                *(uint32_t*)(al + m * (AS_STRIDE * 2) + kk2 * 2) = lp;
            }
        } else {
#pragma unroll
            for (int j = 0; j < 4; j++) {
                int m = mg + j;
                const float* Xr = Xs + m * 196;
                const float* a0 = Xr + 3 * u0; const float* b0 = Xr + 3 * v0;
                const float* a1 = Xr + 3 * u1; const float* b1 = Xr + 3 * v1;
                float f0 = a0[0] * b0[0] + a0[1] * b0[1] + a0[2] * b0[2];
                float f1 = a1[0] * b1[0] + a1[1] * b1[1] + a1[2] * b1[2];
                uint32_t hp, lp; split_pack(f0, f1, hp, lp);
                *(uint32_t*)(ah + m * (AS_STRIDE * 2) + kk2 * 2) = hp;
                *(uint32_t*)(al + m * (AS_STRIDE * 2) + kk2 * 2) = lp;
            }
        }
    };
    auto fetch_B = [&](int c, int st) {
        const uint32_t bh = BH[st], bl = BL[st];
        const int k0 = c * 64;
#pragma unroll
        for (int j = 0; j < 3; j++) {
            int i = t + j * 512;
            int r = i / 24, cc = (i - r * 24) * 8;
            uint32_t doff = (uint32_t)(r * (BS_STRIDE * 2) + cc * 2);
            size_t gi = (size_t)(k0 + r) * NSV + cc;
            cp16(bh + doff, g_WSCh + gi);
            cp16(bl + doff, g_WSCl + gi);
        }
        asm volatile("cp.async.commit_group;" ::: "memory");
    };

    float acc[2][3][4];
#pragma unroll
    for (int mt = 0; mt < 2; mt++)
#pragma unroll
        for (int nt = 0; nt < 3; nt++)
#pragma unroll
            for (int q = 0; q < 4; q++) acc[mt][nt][q] = 0.0f;

    const uint32_t a_eoff = (uint32_t)((wm * 32 + (lane & 15)) * AS_STRIDE +
                                       (lane >> 4) * 8) * 2;
    const uint32_t b_eoff = (uint32_t)((lane & 15) * BS_STRIDE + wn * 24) * 2;

    fetch_B(0, 0);
    build_A(0, 0);
    asm volatile("cp.async.wait_group 0;" ::: "memory");
    __syncthreads();

    for (int i = 0; i < NCHUNK; i++) {
        const int s = i & 1;
        if (i + 1 < NCHUNK) {
            if (i + 1 == NCH0) {
                for (int j = t; j < 64 * 48; j += 512) {
                    int r = j / 48, c4 = (j - r * 48) << 2;
                    *(float4*)&Xs[r * 196 + c4] =
                        *(const float4*)&x[(size_t)(row0 + r) * XDIM + 128 + c4];
                }
                __syncthreads();
            }
            fetch_B(i + 1, s ^ 1);
            build_A(i + 1, s ^ 1);
        }

#pragma unroll
        for (int ks = 0; ks < 4; ks++) {
            uint32_t ah[2][4], al[2][4];
#pragma unroll
            for (int mt = 0; mt < 2; mt++) {
                uint32_t eo = a_eoff + (uint32_t)(mt * 16 * AS_STRIDE + ks * 16) * 2;
                ldsm_x4(ah[mt], AH[s] + eo);
                ldsm_x4(al[mt], AL[s] + eo);
            }
            uint32_t bh[3][2], bl[3][2];
#pragma unroll
            for (int nt = 0; nt < 3; nt++) {
                uint32_t eo = b_eoff + (uint32_t)(ks * 16 * BS_STRIDE + nt * 8) * 2;
                ldsm_x2t(bh[nt], BH[s] + eo);
                ldsm_x2t(bl[nt], BL[s] + eo);
            }
#pragma unroll
            for (int mt = 0; mt < 2; mt++)
#pragma unroll
                for (int nt = 0; nt < 3; nt++) {
                    mma_bf16(acc[mt][nt], ah[mt], bh[nt]);
                    mma_bf16(acc[mt][nt], ah[mt], bl[nt]);
                    mma_bf16(acc[mt][nt], al[mt], bh[nt]);
                }
        }

        if (i + 1 < NCHUNK) {
            asm volatile("cp.async.wait_group 0;" ::: "memory");
            __syncthreads();
        }
    }

#pragma unroll
    for (int mt = 0; mt < 2; mt++) {
#pragma unroll
        for (int nt = 0; nt < 3; nt++) {
            int r = row0 + wm * 32 + mt * 16 + (lane >> 2);
            int c = wn * 24 + nt * 8 + (lane & 3) * 2;
#pragma unroll
            for (int q = 0; q < 4; q++) {
                int rr = r + (q >> 1) * 8;
                int cc = c + (q & 1);
                float s = acc[mt][nt][q];
                float sg = 1.0f / (1.0f + __expf(-s));
                if (cc < 128) out[(size_t)rr * XDIM + cc] = s * sg;
                else          g_G[rr * 64 + (cc - 128)] = sg;
            }
        }
    }
}

// ---- vectors on tensor cores ---------------------------------------------------
// v111[b,w,k] = cross_k feats [8192 x 2048] @ WVA[2048 x 64]  (3 comps, hi/lo x3)
// BM=64, BN=64, BK=64; 128 CTAs x 512 thr; warp grid 2(M) x 8(N); warp tile 32x8 x3.
// Epilogue adds v011 from g_Z and applies sigmoid gates.
#define V_AS 72
#define V_BS 72
#define VS_XS 0                                   // 64 x 196 f32 (x1 rows)
#define VS_A  50176                               // 12 bufs: [st][comp][hi/lo]
#define VS_B  160768                              // 4 bufs: [st][hi/lo]
#define VS_SMEM 197632
#define VA_OFF(st, comp, hl) (VS_A + (((st) * 6) + (comp) * 2 + (hl)) * 9216)
#define VB_OFF(st, hl)       (VS_B + ((st) * 2 + (hl)) * 9216)

__global__ void __launch_bounds__(512) vectors_tc(const float* __restrict__ x,
                                                  float* __restrict__ out) {
    extern __shared__ char vsm[];
    float* Xs = (float*)(vsm + VS_XS);
    const int t = threadIdx.x;
    const int lane = t & 31, warp = t >> 5;
    const int wm = warp & 1, wn = warp >> 1;       // 2 x 8
    const int row0 = blockIdx.x * 64;

    uint32_t sb;
    asm("{ .reg .u64 u; cvta.to.shared.u64 u, %1; cvt.u32.u64 %0, u; }"
        : "=r"(sb) : "l"(vsm));

    // x1 tile: 64 rows x 192 f32, stride 196
    for (int i = t; i < 64 * 48; i += 512) {
        int r = i / 48, c4 = (i - r * 48) << 2;
        *(float4*)&Xs[r * 196 + c4] =
            *(const float4*)&x[(size_t)(row0 + r) * XDIM + 128 + c4];
    }
    __syncthreads();

    const int kk2 = lane * 2;
    const int mg = warp * 4;

    auto build_A = [&](int c, int st) {
        char* a0h = vsm + VA_OFF(st, 0, 0); char* a0l = vsm + VA_OFF(st, 0, 1);
        char* a1h = vsm + VA_OFF(st, 1, 0); char* a1l = vsm + VA_OFF(st, 1, 1);
        char* a2h = vsm + VA_OFF(st, 2, 0); char* a2l = vsm + VA_OFF(st, 2, 1);
        int kg = c * 64 + kk2;
        uint32_t pk = __ldg((const uint32_t*)&g_pa[kg]);
        int u0 = (pk >> 8) & 255, v0 = pk & 255;
        int u1 = pk >> 24,       v1 = (pk >> 16) & 255;
#pragma unroll
        for (int j = 0; j < 4; j++) {
            int m = mg + j;
            const float* Xr = Xs + m * 196;
            const float* pu = Xr + 3 * u0; const float* pv = Xr + 3 * v0;
            float ax = pu[0], ay = pu[1], az = pu[2];
            float bx = pv[0], by = pv[1], bz = pv[2];
            float c00 = ay * bz - az * by;
            float c01 = az * bx - ax * bz;
            float c02 = ax * by - ay * bx;
            pu = Xr + 3 * u1; pv = Xr + 3 * v1;
            ax = pu[0]; ay = pu[1]; az = pu[2];
            bx = pv[0]; by = pv[1]; bz = pv[2];
            float c10 = ay * bz - az * by;
            float c11 = az * bx - ax * bz;
            float c12 = ax * by - ay * bx;
            uint32_t hp, lp;
            int doff = m * (V_AS * 2) + kk2 * 2;
            split_pack(c00, c10, hp, lp);
            *(uint32_t*)(a0h + doff) = hp; *(uint32_t*)(a0l + doff) = lp;
            split_pack(c01, c11, hp, lp);
            *(uint32_t*)(a1h + doff) = hp; *(uint32_t*)(a1l + doff) = lp;
            split_pack(c02, c12, hp, lp);
            *(uint32_t*)(a2h + doff) = hp; *(uint32_t*)(a2l + doff) = lp;
        }
    };
    // B tile: 64 rows x 64 bf16 = 512 16B-chunks per buffer (hi & lo)
    auto fetch_B = [&](int c, int st) {
        const uint32_t bh = sb + VB_OFF(st, 0);
        const uint32_t bl = sb + VB_OFF(st, 1);
        int r = t >> 3, cc = (t & 7) * 8;
        uint32_t doff = (uint32_t)(r * (V_BS * 2) + cc * 2);
        size_t gi = (size_t)(c * 64 + r) * NVD + cc;
        cp16(bh + doff, g_WVAh + gi);
        cp16(bl + doff, g_WVAl + gi);
        asm volatile("cp.async.commit_group;" ::: "memory");
    };

    float acc[2][3][4];
#pragma unroll
    for (int mt = 0; mt < 2; mt++)
#pragma unroll
        for (int cp = 0; cp < 3; cp++)
#pragma unroll
            for (int q = 0; q < 4; q++) acc[mt][cp][q] = 0.0f;

    const uint32_t a_eoff = (uint32_t)((wm * 32 + (lane & 15)) * V_AS +
                                       (lane >> 4) * 8) * 2;
    const uint32_t b_eoff = (uint32_t)((lane & 15) * V_BS + wn * 8) * 2;

    fetch_B(0, 0);
    build_A(0, 0);
    asm volatile("cp.async.wait_group 0;" ::: "memory");
    __syncthreads();

    for (int i = 0; i < NCHV; i++) {
        const int s = i & 1;
        if (i + 1 < NCHV) {
            fetch_B(i + 1, s ^ 1);
            build_A(i + 1, s ^ 1);
        }

#pragma unroll
        for (int ks = 0; ks < 4; ks++) {
            uint32_t bh[2], bl[2];
            uint32_t eo_b = b_eoff + (uint32_t)(ks * 16 * V_BS) * 2;
            ldsm_x2t(bh, sb + VB_OFF(s, 0) + eo_b);
            ldsm_x2t(bl, sb + VB_OFF(s, 1) + eo_b);
#pragma unroll
            for (int cp = 0; cp < 3; cp++) {
#pragma unroll
                for (int mt = 0; mt < 2; mt++) {
                    uint32_t ah[4], al[4];
                    uint32_t eo = a_eoff + (uint32_t)(mt * 16 * V_AS + ks * 16) * 2;
                    ldsm_x4(ah, sb + VA_OFF(s, cp, 0) + eo);
                    ldsm_x4(al, sb + VA_OFF(s, cp, 1) + eo);
                    mma_bf16(acc[mt][cp], ah, bh);
                    mma_bf16(acc[mt][cp], ah, bl);
                    mma_bf16(acc[mt][cp], al, bh);
                }
            }
        }

        if (i + 1 < NCHV) {
            asm volatile("cp.async.wait_group 0;" ::: "memory");
            __syncthreads();
        }
    }

    // epilogue: + v011 from Z, gate, store
#pragma unroll
    for (int mt = 0; mt < 2; mt++) {
#pragma unroll
        for (int qp = 0; qp < 2; qp++) {
            int rloc = wm * 32 + mt * 16 + (lane >> 2) + qp * 8;
            int rr = row0 + rloc;
            int cc = wn * 8 + (lane & 3) * 2;
            float v0[3], v1[3];
#pragma unroll
            for (int cp = 0; cp < 3; cp++) {
                v0[cp] = acc[mt][cp][qp * 2];
                v1[cp] = acc[mt][cp][qp * 2 + 1];
            }
            const float* Zr = g_Z + (size_t)rr * 4096 + cc;
            const float* Xr = Xs + rloc * 196;
            for (int n = 0; n < 64; n++) {
                float2 z = *(const float2*)&Zr[n * 64];
                float xa = Xr[3 * n], xb = Xr[3 * n + 1], xc = Xr[3 * n + 2];
                v0[0] += xa * z.x; v0[1] += xb * z.x; v0[2] += xc * z.x;
                v1[0] += xa * z.y; v1[1] += xb * z.y; v1[2] += xc * z.y;
            }
            float g0 = g_G[rr * 64 + cc];
            float g1 = g_G[rr * 64 + cc + 1];
            float* orow = out + (size_t)rr * XDIM + 128;
#pragma unroll
            for (int k = 0; k < 3; k++) {
                orow[cc * 3 + k]       = v0[k] * g0;
                orow[(cc + 1) * 3 + k] = v1[k] * g1;
            }
        }
    }
}

// ---------------------------------------------------------------------------
extern "C" void kernel_launch(void* const* d_in, const int* in_sizes, int n_in,
                              void* d_out, int out_size) {
    const float* x = 0;
    const float* w000 = 0;
    const float* w110 = 0;
    const float* w011 = 0;
    const float* w111 = 0;
    for (int i = 0; i < n_in; i++) {
        switch (in_sizes[i]) {
            case BATCH * XDIM:       x    = (const float*)d_in[i]; break;
            case NN0 * NN0 * NSV:    w000 = (const float*)d_in[i]; break;
            case NN1 * NN1 * NSV:    w110 = (const float*)d_in[i]; break;
            case NN0 * NN1 * NVD:    w011 = (const float*)d_in[i]; break;
            case NN1 * NN1 * NVD:    w111 = (const float*)d_in[i]; break;
            default: break;
        }
    }
    if (!x)    x    = (const float*)d_in[0];
    if (!w000) w000 = (const float*)d_in[1];
    if (!w110) w110 = (const float*)d_in[2];
    if (!w011) w011 = (const float*)d_in[3];
    if (!w111) w111 = (const float*)d_in[4];
    float* out = (float*)d_out;

    cudaFuncSetAttribute(scalars_tc9,
                         cudaFuncAttributeMaxDynamicSharedMemorySize, TC_SMEM);
    cudaFuncSetAttribute(g3_tc,
                         cudaFuncAttributeMaxDynamicSharedMemorySize, G3T_SMEM);
    cudaFuncSetAttribute(vectors_tc,
                         cudaFuncAttributeMaxDynamicSharedMemorySize, VS_SMEM);

    build_wsc<<<(KSC_PAD * NSV + 255) / 256, 256>>>(w000, w110);
    build_wva<<<(NPA_PAD * NVD + 255) / 256, 256>>>(w111);
    build_w3<<<(NN0 * NN1 * NVD + 255) / 256, 256>>>(w011);
    g3_tc<<<dim3(BATCH / 64, 4096 / 128), 256, G3T_SMEM>>>(x);
    scalars_tc9<<<BATCH / 64, 512, TC_SMEM>>>(x, out);
    vectors_tc<<<BATCH / 64, 512, VS_SMEM>>>(x, out);
}

// round 12
// speedup vs baseline: 3.2224x; 1.1972x over previous
#include <cuda_runtime.h>
#include <cuda_fp16.h>
#include <math.h>
#include <stdint.h>

// ---------------------------------------------------------------------------
// PE_GatedBlock: B=8192, N0=128, N1=64, NS=128, NV=64
//   scalars = [sym-pair feats x0 | sym-dot feats x1] @ WSC   (mma.sync fp16)
//   Z = (1/128) x0 @ w011                                    (mma.sync fp16)
//   v111 = cross feats @ WVA                                 (mma.sync fp16)
//   v011 from Z contraction (fp32 epilogue), gating fused.
//   out = [silu(s[:,:128]) | (v111+v011)*sigmoid(s[:,128:])]
// Precision scheme: features = single fp16 (err ~2^-12); weights = fp16 hi+lo
// Dekker pair (err ~1e-5); 2 MMA products per logical product: a*bh + a*bl.
// NOTE: harness ptxas targets sm_103 (no 'a') -> tcgen05 unavailable; mma.sync.
// ---------------------------------------------------------------------------

#define BATCH   8192
#define XDIM    320
#define NN0     128
#define NN1     64
#define NSV     192
#define NVD     64

#define NP0     8256
#define NP1     2080
#define NPA     2016
#define NPA_PAD 2048                 // 32*64 (zero-padded)
#define NCHV    32
#define KSC     (NP0 + NP1)          // 10336
#define KSC_PAD 10368                // 162*64 ; NP0 = 129*64 exactly
#define NCHUNK  162
#define NCH0    129                  // chunks 0..128 x0-pairs, 129.. x1-dots

// ---- static device scratch -------------------------------------------------
__device__ __align__(16) __half g_WSCh[KSC_PAD * NSV];   // [k][n] hi
__device__ __align__(16) __half g_WSCl[KSC_PAD * NSV];   // [k][n] lo (residual)
__device__ __align__(16) __half g_W3h[NN0 * NN1 * NVD];  // [u][v*64+w] hi
__device__ __align__(16) __half g_W3l[NN0 * NN1 * NVD];  // lo
__device__ __align__(16) __half g_WVAh[NPA_PAD * NVD];   // [p][w] hi
__device__ __align__(16) __half g_WVAl[NPA_PAD * NVD];   // lo
__device__ __align__(4) unsigned short g_sp[KSC_PAD];
__device__ __align__(4) unsigned short g_pa[NPA_PAD];
__device__ float g_Z[(size_t)BATCH * NN1 * NVD];
__device__ float g_G[BATCH * NVD];

// ---- triangular index helpers ----------------------------------------------
__device__ __forceinline__ void tri_le(int p, int& u, int& v) {
    int vv = (int)floorf((sqrtf(8.0f * (float)p + 1.0f) - 1.0f) * 0.5f);
    while ((vv + 1) * (vv + 2) / 2 <= p) vv++;
    while (vv * (vv + 1) / 2 > p) vv--;
    v = vv;
    u = p - vv * (vv + 1) / 2;
}
__device__ __forceinline__ void tri_lt(int p, int& u, int& v) {
    int vv = (int)floorf((1.0f + sqrtf(8.0f * (float)p + 1.0f)) * 0.5f);
    while ((vv + 1) * vv / 2 <= p) vv++;
    while (vv * (vv - 1) / 2 > p) vv--;
    v = vv;
    u = p - vv * (vv - 1) / 2;
}

// pack two fp32 -> fp16x2 (f0 in low half, f1 in high half)
__device__ __forceinline__ uint32_t pack_f16x2(float f0, float f1) {
    __half2 h2 = __floats2half2_rn(f0, f1);
    return *(uint32_t*)&h2;
}

// ---- pair-list kernel (one-time index math) ---------------------------------
__global__ void build_pairs() {
    int p = blockIdx.x * blockDim.x + threadIdx.x;
    if (p < KSC_PAD) {
        unsigned short pk = 0;
        if (p < NP0) {
            int u, v; tri_le(p, u, v);
            pk = (unsigned short)((u << 8) | v);
        } else if (p < KSC) {
            int u, v; tri_le(p - NP0, u, v);
            pk = (unsigned short)((u << 8) | v);
        }
        g_sp[p] = pk;
    }
    if (p < NPA_PAD) {
        unsigned short pk = 0;
        if (p < NPA) {
            int u, v; tri_lt(p, u, v);
            pk = (unsigned short)((u << 8) | v);
        }
        g_pa[p] = pk;
    }
}

// ---- weight folding: fold + fp16 hi/lo split ---------------------------------
// one block per k-row; threads = n columns (coalesced loads/stores)
__global__ void build_wsc(const float* __restrict__ w000,
                          const float* __restrict__ w110) {
    int p = blockIdx.x;          // 0..KSC_PAD-1
    int w = threadIdx.x;         // 0..191
    const float inv_sqrt2 = 0.7071067811865476f;
    float f = 0.0f;
    unsigned int pk = g_sp[p];
    int u = pk >> 8, v = pk & 255;
    if (p < NP0) {
        float val = w000[(u * NN0 + v) * NSV + w];
        if (u != v) val += w000[(v * NN0 + u) * NSV + w];
        f = (inv_sqrt2 / 128.0f) * val;
    } else if (p < KSC) {
        float val = w110[(u * NN1 + v) * NSV + w];
        if (u != v) val += w110[(v * NN1 + u) * NSV + w];
        f = (inv_sqrt2 / (64.0f * 1.7320508075688772f)) * val;
    }
    __half h = __float2half_rn(f);
    g_WSCh[p * NSV + w] = h;
    g_WSCl[p * NSV + w] = __float2half_rn(f - __half2float(h));
}

__global__ void build_wva(const float* __restrict__ w111) {
    int p = blockIdx.x;          // 0..NPA_PAD-1
    int w = threadIdx.x;         // 0..63
    float f = 0.0f;
    unsigned int pk = g_pa[p];
    int u = pk >> 8, v = pk & 255;
    if (p < NPA) {
        f = (1.0f / 128.0f) *
            (w111[(u * NN1 + v) * NVD + w] - w111[(v * NN1 + u) * NVD + w]);
    }
    __half h = __float2half_rn(f);
    g_WVAh[p * NVD + w] = h;
    g_WVAl[p * NVD + w] = __float2half_rn(f - __half2float(h));
}

__global__ void build_w3(const float* __restrict__ w011) {
    int idx = blockIdx.x * blockDim.x + threadIdx.x;
    if (idx >= NN0 * NN1 * NVD) return;
    float f = w011[idx] * (1.0f / 128.0f);   // inv_sqrt2 / sqrt(N0*N1)
    __half h = __float2half_rn(f);
    g_W3h[idx] = h;
    g_W3l[idx] = __float2half_rn(f - __half2float(h));
}

// ---- mma.sync helpers --------------------------------------------------------
__device__ __forceinline__ void mma_f16(float* d, const uint32_t* a, const uint32_t* b) {
    asm volatile(
        "mma.sync.aligned.m16n8k16.row.col.f32.f16.f16.f32 "
        "{%0,%1,%2,%3}, {%4,%5,%6,%7}, {%8,%9}, {%0,%1,%2,%3};\n"
        : "+f"(d[0]), "+f"(d[1]), "+f"(d[2]), "+f"(d[3])
        : "r"(a[0]), "r"(a[1]), "r"(a[2]), "r"(a[3]), "r"(b[0]), "r"(b[1]));
}
__device__ __forceinline__ void ldsm_x4(uint32_t* r, uint32_t addr) {
    asm volatile("ldmatrix.sync.aligned.m8n8.x4.shared.b16 {%0,%1,%2,%3}, [%4];"
                 : "=r"(r[0]), "=r"(r[1]), "=r"(r[2]), "=r"(r[3]) : "r"(addr));
}
__device__ __forceinline__ void ldsm_x2t(uint32_t* r, uint32_t addr) {
    asm volatile("ldmatrix.sync.aligned.m8n8.x2.trans.shared.b16 {%0,%1}, [%2];"
                 : "=r"(r[0]), "=r"(r[1]) : "r"(addr));
}
__device__ __forceinline__ void cp16(uint32_t dst, const void* src) {
    asm volatile("cp.async.cg.shared.global [%0], [%1], 16;"
                 :: "r"(dst), "l"(src) : "memory");
}

// ---- g3 on tensor cores: g_Z = x0[8192x128] @ W3[128x4096] -------------------
// A single fp16; B fp16 hi/lo; 2 products.
#define G3_AS  136
#define G3_BS  136
#define G3_A   0
#define G3_BH  17408
#define G3_BL  52224
#define G3T_SMEM 87040

__global__ void __launch_bounds__(256) g3_tc(const float* __restrict__ x) {
    extern __shared__ char g3m[];
    const int t = threadIdx.x;
    const int lane = t & 31, warp = t >> 5;
    const int wm = warp & 1, wn = warp >> 1;
    const int row0 = blockIdx.x * 64;
    const int col0 = blockIdx.y * 128;

    uint32_t sb;
    asm("{ .reg .u64 u; cvta.to.shared.u64 u, %1; cvt.u32.u64 %0, u; }"
        : "=r"(sb) : "l"(g3m));

    // B tile: 128 k-rows x 128 n-cols fp16, hi & lo (2048 16B chunks each)
#pragma unroll
    for (int j = 0; j < 8; j++) {
        int i = t + j * 256;
        int r = i >> 4, cc = (i & 15) * 8;
        uint32_t doff = (uint32_t)(r * (G3_BS * 2) + cc * 2);
        size_t gi = (size_t)r * 4096 + col0 + cc;
        cp16(sb + G3_BH + doff, g_W3h + gi);
        cp16(sb + G3_BL + doff, g_W3l + gi);
    }
    asm volatile("cp.async.commit_group;" ::: "memory");

    // A tile: 64 rows x 128 k fp32 -> single fp16
    for (int i = t; i < 4096; i += 256) {
        int r = i >> 6, c2 = (i & 63) * 2;
        const float* xp = x + (size_t)(row0 + r) * XDIM + c2;
        *(uint32_t*)(g3m + G3_A + r * (G3_AS * 2) + c2 * 2) = pack_f16x2(xp[0], xp[1]);
    }
    asm volatile("cp.async.wait_group 0;" ::: "memory");
    __syncthreads();

    float acc[2][4][4];
#pragma unroll
    for (int mt = 0; mt < 2; mt++)
#pragma unroll
        for (int nt = 0; nt < 4; nt++)
#pragma unroll
            for (int q = 0; q < 4; q++) acc[mt][nt][q] = 0.0f;

    const uint32_t a_eoff = (uint32_t)((wm * 32 + (lane & 15)) * G3_AS +
                                       (lane >> 4) * 8) * 2;
    const uint32_t b_eoff = (uint32_t)((lane & 15) * G3_BS + wn * 32) * 2;

#pragma unroll
    for (int ks = 0; ks < 8; ks++) {
        uint32_t a[2][4];
#pragma unroll
        for (int mt = 0; mt < 2; mt++) {
            uint32_t eo = a_eoff + (uint32_t)(mt * 16 * G3_AS + ks * 16) * 2;
            ldsm_x4(a[mt], sb + G3_A + eo);
        }
        uint32_t bh[4][2], bl[4][2];
#pragma unroll
        for (int nt = 0; nt < 4; nt++) {
            uint32_t eo = b_eoff + (uint32_t)(ks * 16 * G3_BS + nt * 8) * 2;
            ldsm_x2t(bh[nt], sb + G3_BH + eo);
            ldsm_x2t(bl[nt], sb + G3_BL + eo);
        }
#pragma unroll
        for (int mt = 0; mt < 2; mt++)
#pragma unroll
            for (int nt = 0; nt < 4; nt++) {
                mma_f16(acc[mt][nt], a[mt], bh[nt]);
                mma_f16(acc[mt][nt], a[mt], bl[nt]);
            }
    }

#pragma unroll
    for (int mt = 0; mt < 2; mt++)
#pragma unroll
        for (int nt = 0; nt < 4; nt++) {
            int r = row0 + wm * 32 + mt * 16 + (lane >> 2);
            int c = col0 + wn * 32 + nt * 8 + (lane & 3) * 2;
            float2 v0 = {acc[mt][nt][0], acc[mt][nt][1]};
            float2 v1 = {acc[mt][nt][2], acc[mt][nt][3]};
            *(float2*)&g_Z[(size_t)r * 4096 + c]       = v0;
            *(float2*)&g_Z[(size_t)(r + 8) * 4096 + c] = v1;
        }
}

// ---- scalars: pipelined mma.sync GEMM, 512 threads ----------------------------
// A = features single fp16 (built in smem); B = WSC fp16 hi/lo; 2 products.
#define AS_STRIDE 72      // fp16; 144B rows -> ldmatrix conflict-free
#define BS_STRIDE 216     // fp16; 432B rows -> ldmatrix conflict-free

#define SM_XS   0                           // p1: 64x132 f32; p2: 64x196 f32
#define SM_A0   50176
#define SM_A1   59392
#define SM_BH0  68608
#define SM_BL0  96256
#define SM_BH1  123904
#define SM_BL1  151552
#define TC_SMEM 179200

__global__ void __launch_bounds__(512) scalars_tc11(const float* __restrict__ x,
                                                    float* __restrict__ out) {
    extern __shared__ char tcsm[];
    float* Xs = (float*)(tcsm + SM_XS);
    const int t = threadIdx.x;
    const int lane = t & 31, warp = t >> 5;
    const int wm = warp & 1, wn = warp >> 1;       // 2 x 8
    const int row0 = blockIdx.x * 64;

    uint32_t sb;
    asm("{ .reg .u64 u; cvta.to.shared.u64 u, %1; cvt.u32.u64 %0, u; }"
        : "=r"(sb) : "l"(tcsm));

    const uint32_t AA[2] = {sb + SM_A0, sb + SM_A1};
    const uint32_t BH[2] = {sb + SM_BH0, sb + SM_BH1};
    const uint32_t BL[2] = {sb + SM_BL0, sb + SM_BL1};

    // phase-1 x tile: x0 (64 rows x 128 f32, stride 132)
    for (int i = t; i < 64 * 32; i += 512) {
        int r = i >> 5, c4 = (i & 31) << 2;
        *(float4*)&Xs[r * 132 + c4] =
            *(const float4*)&x[(size_t)(row0 + r) * XDIM + c4];
    }
    __syncthreads();

    const int kk2 = lane * 2;
    const int mg = warp * 4;

    auto build_A = [&](int c, int st) {
        char* aa = tcsm + (st ? SM_A1 : SM_A0);
        int kg = c * 64 + kk2;
        uint32_t pk = __ldg((const uint32_t*)&g_sp[kg]);
        int u0 = (pk >> 8) & 255, v0 = pk & 255;
        int u1 = pk >> 24,       v1 = (pk >> 16) & 255;
        if (c < NCH0) {
#pragma unroll
            for (int j = 0; j < 4; j++) {
                int m = mg + j;
                const float* Xr = Xs + m * 132;
                float f0 = Xr[u0] * Xr[v0];
                float f1 = Xr[u1] * Xr[v1];
                *(uint32_t*)(aa + m * (AS_STRIDE * 2) + kk2 * 2) = pack_f16x2(f0, f1);
            }
        } else {
#pragma unroll
            for (int j = 0; j < 4; j++) {
                int m = mg + j;
                const float* Xr = Xs + m * 196;
                const float* a0 = Xr + 3 * u0; const float* b0 = Xr + 3 * v0;
                const float* a1 = Xr + 3 * u1; const float* b1 = Xr + 3 * v1;
                float f0 = a0[0] * b0[0] + a0[1] * b0[1] + a0[2] * b0[2];
                float f1 = a1[0] * b1[0] + a1[1] * b1[1] + a1[2] * b1[2];
                *(uint32_t*)(aa + m * (AS_STRIDE * 2) + kk2 * 2) = pack_f16x2(f0, f1);
            }
        }
    };
    // B tile: 64 rows x 192 fp16 = 1536 16B-chunks per buffer (hi & lo)
    auto fetch_B = [&](int c, int st) {
        const uint32_t bh = BH[st], bl = BL[st];
        const int k0 = c * 64;
#pragma unroll
        for (int j = 0; j < 3; j++) {
            int i = t + j * 512;
            int r = i / 24, cc = (i - r * 24) * 8;
            uint32_t doff = (uint32_t)(r * (BS_STRIDE * 2) + cc * 2);
            size_t gi = (size_t)(k0 + r) * NSV + cc;
            cp16(bh + doff, g_WSCh + gi);
            cp16(bl + doff, g_WSCl + gi);
        }
        asm volatile("cp.async.commit_group;" ::: "memory");
    };

    float acc[2][3][4];
#pragma unroll
    for (int mt = 0; mt < 2; mt++)
#pragma unroll
        for (int nt = 0; nt < 3; nt++)
#pragma unroll
            for (int q = 0; q < 4; q++) acc[mt][nt][q] = 0.0f;

    const uint32_t a_eoff = (uint32_t)((wm * 32 + (lane & 15)) * AS_STRIDE +
                                       (lane >> 4) * 8) * 2;
    const uint32_t b_eoff = (uint32_t)((lane & 15) * BS_STRIDE + wn * 24) * 2;

    fetch_B(0, 0);
    build_A(0, 0);
    asm volatile("cp.async.wait_group 0;" ::: "memory");
    __syncthreads();

    for (int i = 0; i < NCHUNK; i++) {
        const int s = i & 1;
        if (i + 1 < NCHUNK) {
            if (i + 1 == NCH0) {
                for (int j = t; j < 64 * 48; j += 512) {
                    int r = j / 48, c4 = (j - r * 48) << 2;
                    *(float4*)&Xs[r * 196 + c4] =
                        *(const float4*)&x[(size_t)(row0 + r) * XDIM + 128 + c4];
                }
                __syncthreads();
            }
            fetch_B(i + 1, s ^ 1);
            build_A(i + 1, s ^ 1);
        }

#pragma unroll
        for (int ks = 0; ks < 4; ks++) {
            uint32_t a[2][4];
#pragma unroll
            for (int mt = 0; mt < 2; mt++) {
                uint32_t eo = a_eoff + (uint32_t)(mt * 16 * AS_STRIDE + ks * 16) * 2;
                ldsm_x4(a[mt], AA[s] + eo);
            }
            uint32_t bh[3][2], bl[3][2];
#pragma unroll
            for (int nt = 0; nt < 3; nt++) {
                uint32_t eo = b_eoff + (uint32_t)(ks * 16 * BS_STRIDE + nt * 8) * 2;
                ldsm_x2t(bh[nt], BH[s] + eo);
                ldsm_x2t(bl[nt], BL[s] + eo);
            }
#pragma unroll
            for (int mt = 0; mt < 2; mt++)
#pragma unroll
                for (int nt = 0; nt < 3; nt++) {
                    mma_f16(acc[mt][nt], a[mt], bh[nt]);
                    mma_f16(acc[mt][nt], a[mt], bl[nt]);
                }
        }

        if (i + 1 < NCHUNK) {
            asm volatile("cp.async.wait_group 0;" ::: "memory");
            __syncthreads();
        }
    }

    // epilogue: silu -> out[:, :128], sigmoid -> g_G
#pragma unroll
    for (int mt = 0; mt < 2; mt++) {
#pragma unroll
        for (int nt = 0; nt < 3; nt++) {
            int r = row0 + wm * 32 + mt * 16 + (lane >> 2);
            int c = wn * 24 + nt * 8 + (lane & 3) * 2;
#pragma unroll
            for (int q = 0; q < 4; q++) {
                int rr = r + (q >> 1) * 8;
                int cc = c + (q & 1);
                float s = acc[mt][nt][q];
                float sg = 1.0f / (1.0f + __expf(-s));
                if (cc < 128) out[(size_t)rr * XDIM + cc] = s * sg;
                else          g_G[rr * 64 + (cc - 128)] = sg;
            }
        }
    }
}

// ---- vectors on tensor cores ---------------------------------------------------
// v111[b,w,k] = cross_k feats [8192 x 2048] @ WVA[2048 x 64]  (3 comps, fp16)
// A = single fp16 per comp; B = fp16 hi/lo; 2 products. Epilogue adds v011 + gate.
#define V_AS 72
#define V_BS 72
#define VS_XS 0                                   // 64 x 196 f32 (x1 rows)
#define VS_A  50176                               // 6 bufs: [st][comp]
#define VS_B  105472                              // 4 bufs: [st][hi/lo]
#define VS_SMEM 142336
#define VA_OFF(st, comp)  (VS_A + (((st) * 3) + (comp)) * 9216)
#define VB_OFF(st, hl)    (VS_B + ((st) * 2 + (hl)) * 9216)

__global__ void __launch_bounds__(512) vectors_tc(const float* __restrict__ x,
                                                  float* __restrict__ out) {
    extern __shared__ char vsm[];
    float* Xs = (float*)(vsm + VS_XS);
    const int t = threadIdx.x;
    const int lane = t & 31, warp = t >> 5;
    const int wm = warp & 1, wn = warp >> 1;       // 2 x 8
    const int row0 = blockIdx.x * 64;

    uint32_t sb;
    asm("{ .reg .u64 u; cvta.to.shared.u64 u, %1; cvt.u32.u64 %0, u; }"
        : "=r"(sb) : "l"(vsm));

    // x1 tile: 64 rows x 192 f32, stride 196
    for (int i = t; i < 64 * 48; i += 512) {
        int r = i / 48, c4 = (i - r * 48) << 2;
        *(float4*)&Xs[r * 196 + c4] =
            *(const float4*)&x[(size_t)(row0 + r) * XDIM + 128 + c4];
    }
    __syncthreads();

    const int kk2 = lane * 2;
    const int mg = warp * 4;

    auto build_A = [&](int c, int st) {
        char* a0p = vsm + VA_OFF(st, 0);
        char* a1p = vsm + VA_OFF(st, 1);
        char* a2p = vsm + VA_OFF(st, 2);
        int kg = c * 64 + kk2;
        uint32_t pk = __ldg((const uint32_t*)&g_pa[kg]);
        int u0 = (pk >> 8) & 255, v0 = pk & 255;
        int u1 = pk >> 24,       v1 = (pk >> 16) & 255;
#pragma unroll
        for (int j = 0; j < 4; j++) {
            int m = mg + j;
            const float* Xr = Xs + m * 196;
            const float* pu = Xr + 3 * u0; const float* pv = Xr + 3 * v0;
            float ax = pu[0], ay = pu[1], az = pu[2];
            float bx = pv[0], by = pv[1], bz = pv[2];
            float c00 = ay * bz - az * by;
            float c01 = az * bx - ax * bz;
            float c02 = ax * by - ay * bx;
            pu = Xr + 3 * u1; pv = Xr + 3 * v1;
            ax = pu[0]; ay = pu[1]; az = pu[2];
            bx = pv[0]; by = pv[1]; bz = pv[2];
            float c10 = ay * bz - az * by;
            float c11 = az * bx - ax * bz;
            float c12 = ax * by - ay * bx;
            int doff = m * (V_AS * 2) + kk2 * 2;
            *(uint32_t*)(a0p + doff) = pack_f16x2(c00, c10);
            *(uint32_t*)(a1p + doff) = pack_f16x2(c01, c11);
            *(uint32_t*)(a2p + doff) = pack_f16x2(c02, c12);
        }
    };
    // B tile: 64 rows x 64 fp16 = 512 16B-chunks per buffer (hi & lo)
    auto fetch_B = [&](int c, int st) {
        const uint32_t bh = sb + VB_OFF(st, 0);
        const uint32_t bl = sb + VB_OFF(st, 1);
        int r = t >> 3, cc = (t & 7) * 8;
        uint32_t doff = (uint32_t)(r * (V_BS * 2) + cc * 2);
        size_t gi = (size_t)(c * 64 + r) * NVD + cc;
        cp16(bh + doff, g_WVAh + gi);
        cp16(bl + doff, g_WVAl + gi);
        asm volatile("cp.async.commit_group;" ::: "memory");
    };

    float acc[2][3][4];
#pragma unroll
    for (int mt = 0; mt < 2; mt++)
#pragma unroll
        for (int cp = 0; cp < 3; cp++)
#pragma unroll
            for (int q = 0; q < 4; q++) acc[mt][cp][q] = 0.0f;

    const uint32_t a_eoff = (uint32_t)((wm * 32 + (lane & 15)) * V_AS +
                                       (lane >> 4) * 8) * 2;
    const uint32_t b_eoff = (uint32_t)((lane & 15) * V_BS + wn * 8) * 2;

    fetch_B(0, 0);
    build_A(0, 0);
    asm volatile("cp.async.wait_group 0;" ::: "memory");
    __syncthreads();

    for (int i = 0; i < NCHV; i++) {
        const int s = i & 1;
        if (i + 1 < NCHV) {
            fetch_B(i + 1, s ^ 1);
            build_A(i + 1, s ^ 1);
        }

#pragma unroll
        for (int ks = 0; ks < 4; ks++) {
            uint32_t bh[2], bl[2];
            uint32_t eo_b = b_eoff + (uint32_t)(ks * 16 * V_BS) * 2;
            ldsm_x2t(bh, sb + VB_OFF(s, 0) + eo_b);
            ldsm_x2t(bl, sb + VB_OFF(s, 1) + eo_b);
#pragma unroll
            for (int cp = 0; cp < 3; cp++) {
#pragma unroll
                for (int mt = 0; mt < 2; mt++) {
                    uint32_t a[4];
                    uint32_t eo = a_eoff + (uint32_t)(mt * 16 * V_AS + ks * 16) * 2;
                    ldsm_x4(a, sb + VA_OFF(s, cp) + eo);
                    mma_f16(acc[mt][cp], a, bh);
                    mma_f16(acc[mt][cp], a, bl);
                }
            }
        }

        if (i + 1 < NCHV) {
            asm volatile("cp.async.wait_group 0;" ::: "memory");
            __syncthreads();
        }
    }

    // epilogue: + v011 from Z, gate, store
#pragma unroll
    for (int mt = 0; mt < 2; mt++) {
#pragma unroll
        for (int qp = 0; qp < 2; qp++) {
            int rloc = wm * 32 + mt * 16 + (lane >> 2) + qp * 8;
            int rr = row0 + rloc;
            int cc = wn * 8 + (lane & 3) * 2;
            float v0[3], v1[3];
#pragma unroll
            for (int cp = 0; cp < 3; cp++) {
                v0[cp] = acc[mt][cp][qp * 2];
                v1[cp] = acc[mt][cp][qp * 2 + 1];
            }
            const float* Zr = g_Z + (size_t)rr * 4096 + cc;
            const float* Xr = Xs + rloc * 196;
            for (int n = 0; n < 64; n++) {
                float2 z = *(const float2*)&Zr[n * 64];
                float xa = Xr[3 * n], xb = Xr[3 * n + 1], xc = Xr[3 * n + 2];
                v0[0] += xa * z.x; v0[1] += xb * z.x; v0[2] += xc * z.x;
                v1[0] += xa * z.y; v1[1] += xb * z.y; v1[2] += xc * z.y;
            }
            float g0 = g_G[rr * 64 + cc];
            float g1 = g_G[rr * 64 + cc + 1];
            float* orow = out + (size_t)rr * XDIM + 128;
#pragma unroll
            for (int k = 0; k < 3; k++) {
                orow[cc * 3 + k]       = v0[k] * g0;
                orow[(cc + 1) * 3 + k] = v1[k] * g1;
            }
        }
    }
}

// ---------------------------------------------------------------------------
extern "C" void kernel_launch(void* const* d_in, const int* in_sizes, int n_in,
                              void* d_out, int out_size) {
    const float* x = 0;
    const float* w000 = 0;
    const float* w110 = 0;
    const float* w011 = 0;
    const float* w111 = 0;
    for (int i = 0; i < n_in; i++) {
        switch (in_sizes[i]) {
            case BATCH * XDIM:       x    = (const float*)d_in[i]; break;
            case NN0 * NN0 * NSV:    w000 = (const float*)d_in[i]; break;
            case NN1 * NN1 * NSV:    w110 = (const float*)d_in[i]; break;
            case NN0 * NN1 * NVD:    w011 = (const float*)d_in[i]; break;
            case NN1 * NN1 * NVD:    w111 = (const float*)d_in[i]; break;
            default: break;
        }
    }
    if (!x)    x    = (const float*)d_in[0];
    if (!w000) w000 = (const float*)d_in[1];
    if (!w110) w110 = (const float*)d_in[2];
    if (!w011) w011 = (const float*)d_in[3];
    if (!w111) w111 = (const float*)d_in[4];
    float* out = (float*)d_out;

    cudaFuncSetAttribute(scalars_tc11,
                         cudaFuncAttributeMaxDynamicSharedMemorySize, TC_SMEM);
    cudaFuncSetAttribute(g3_tc,
                         cudaFuncAttributeMaxDynamicSharedMemorySize, G3T_SMEM);
    cudaFuncSetAttribute(vectors_tc,
                         cudaFuncAttributeMaxDynamicSharedMemorySize, VS_SMEM);

    build_pairs<<<(KSC_PAD + 255) / 256, 256>>>();
    build_wsc<<<KSC_PAD, NSV>>>(w000, w110);
    build_wva<<<NPA_PAD, NVD>>>(w111);
    build_w3<<<(NN0 * NN1 * NVD + 255) / 256, 256>>>(w011);
    g3_tc<<<dim3(BATCH / 64, 4096 / 128), 256, G3T_SMEM>>>(x);
    scalars_tc11<<<BATCH / 64, 512, TC_SMEM>>>(x, out);
    vectors_tc<<<BATCH / 64, 512, VS_SMEM>>>(x, out);
}

// round 13
// speedup vs baseline: 3.9807x; 1.2353x over previous
#include <cuda_runtime.h>
#include <cuda_fp16.h>
#include <math.h>
#include <stdint.h>

// ---------------------------------------------------------------------------
// PE_GatedBlock: B=8192, N0=128, N1=64, NS=128, NV=64
//   scalars = [sym-pair feats x0 | sym-dot feats x1] @ WSC   (mma.sync fp16)
//   Z = (1/128) x0 @ w011                                    (mma.sync fp16)
//   v111 = cross feats @ WVA                                 (mma.sync fp16)
//   v011 from Z contraction (fp32 epilogue), gating fused.
//   out = [silu(s[:,:128]) | (v111+v011)*sigmoid(s[:,128:])]
// Precision: features AND weights single fp16 (each err ~2^-12, independent);
// fp32 accumulate. Measured r12 (weights hi/lo): 2.2e-4; expected here ~3-4e-4.
// NOTE: harness ptxas targets sm_103 (no 'a') -> tcgen05 unavailable; mma.sync.
// ---------------------------------------------------------------------------

#define BATCH   8192
#define XDIM    320
#define NN0     128
#define NN1     64
#define NSV     192
#define NVD     64

#define NP0     8256
#define NP1     2080
#define NPA     2016
#define NPA_PAD 2048                 // 32*64 (zero-padded)
#define NCHV    32
#define KSC     (NP0 + NP1)          // 10336
#define KSC_PAD 10368                // 162*64 ; NP0 = 129*64 exactly
#define NCHUNK  162
#define NCH0    129                  // chunks 0..128 x0-pairs, 129.. x1-dots

// ---- static device scratch -------------------------------------------------
__device__ __align__(16) __half g_WSC[KSC_PAD * NSV];    // [k][n]
__device__ __align__(16) __half g_W3[NN0 * NN1 * NVD];   // [u][v*64+w]
__device__ __align__(16) __half g_WVA[NPA_PAD * NVD];    // [p][w]
__device__ __align__(4) unsigned short g_sp[KSC_PAD];
__device__ __align__(4) unsigned short g_pa[NPA_PAD];
__device__ float g_Z[(size_t)BATCH * NN1 * NVD];
__device__ float g_G[BATCH * NVD];

// ---- triangular index helpers ----------------------------------------------
__device__ __forceinline__ void tri_le(int p, int& u, int& v) {
    int vv = (int)floorf((sqrtf(8.0f * (float)p + 1.0f) - 1.0f) * 0.5f);
    while ((vv + 1) * (vv + 2) / 2 <= p) vv++;
    while (vv * (vv + 1) / 2 > p) vv--;
    v = vv;
    u = p - vv * (vv + 1) / 2;
}
__device__ __forceinline__ void tri_lt(int p, int& u, int& v) {
    int vv = (int)floorf((1.0f + sqrtf(8.0f * (float)p + 1.0f)) * 0.5f);
    while ((vv + 1) * vv / 2 <= p) vv++;
    while (vv * (vv - 1) / 2 > p) vv--;
    v = vv;
    u = p - vv * (vv - 1) / 2;
}

// pack two fp32 -> fp16x2 (f0 low half, f1 high half)
__device__ __forceinline__ uint32_t pack_f16x2(float f0, float f1) {
    __half2 h2 = __floats2half2_rn(f0, f1);
    return *(uint32_t*)&h2;
}

// ---- pair-list kernel (one-time index math) ---------------------------------
__global__ void build_pairs() {
    int p = blockIdx.x * blockDim.x + threadIdx.x;
    if (p < KSC_PAD) {
        unsigned short pk = 0;
        if (p < NP0) {
            int u, v; tri_le(p, u, v);
            pk = (unsigned short)((u << 8) | v);
        } else if (p < KSC) {
            int u, v; tri_le(p - NP0, u, v);
            pk = (unsigned short)((u << 8) | v);
        }
        g_sp[p] = pk;
    }
    if (p < NPA_PAD) {
        unsigned short pk = 0;
        if (p < NPA) {
            int u, v; tri_lt(p, u, v);
            pk = (unsigned short)((u << 8) | v);
        }
        g_pa[p] = pk;
    }
}

// ---- weight folding: fold -> single fp16 -------------------------------------
__global__ void build_wsc(const float* __restrict__ w000,
                          const float* __restrict__ w110) {
    int p = blockIdx.x;          // 0..KSC_PAD-1
    int w = threadIdx.x;         // 0..191
    const float inv_sqrt2 = 0.7071067811865476f;
    float f = 0.0f;
    unsigned int pk = g_sp[p];
    int u = pk >> 8, v = pk & 255;
    if (p < NP0) {
        float val = w000[(u * NN0 + v) * NSV + w];
        if (u != v) val += w000[(v * NN0 + u) * NSV + w];
        f = (inv_sqrt2 / 128.0f) * val;
    } else if (p < KSC) {
        float val = w110[(u * NN1 + v) * NSV + w];
        if (u != v) val += w110[(v * NN1 + u) * NSV + w];
        f = (inv_sqrt2 / (64.0f * 1.7320508075688772f)) * val;
    }
    g_WSC[p * NSV + w] = __float2half_rn(f);
}

__global__ void build_wva(const float* __restrict__ w111) {
    int p = blockIdx.x;          // 0..NPA_PAD-1
    int w = threadIdx.x;         // 0..63
    float f = 0.0f;
    unsigned int pk = g_pa[p];
    int u = pk >> 8, v = pk & 255;
    if (p < NPA) {
        f = (1.0f / 128.0f) *
            (w111[(u * NN1 + v) * NVD + w] - w111[(v * NN1 + u) * NVD + w]);
    }
    g_WVA[p * NVD + w] = __float2half_rn(f);
}

__global__ void build_w3(const float* __restrict__ w011) {
    int idx = blockIdx.x * blockDim.x + threadIdx.x;
    if (idx >= NN0 * NN1 * NVD) return;
    g_W3[idx] = __float2half_rn(w011[idx] * (1.0f / 128.0f));
}

// ---- mma.sync helpers --------------------------------------------------------
__device__ __forceinline__ void mma_f16(float* d, const uint32_t* a, const uint32_t* b) {
    asm volatile(
        "mma.sync.aligned.m16n8k16.row.col.f32.f16.f16.f32 "
        "{%0,%1,%2,%3}, {%4,%5,%6,%7}, {%8,%9}, {%0,%1,%2,%3};\n"
        : "+f"(d[0]), "+f"(d[1]), "+f"(d[2]), "+f"(d[3])
        : "r"(a[0]), "r"(a[1]), "r"(a[2]), "r"(a[3]), "r"(b[0]), "r"(b[1]));
}
__device__ __forceinline__ void ldsm_x4(uint32_t* r, uint32_t addr) {
    asm volatile("ldmatrix.sync.aligned.m8n8.x4.shared.b16 {%0,%1,%2,%3}, [%4];"
                 : "=r"(r[0]), "=r"(r[1]), "=r"(r[2]), "=r"(r[3]) : "r"(addr));
}
__device__ __forceinline__ void ldsm_x2t(uint32_t* r, uint32_t addr) {
    asm volatile("ldmatrix.sync.aligned.m8n8.x2.trans.shared.b16 {%0,%1}, [%2];"
                 : "=r"(r[0]), "=r"(r[1]) : "r"(addr));
}
__device__ __forceinline__ void cp16(uint32_t dst, const void* src) {
    asm volatile("cp.async.cg.shared.global [%0], [%1], 16;"
                 :: "r"(dst), "l"(src) : "memory");
}

// ---- g3 on tensor cores: g_Z = x0[8192x128] @ W3[128x4096] -------------------
#define G3_AS  136
#define G3_BS  136
#define G3_A   0
#define G3_B   17408
#define G3T_SMEM 52224

__global__ void __launch_bounds__(256) g3_tc(const float* __restrict__ x) {
    extern __shared__ char g3m[];
    const int t = threadIdx.x;
    const int lane = t & 31, warp = t >> 5;
    const int wm = warp & 1, wn = warp >> 1;
    const int row0 = blockIdx.x * 64;
    const int col0 = blockIdx.y * 128;

    uint32_t sb;
    asm("{ .reg .u64 u; cvta.to.shared.u64 u, %1; cvt.u32.u64 %0, u; }"
        : "=r"(sb) : "l"(g3m));

    // B tile: 128 k-rows x 128 n-cols fp16 (2048 16B chunks)
#pragma unroll
    for (int j = 0; j < 8; j++) {
        int i = t + j * 256;
        int r = i >> 4, cc = (i & 15) * 8;
        uint32_t doff = (uint32_t)(r * (G3_BS * 2) + cc * 2);
        cp16(sb + G3_B + doff, g_W3 + (size_t)r * 4096 + col0 + cc);
    }
    asm volatile("cp.async.commit_group;" ::: "memory");

    // A tile: 64 rows x 128 k fp32 -> fp16
    for (int i = t; i < 4096; i += 256) {
        int r = i >> 6, c2 = (i & 63) * 2;
        const float* xp = x + (size_t)(row0 + r) * XDIM + c2;
        *(uint32_t*)(g3m + G3_A + r * (G3_AS * 2) + c2 * 2) = pack_f16x2(xp[0], xp[1]);
    }
    asm volatile("cp.async.wait_group 0;" ::: "memory");
    __syncthreads();

    float acc[2][4][4];
#pragma unroll
    for (int mt = 0; mt < 2; mt++)
#pragma unroll
        for (int nt = 0; nt < 4; nt++)
#pragma unroll
            for (int q = 0; q < 4; q++) acc[mt][nt][q] = 0.0f;

    const uint32_t a_eoff = (uint32_t)((wm * 32 + (lane & 15)) * G3_AS +
                                       (lane >> 4) * 8) * 2;
    const uint32_t b_eoff = (uint32_t)((lane & 15) * G3_BS + wn * 32) * 2;

#pragma unroll
    for (int ks = 0; ks < 8; ks++) {
        uint32_t a[2][4];
#pragma unroll
        for (int mt = 0; mt < 2; mt++) {
            uint32_t eo = a_eoff + (uint32_t)(mt * 16 * G3_AS + ks * 16) * 2;
            ldsm_x4(a[mt], sb + G3_A + eo);
        }
        uint32_t b[4][2];
#pragma unroll
        for (int nt = 0; nt < 4; nt++) {
            uint32_t eo = b_eoff + (uint32_t)(ks * 16 * G3_BS + nt * 8) * 2;
            ldsm_x2t(b[nt], sb + G3_B + eo);
        }
#pragma unroll
        for (int mt = 0; mt < 2; mt++)
#pragma unroll
            for (int nt = 0; nt < 4; nt++)
                mma_f16(acc[mt][nt], a[mt], b[nt]);
    }

#pragma unroll
    for (int mt = 0; mt < 2; mt++)
#pragma unroll
        for (int nt = 0; nt < 4; nt++) {
            int r = row0 + wm * 32 + mt * 16 + (lane >> 2);
            int c = col0 + wn * 32 + nt * 8 + (lane & 3) * 2;
            float2 v0 = {acc[mt][nt][0], acc[mt][nt][1]};
            float2 v1 = {acc[mt][nt][2], acc[mt][nt][3]};
            *(float2*)&g_Z[(size_t)r * 4096 + c]       = v0;
            *(float2*)&g_Z[(size_t)(r + 8) * 4096 + c] = v1;
        }
}

// ---- scalars: pipelined mma.sync GEMM, 512 threads ----------------------------
#define AS_STRIDE 72      // fp16; 144B rows -> ldmatrix conflict-free
#define BS_STRIDE 216     // fp16; 432B rows -> ldmatrix conflict-free

#define SM_XS   0                           // p1: 64x132 f32; p2: 64x196 f32
#define SM_A0   50176
#define SM_A1   59392
#define SM_B0   68608
#define SM_B1   96256
#define TC_SMEM 123904

__global__ void __launch_bounds__(512) scalars_tc12(const float* __restrict__ x,
                                                    float* __restrict__ out) {
    extern __shared__ char tcsm[];
    float* Xs = (float*)(tcsm + SM_XS);
    const int t = threadIdx.x;
    const int lane = t & 31, warp = t >> 5;
    const int wm = warp & 1, wn = warp >> 1;       // 2 x 8
    const int row0 = blockIdx.x * 64;

    uint32_t sb;
    asm("{ .reg .u64 u; cvta.to.shared.u64 u, %1; cvt.u32.u64 %0, u; }"
        : "=r"(sb) : "l"(tcsm));

    const uint32_t AA[2] = {sb + SM_A0, sb + SM_A1};
    const uint32_t BB[2] = {sb + SM_B0, sb + SM_B1};

    for (int i = t; i < 64 * 32; i += 512) {
        int r = i >> 5, c4 = (i & 31) << 2;
        *(float4*)&Xs[r * 132 + c4] =
            *(const float4*)&x[(size_t)(row0 + r) * XDIM + c4];
    }
    __syncthreads();

    const int kk2 = lane * 2;
    const int mg = warp * 4;

    auto build_A = [&](int c, int st) {
        char* aa = tcsm + (st ? SM_A1 : SM_A0);
        int kg = c * 64 + kk2;
        uint32_t pk = __ldg((const uint32_t*)&g_sp[kg]);
        int u0 = (pk >> 8) & 255, v0 = pk & 255;
        int u1 = pk >> 24,       v1 = (pk >> 16) & 255;
        if (c < NCH0) {
#pragma unroll
            for (int j = 0; j < 4; j++) {
                int m = mg + j;
                const float* Xr = Xs + m * 132;
                *(uint32_t*)(aa + m * (AS_STRIDE * 2) + kk2 * 2) =
                    pack_f16x2(Xr[u0] * Xr[v0], Xr[u1] * Xr[v1]);
            }
        } else {
#pragma unroll
            for (int j = 0; j < 4; j++) {
                int m = mg + j;
                const float* Xr = Xs + m * 196;
                const float* a0 = Xr + 3 * u0; const float* b0 = Xr + 3 * v0;
                const float* a1 = Xr + 3 * u1; const float* b1 = Xr + 3 * v1;
                float f0 = a0[0] * b0[0] + a0[1] * b0[1] + a0[2] * b0[2];
                float f1 = a1[0] * b1[0] + a1[1] * b1[1] + a1[2] * b1[2];
                *(uint32_t*)(aa + m * (AS_STRIDE * 2) + kk2 * 2) = pack_f16x2(f0, f1);
            }
        }
    };
    // B tile: 64 rows x 192 fp16 = 1536 16B-chunks
    auto fetch_B = [&](int c, int st) {
        const uint32_t bb = BB[st];
        const int k0 = c * 64;
#pragma unroll
        for (int j = 0; j < 3; j++) {
            int i = t + j * 512;
            int r = i / 24, cc = (i - r * 24) * 8;
            uint32_t doff = (uint32_t)(r * (BS_STRIDE * 2) + cc * 2);
            cp16(bb + doff, g_WSC + (size_t)(k0 + r) * NSV + cc);
        }
        asm volatile("cp.async.commit_group;" ::: "memory");
    };

    float acc[2][3][4];
#pragma unroll
    for (int mt = 0; mt < 2; mt++)
#pragma unroll
        for (int nt = 0; nt < 3; nt++)
#pragma unroll
            for (int q = 0; q < 4; q++) acc[mt][nt][q] = 0.0f;

    const uint32_t a_eoff = (uint32_t)((wm * 32 + (lane & 15)) * AS_STRIDE +
                                       (lane >> 4) * 8) * 2;
    const uint32_t b_eoff = (uint32_t)((lane & 15) * BS_STRIDE + wn * 24) * 2;

    fetch_B(0, 0);
    build_A(0, 0);
    asm volatile("cp.async.wait_group 0;" ::: "memory");
    __syncthreads();

    for (int i = 0; i < NCHUNK; i++) {
        const int s = i & 1;
        if (i + 1 < NCHUNK) {
            if (i + 1 == NCH0) {
                for (int j = t; j < 64 * 48; j += 512) {
                    int r = j / 48, c4 = (j - r * 48) << 2;
                    *(float4*)&Xs[r * 196 + c4] =
                        *(const float4*)&x[(size_t)(row0 + r) * XDIM + 128 + c4];
                }
                __syncthreads();
            }
            fetch_B(i + 1, s ^ 1);
            build_A(i + 1, s ^ 1);
        }

#pragma unroll
        for (int ks = 0; ks < 4; ks++) {
            uint32_t a[2][4];
#pragma unroll
            for (int mt = 0; mt < 2; mt++) {
                uint32_t eo = a_eoff + (uint32_t)(mt * 16 * AS_STRIDE + ks * 16) * 2;
                ldsm_x4(a[mt], AA[s] + eo);
            }
            uint32_t b[3][2];
#pragma unroll
            for (int nt = 0; nt < 3; nt++) {
                uint32_t eo = b_eoff + (uint32_t)(ks * 16 * BS_STRIDE + nt * 8) * 2;
                ldsm_x2t(b[nt], BB[s] + eo);
            }
#pragma unroll
            for (int mt = 0; mt < 2; mt++)
#pragma unroll
                for (int nt = 0; nt < 3; nt++)
                    mma_f16(acc[mt][nt], a[mt], b[nt]);
        }

        if (i + 1 < NCHUNK) {
            asm volatile("cp.async.wait_group 0;" ::: "memory");
            __syncthreads();
        }
    }

    // epilogue: silu -> out[:, :128], sigmoid -> g_G
#pragma unroll
    for (int mt = 0; mt < 2; mt++) {
#pragma unroll
        for (int nt = 0; nt < 3; nt++) {
            int r = row0 + wm * 32 + mt * 16 + (lane >> 2);
            int c = wn * 24 + nt * 8 + (lane & 3) * 2;
#pragma unroll
            for (int q = 0; q < 4; q++) {
                int rr = r + (q >> 1) * 8;
                int cc = c + (q & 1);
                float s = acc[mt][nt][q];
                float sg = 1.0f / (1.0f + __expf(-s));
                if (cc < 128) out[(size_t)rr * XDIM + cc] = s * sg;
                else          g_G[rr * 64 + (cc - 128)] = sg;
            }
        }
    }
}

// ---- vectors on tensor cores ---------------------------------------------------
// v111[b,w,k] = cross_k feats [8192 x 2048] @ WVA[2048 x 64]  (3 comps, fp16)
#define V_AS 72
#define V_BS 72
#define VS_XS 0                                   // 64 x 196 f32 (x1 rows)
#define VS_A  50176                               // 6 bufs: [st][comp]
#define VS_B  105472                              // 2 bufs: [st]
#define VS_SMEM 123904
#define VA_OFF(st, comp)  (VS_A + (((st) * 3) + (comp)) * 9216)
#define VB_OFF(st)        (VS_B + (st) * 9216)

__global__ void __launch_bounds__(512) vectors_tc(const float* __restrict__ x,
                                                  float* __restrict__ out) {
    extern __shared__ char vsm[];
    float* Xs = (float*)(vsm + VS_XS);
    const int t = threadIdx.x;
    const int lane = t & 31, warp = t >> 5;
    const int wm = warp & 1, wn = warp >> 1;       // 2 x 8
    const int row0 = blockIdx.x * 64;

    uint32_t sb;
    asm("{ .reg .u64 u; cvta.to.shared.u64 u, %1; cvt.u32.u64 %0, u; }"
        : "=r"(sb) : "l"(vsm));

    for (int i = t; i < 64 * 48; i += 512) {
        int r = i / 48, c4 = (i - r * 48) << 2;
        *(float4*)&Xs[r * 196 + c4] =
            *(const float4*)&x[(size_t)(row0 + r) * XDIM + 128 + c4];
    }
    __syncthreads();

    const int kk2 = lane * 2;
    const int mg = warp * 4;

    auto build_A = [&](int c, int st) {
        char* a0p = vsm + VA_OFF(st, 0);
        char* a1p = vsm + VA_OFF(st, 1);
        char* a2p = vsm + VA_OFF(st, 2);
        int kg = c * 64 + kk2;
        uint32_t pk = __ldg((const uint32_t*)&g_pa[kg]);
        int u0 = (pk >> 8) & 255, v0 = pk & 255;
        int u1 = pk >> 24,       v1 = (pk >> 16) & 255;
#pragma unroll
        for (int j = 0; j < 4; j++) {
            int m = mg + j;
            const float* Xr = Xs + m * 196;
            const float* pu = Xr + 3 * u0; const float* pv = Xr + 3 * v0;
            float ax = pu[0], ay = pu[1], az = pu[2];
            float bx = pv[0], by = pv[1], bz = pv[2];
            float c00 = ay * bz - az * by;
            float c01 = az * bx - ax * bz;
            float c02 = ax * by - ay * bx;
            pu = Xr + 3 * u1; pv = Xr + 3 * v1;
            ax = pu[0]; ay = pu[1]; az = pu[2];
            bx = pv[0]; by = pv[1]; bz = pv[2];
            float c10 = ay * bz - az * by;
            float c11 = az * bx - ax * bz;
            float c12 = ax * by - ay * bx;
            int doff = m * (V_AS * 2) + kk2 * 2;
            *(uint32_t*)(a0p + doff) = pack_f16x2(c00, c10);
            *(uint32_t*)(a1p + doff) = pack_f16x2(c01, c11);
            *(uint32_t*)(a2p + doff) = pack_f16x2(c02, c12);
        }
    };
    // B tile: 64 rows x 64 fp16 = 512 16B-chunks
    auto fetch_B = [&](int c, int st) {
        const uint32_t bb = sb + VB_OFF(st);
        int r = t >> 3, cc = (t & 7) * 8;
        uint32_t doff = (uint32_t)(r * (V_BS * 2) + cc * 2);
        cp16(bb + doff, g_WVA + (size_t)(c * 64 + r) * NVD + cc);
        asm volatile("cp.async.commit_group;" ::: "memory");
    };

    float acc[2][3][4];
#pragma unroll
    for (int mt = 0; mt < 2; mt++)
#pragma unroll
        for (int cp = 0; cp < 3; cp++)
#pragma unroll
            for (int q = 0; q < 4; q++) acc[mt][cp][q] = 0.0f;

    const uint32_t a_eoff = (uint32_t)((wm * 32 + (lane & 15)) * V_AS +
                                       (lane >> 4) * 8) * 2;
    const uint32_t b_eoff = (uint32_t)((lane & 15) * V_BS + wn * 8) * 2;

    fetch_B(0, 0);
    build_A(0, 0);
    asm volatile("cp.async.wait_group 0;" ::: "memory");
    __syncthreads();

    for (int i = 0; i < NCHV; i++) {
        const int s = i & 1;
        if (i + 1 < NCHV) {
            fetch_B(i + 1, s ^ 1);
            build_A(i + 1, s ^ 1);
        }

#pragma unroll
        for (int ks = 0; ks < 4; ks++) {
            uint32_t b[2];
            uint32_t eo_b = b_eoff + (uint32_t)(ks * 16 * V_BS) * 2;
            ldsm_x2t(b, sb + VB_OFF(s) + eo_b);
#pragma unroll
            for (int cp = 0; cp < 3; cp++) {
#pragma unroll
                for (int mt = 0; mt < 2; mt++) {
                    uint32_t a[4];
                    uint32_t eo = a_eoff + (uint32_t)(mt * 16 * V_AS + ks * 16) * 2;
                    ldsm_x4(a, sb + VA_OFF(s, cp) + eo);
                    mma_f16(acc[mt][cp], a, b);
                }
            }
        }

        if (i + 1 < NCHV) {
            asm volatile("cp.async.wait_group 0;" ::: "memory");
            __syncthreads();
        }
    }

    // epilogue: + v011 from Z, gate, store
#pragma unroll
    for (int mt = 0; mt < 2; mt++) {
#pragma unroll
        for (int qp = 0; qp < 2; qp++) {
            int rloc = wm * 32 + mt * 16 + (lane >> 2) + qp * 8;
            int rr = row0 + rloc;
            int cc = wn * 8 + (lane & 3) * 2;
            float v0[3], v1[3];
#pragma unroll
            for (int cp = 0; cp < 3; cp++) {
                v0[cp] = acc[mt][cp][qp * 2];
                v1[cp] = acc[mt][cp][qp * 2 + 1];
            }
            const float* Zr = g_Z + (size_t)rr * 4096 + cc;
            const float* Xr = Xs + rloc * 196;
            for (int n = 0; n < 64; n++) {
                float2 z = *(const float2*)&Zr[n * 64];
                float xa = Xr[3 * n], xb = Xr[3 * n + 1], xc = Xr[3 * n + 2];
                v0[0] += xa * z.x; v0[1] += xb * z.x; v0[2] += xc * z.x;
                v1[0] += xa * z.y; v1[1] += xb * z.y; v1[2] += xc * z.y;
            }
            float g0 = g_G[rr * 64 + cc];
            float g1 = g_G[rr * 64 + cc + 1];
            float* orow = out + (size_t)rr * XDIM + 128;
#pragma unroll
            for (int k = 0; k < 3; k++) {
                orow[cc * 3 + k]       = v0[k] * g0;
                orow[(cc + 1) * 3 + k] = v1[k] * g1;
            }
        }
    }
}

// ---------------------------------------------------------------------------
extern "C" void kernel_launch(void* const* d_in, const int* in_sizes, int n_in,
                              void* d_out, int out_size) {
    const float* x = 0;
    const float* w000 = 0;
    const float* w110 = 0;
    const float* w011 = 0;
    const float* w111 = 0;
    for (int i = 0; i < n_in; i++) {
        switch (in_sizes[i]) {
            case BATCH * XDIM:       x    = (const float*)d_in[i]; break;
            case NN0 * NN0 * NSV:    w000 = (const float*)d_in[i]; break;
            case NN1 * NN1 * NSV:    w110 = (const float*)d_in[i]; break;
            case NN0 * NN1 * NVD:    w011 = (const float*)d_in[i]; break;
            case NN1 * NN1 * NVD:    w111 = (const float*)d_in[i]; break;
            default: break;
        }
    }
    if (!x)    x    = (const float*)d_in[0];
    if (!w000) w000 = (const float*)d_in[1];
    if (!w110) w110 = (const float*)d_in[2];
    if (!w011) w011 = (const float*)d_in[3];
    if (!w111) w111 = (const float*)d_in[4];
    float* out = (float*)d_out;

    cudaFuncSetAttribute(scalars_tc12,
                         cudaFuncAttributeMaxDynamicSharedMemorySize, TC_SMEM);
    cudaFuncSetAttribute(g3_tc,
                         cudaFuncAttributeMaxDynamicSharedMemorySize, G3T_SMEM);
    cudaFuncSetAttribute(vectors_tc,
                         cudaFuncAttributeMaxDynamicSharedMemorySize, VS_SMEM);

    build_pairs<<<(KSC_PAD + 255) / 256, 256>>>();
    build_wsc<<<KSC_PAD, NSV>>>(w000, w110);
    build_wva<<<NPA_PAD, NVD>>>(w111);
    build_w3<<<(NN0 * NN1 * NVD + 255) / 256, 256>>>(w011);
    g3_tc<<<dim3(BATCH / 64, 4096 / 128), 256, G3T_SMEM>>>(x);
    scalars_tc12<<<BATCH / 64, 512, TC_SMEM>>>(x, out);
    vectors_tc<<<BATCH / 64, 512, VS_SMEM>>>(x, out);
}

// round 14
// speedup vs baseline: 4.5279x; 1.1374x over previous
#include <cuda_runtime.h>
#include <cuda_fp16.h>
#include <math.h>
#include <stdint.h>

// ---------------------------------------------------------------------------
// PE_GatedBlock: B=8192, N0=128, N1=64, NS=128, NV=64
//   scalars = [sym-pair feats x0 | sym-dot feats x1] @ WSC   (mma.sync fp16)
//   Zt = (1/128) x0 @ w011  (TRANSPOSED layout [b][w*64+v], fp16)
//   v111 = cross feats @ WVA                                 (mma.sync fp16)
//   v011 from Zt contraction (fp32 epilogue, contiguous fp16 reads), gating fused.
//   out = [silu(s[:,:128]) | (v111+v011)*sigmoid(s[:,128:])]
// Precision: fp16 operands, fp32 accumulate; Z stored fp16 (adds ~2^-11 on v011).
// NOTE: harness ptxas targets sm_103 (no 'a') -> tcgen05 unavailable; mma.sync.
// ---------------------------------------------------------------------------

#define BATCH   8192
#define XDIM    320
#define NN0     128
#define NN1     64
#define NSV     192
#define NVD     64

#define NP0     8256
#define NP1     2080
#define NPA     2016
#define NPA_PAD 2048                 // 32*64 (zero-padded)
#define NCHV    32
#define KSC     (NP0 + NP1)          // 10336
#define KSC_PAD 10368                // 162*64 ; NP0 = 129*64 exactly
#define NCHUNK  162
#define NCH0    129                  // chunks 0..128 x0-pairs, 129.. x1-dots

// ---- static device scratch -------------------------------------------------
__device__ __align__(16) __half g_WSC[KSC_PAD * NSV];    // [k][n]
__device__ __align__(16) __half g_W3[NN0 * NN1 * NVD];   // [u][w*64+v] (transposed)
__device__ __align__(16) __half g_WVA[NPA_PAD * NVD];    // [p][w]
__device__ __align__(4) unsigned short g_sp[KSC_PAD];
__device__ __align__(4) unsigned short g_pa[NPA_PAD];
__device__ __align__(16) __half g_Zh[(size_t)BATCH * NN1 * NVD];  // [b][w*64+v]
__device__ float g_G[BATCH * NVD];

// ---- triangular index helpers ----------------------------------------------
__device__ __forceinline__ void tri_le(int p, int& u, int& v) {
    int vv = (int)floorf((sqrtf(8.0f * (float)p + 1.0f) - 1.0f) * 0.5f);
    while ((vv + 1) * (vv + 2) / 2 <= p) vv++;
    while (vv * (vv + 1) / 2 > p) vv--;
    v = vv;
    u = p - vv * (vv + 1) / 2;
}
__device__ __forceinline__ void tri_lt(int p, int& u, int& v) {
    int vv = (int)floorf((1.0f + sqrtf(8.0f * (float)p + 1.0f)) * 0.5f);
    while ((vv + 1) * vv / 2 <= p) vv++;
    while (vv * (vv - 1) / 2 > p) vv--;
    v = vv;
    u = p - vv * (vv - 1) / 2;
}

// pack two fp32 -> fp16x2 (f0 low half, f1 high half)
__device__ __forceinline__ uint32_t pack_f16x2(float f0, float f1) {
    __half2 h2 = __floats2half2_rn(f0, f1);
    return *(uint32_t*)&h2;
}
__device__ __forceinline__ float2 h2f(uint32_t u) {
    __half2 h = *(__half2*)&u;
    return __half22float2(h);
}

// ---- pair-list kernel (one-time index math) ---------------------------------
__global__ void build_pairs() {
    int p = blockIdx.x * blockDim.x + threadIdx.x;
    if (p < KSC_PAD) {
        unsigned short pk = 0;
        if (p < NP0) {
            int u, v; tri_le(p, u, v);
            pk = (unsigned short)((u << 8) | v);
        } else if (p < KSC) {
            int u, v; tri_le(p - NP0, u, v);
            pk = (unsigned short)((u << 8) | v);
        }
        g_sp[p] = pk;
    }
    if (p < NPA_PAD) {
        unsigned short pk = 0;
        if (p < NPA) {
            int u, v; tri_lt(p, u, v);
            pk = (unsigned short)((u << 8) | v);
        }
        g_pa[p] = pk;
    }
}

// ---- weight folding: fold -> single fp16 -------------------------------------
__global__ void build_wsc(const float* __restrict__ w000,
                          const float* __restrict__ w110) {
    int p = blockIdx.x;          // 0..KSC_PAD-1
    int w = threadIdx.x;         // 0..191
    const float inv_sqrt2 = 0.7071067811865476f;
    float f = 0.0f;
    unsigned int pk = g_sp[p];
    int u = pk >> 8, v = pk & 255;
    if (p < NP0) {
        float val = w000[(u * NN0 + v) * NSV + w];
        if (u != v) val += w000[(v * NN0 + u) * NSV + w];
        f = (inv_sqrt2 / 128.0f) * val;
    } else if (p < KSC) {
        float val = w110[(u * NN1 + v) * NSV + w];
        if (u != v) val += w110[(v * NN1 + u) * NSV + w];
        f = (inv_sqrt2 / (64.0f * 1.7320508075688772f)) * val;
    }
    g_WSC[p * NSV + w] = __float2half_rn(f);
}

__global__ void build_wva(const float* __restrict__ w111) {
    int p = blockIdx.x;          // 0..NPA_PAD-1
    int w = threadIdx.x;         // 0..63
    float f = 0.0f;
    unsigned int pk = g_pa[p];
    int u = pk >> 8, v = pk & 255;
    if (p < NPA) {
        f = (1.0f / 128.0f) *
            (w111[(u * NN1 + v) * NVD + w] - w111[(v * NN1 + u) * NVD + w]);
    }
    g_WVA[p * NVD + w] = __float2half_rn(f);
}

// w011[u][v][w] -> g_W3[u][w*64+v], coalesced both ways via smem transpose
__global__ void build_w3(const float* __restrict__ w011) {
    __shared__ float tile[64][65];
    int u = blockIdx.x;          // 0..127
    const float* src = w011 + (size_t)u * 4096;
    for (int i = threadIdx.x; i < 4096; i += 256) {
        int v = i >> 6, w = i & 63;
        tile[v][w] = src[i];
    }
    __syncthreads();
    __half* dst = g_W3 + (size_t)u * 4096;
    for (int i = threadIdx.x; i < 4096; i += 256) {
        int w = i >> 6, v = i & 63;
        dst[i] = __float2half_rn(tile[v][w] * (1.0f / 128.0f));
    }
}

// ---- mma.sync helpers --------------------------------------------------------
__device__ __forceinline__ void mma_f16(float* d, const uint32_t* a, const uint32_t* b) {
    asm volatile(
        "mma.sync.aligned.m16n8k16.row.col.f32.f16.f16.f32 "
        "{%0,%1,%2,%3}, {%4,%5,%6,%7}, {%8,%9}, {%0,%1,%2,%3};\n"
        : "+f"(d[0]), "+f"(d[1]), "+f"(d[2]), "+f"(d[3])
        : "r"(a[0]), "r"(a[1]), "r"(a[2]), "r"(a[3]), "r"(b[0]), "r"(b[1]));
}
__device__ __forceinline__ void ldsm_x4(uint32_t* r, uint32_t addr) {
    asm volatile("ldmatrix.sync.aligned.m8n8.x4.shared.b16 {%0,%1,%2,%3}, [%4];"
                 : "=r"(r[0]), "=r"(r[1]), "=r"(r[2]), "=r"(r[3]) : "r"(addr));
}
__device__ __forceinline__ void ldsm_x2t(uint32_t* r, uint32_t addr) {
    asm volatile("ldmatrix.sync.aligned.m8n8.x2.trans.shared.b16 {%0,%1}, [%2];"
                 : "=r"(r[0]), "=r"(r[1]) : "r"(addr));
}
__device__ __forceinline__ void cp16(uint32_t dst, const void* src) {
    asm volatile("cp.async.cg.shared.global [%0], [%1], 16;"
                 :: "r"(dst), "l"(src) : "memory");
}

// ---- g3 on tensor cores: g_Zh = x0[8192x128] @ W3[128x4096] (fp16 out) -------
#define G3_AS  136
#define G3_BS  136
#define G3_A   0
#define G3_B   17408
#define G3T_SMEM 52224

__global__ void __launch_bounds__(256) g3_tc(const float* __restrict__ x) {
    extern __shared__ char g3m[];
    const int t = threadIdx.x;
    const int lane = t & 31, warp = t >> 5;
    const int wm = warp & 1, wn = warp >> 1;
    const int row0 = blockIdx.x * 64;
    const int col0 = blockIdx.y * 128;

    uint32_t sb;
    asm("{ .reg .u64 u; cvta.to.shared.u64 u, %1; cvt.u32.u64 %0, u; }"
        : "=r"(sb) : "l"(g3m));

    // B tile: 128 k-rows x 128 n-cols fp16 (2048 16B chunks)
#pragma unroll
    for (int j = 0; j < 8; j++) {
        int i = t + j * 256;
        int r = i >> 4, cc = (i & 15) * 8;
        uint32_t doff = (uint32_t)(r * (G3_BS * 2) + cc * 2);
        cp16(sb + G3_B + doff, g_W3 + (size_t)r * 4096 + col0 + cc);
    }
    asm volatile("cp.async.commit_group;" ::: "memory");

    // A tile: 64 rows x 128 k fp32 -> fp16
    for (int i = t; i < 4096; i += 256) {
        int r = i >> 6, c2 = (i & 63) * 2;
        const float* xp = x + (size_t)(row0 + r) * XDIM + c2;
        *(uint32_t*)(g3m + G3_A + r * (G3_AS * 2) + c2 * 2) = pack_f16x2(xp[0], xp[1]);
    }
    asm volatile("cp.async.wait_group 0;" ::: "memory");
    __syncthreads();

    float acc[2][4][4];
#pragma unroll
    for (int mt = 0; mt < 2; mt++)
#pragma unroll
        for (int nt = 0; nt < 4; nt++)
#pragma unroll
            for (int q = 0; q < 4; q++) acc[mt][nt][q] = 0.0f;

    const uint32_t a_eoff = (uint32_t)((wm * 32 + (lane & 15)) * G3_AS +
                                       (lane >> 4) * 8) * 2;
    const uint32_t b_eoff = (uint32_t)((lane & 15) * G3_BS + wn * 32) * 2;

#pragma unroll
    for (int ks = 0; ks < 8; ks++) {
        uint32_t a[2][4];
#pragma unroll
        for (int mt = 0; mt < 2; mt++) {
            uint32_t eo = a_eoff + (uint32_t)(mt * 16 * G3_AS + ks * 16) * 2;
            ldsm_x4(a[mt], sb + G3_A + eo);
        }
        uint32_t b[4][2];
#pragma unroll
        for (int nt = 0; nt < 4; nt++) {
            uint32_t eo = b_eoff + (uint32_t)(ks * 16 * G3_BS + nt * 8) * 2;
            ldsm_x2t(b[nt], sb + G3_B + eo);
        }
#pragma unroll
        for (int mt = 0; mt < 2; mt++)
#pragma unroll
            for (int nt = 0; nt < 4; nt++)
                mma_f16(acc[mt][nt], a[mt], b[nt]);
    }

    // store fp16 Zt (half2 per q-pair)
#pragma unroll
    for (int mt = 0; mt < 2; mt++)
#pragma unroll
        for (int nt = 0; nt < 4; nt++) {
            int r = row0 + wm * 32 + mt * 16 + (lane >> 2);
            int c = col0 + wn * 32 + nt * 8 + (lane & 3) * 2;
            *(uint32_t*)&g_Zh[(size_t)r * 4096 + c] =
                pack_f16x2(acc[mt][nt][0], acc[mt][nt][1]);
            *(uint32_t*)&g_Zh[(size_t)(r + 8) * 4096 + c] =
                pack_f16x2(acc[mt][nt][2], acc[mt][nt][3]);
        }
}

// ---- scalars: pipelined mma.sync GEMM, 512 threads ----------------------------
#define AS_STRIDE 72      // fp16; 144B rows -> ldmatrix conflict-free
#define BS_STRIDE 216     // fp16; 432B rows -> ldmatrix conflict-free

#define SM_XS   0                           // p1: 64x132 f32; p2: 64x196 f32
#define SM_A0   50176
#define SM_A1   59392
#define SM_B0   68608
#define SM_B1   96256
#define TC_SMEM 123904

__global__ void __launch_bounds__(512) scalars_tc12(const float* __restrict__ x,
                                                    float* __restrict__ out) {
    extern __shared__ char tcsm[];
    float* Xs = (float*)(tcsm + SM_XS);
    const int t = threadIdx.x;
    const int lane = t & 31, warp = t >> 5;
    const int wm = warp & 1, wn = warp >> 1;       // 2 x 8
    const int row0 = blockIdx.x * 64;

    uint32_t sb;
    asm("{ .reg .u64 u; cvta.to.shared.u64 u, %1; cvt.u32.u64 %0, u; }"
        : "=r"(sb) : "l"(tcsm));

    const uint32_t AA[2] = {sb + SM_A0, sb + SM_A1};
    const uint32_t BB[2] = {sb + SM_B0, sb + SM_B1};

    for (int i = t; i < 64 * 32; i += 512) {
        int r = i >> 5, c4 = (i & 31) << 2;
        *(float4*)&Xs[r * 132 + c4] =
            *(const float4*)&x[(size_t)(row0 + r) * XDIM + c4];
    }
    __syncthreads();

    const int kk2 = lane * 2;
    const int mg = warp * 4;

    auto build_A = [&](int c, int st) {
        char* aa = tcsm + (st ? SM_A1 : SM_A0);
        int kg = c * 64 + kk2;
        uint32_t pk = __ldg((const uint32_t*)&g_sp[kg]);
        int u0 = (pk >> 8) & 255, v0 = pk & 255;
        int u1 = pk >> 24,       v1 = (pk >> 16) & 255;
        if (c < NCH0) {
#pragma unroll
            for (int j = 0; j < 4; j++) {
                int m = mg + j;
                const float* Xr = Xs + m * 132;
                *(uint32_t*)(aa + m * (AS_STRIDE * 2) + kk2 * 2) =
                    pack_f16x2(Xr[u0] * Xr[v0], Xr[u1] * Xr[v1]);
            }
        } else {
#pragma unroll
            for (int j = 0; j < 4; j++) {
                int m = mg + j;
                const float* Xr = Xs + m * 196;
                const float* a0 = Xr + 3 * u0; const float* b0 = Xr + 3 * v0;
                const float* a1 = Xr + 3 * u1; const float* b1 = Xr + 3 * v1;
                float f0 = a0[0] * b0[0] + a0[1] * b0[1] + a0[2] * b0[2];
                float f1 = a1[0] * b1[0] + a1[1] * b1[1] + a1[2] * b1[2];
                *(uint32_t*)(aa + m * (AS_STRIDE * 2) + kk2 * 2) = pack_f16x2(f0, f1);
            }
        }
    };
    // B tile: 64 rows x 192 fp16 = 1536 16B-chunks
    auto fetch_B = [&](int c, int st) {
        const uint32_t bb = BB[st];
        const int k0 = c * 64;
#pragma unroll
        for (int j = 0; j < 3; j++) {
            int i = t + j * 512;
            int r = i / 24, cc = (i - r * 24) * 8;
            uint32_t doff = (uint32_t)(r * (BS_STRIDE * 2) + cc * 2);
            cp16(bb + doff, g_WSC + (size_t)(k0 + r) * NSV + cc);
        }
        asm volatile("cp.async.commit_group;" ::: "memory");
    };

    float acc[2][3][4];
#pragma unroll
    for (int mt = 0; mt < 2; mt++)
#pragma unroll
        for (int nt = 0; nt < 3; nt++)
#pragma unroll
            for (int q = 0; q < 4; q++) acc[mt][nt][q] = 0.0f;

    const uint32_t a_eoff = (uint32_t)((wm * 32 + (lane & 15)) * AS_STRIDE +
                                       (lane >> 4) * 8) * 2;
    const uint32_t b_eoff = (uint32_t)((lane & 15) * BS_STRIDE + wn * 24) * 2;

    fetch_B(0, 0);
    build_A(0, 0);
    asm volatile("cp.async.wait_group 0;" ::: "memory");
    __syncthreads();

    for (int i = 0; i < NCHUNK; i++) {
        const int s = i & 1;
        if (i + 1 < NCHUNK) {
            if (i + 1 == NCH0) {
                for (int j = t; j < 64 * 48; j += 512) {
                    int r = j / 48, c4 = (j - r * 48) << 2;
                    *(float4*)&Xs[r * 196 + c4] =
                        *(const float4*)&x[(size_t)(row0 + r) * XDIM + 128 + c4];
                }
                __syncthreads();
            }
            fetch_B(i + 1, s ^ 1);
            build_A(i + 1, s ^ 1);
        }

#pragma unroll
        for (int ks = 0; ks < 4; ks++) {
            uint32_t a[2][4];
#pragma unroll
            for (int mt = 0; mt < 2; mt++) {
                uint32_t eo = a_eoff + (uint32_t)(mt * 16 * AS_STRIDE + ks * 16) * 2;
                ldsm_x4(a[mt], AA[s] + eo);
            }
            uint32_t b[3][2];
#pragma unroll
            for (int nt = 0; nt < 3; nt++) {
                uint32_t eo = b_eoff + (uint32_t)(ks * 16 * BS_STRIDE + nt * 8) * 2;
                ldsm_x2t(b[nt], BB[s] + eo);
            }
#pragma unroll
            for (int mt = 0; mt < 2; mt++)
#pragma unroll
                for (int nt = 0; nt < 3; nt++)
                    mma_f16(acc[mt][nt], a[mt], b[nt]);
        }

        if (i + 1 < NCHUNK) {
            asm volatile("cp.async.wait_group 0;" ::: "memory");
            __syncthreads();
        }
    }

    // epilogue: silu -> out[:, :128], sigmoid -> g_G
#pragma unroll
    for (int mt = 0; mt < 2; mt++) {
#pragma unroll
        for (int nt = 0; nt < 3; nt++) {
            int r = row0 + wm * 32 + mt * 16 + (lane >> 2);
            int c = wn * 24 + nt * 8 + (lane & 3) * 2;
#pragma unroll
            for (int q = 0; q < 4; q++) {
                int rr = r + (q >> 1) * 8;
                int cc = c + (q & 1);
                float s = acc[mt][nt][q];
                float sg = 1.0f / (1.0f + __expf(-s));
                if (cc < 128) out[(size_t)rr * XDIM + cc] = s * sg;
                else          g_G[rr * 64 + (cc - 128)] = sg;
            }
        }
    }
}

// ---- vectors on tensor cores ---------------------------------------------------
// v111[b,w,k] = cross_k feats [8192 x 2048] @ WVA[2048 x 64]  (3 comps, fp16)
#define V_AS 72
#define V_BS 72
#define VS_XS 0                                   // 64 x 196 f32 (x1 rows)
#define VS_A  50176                               // 6 bufs: [st][comp]
#define VS_B  105472                              // 2 bufs: [st]
#define VS_SMEM 123904
#define VA_OFF(st, comp)  (VS_A + (((st) * 3) + (comp)) * 9216)
#define VB_OFF(st)        (VS_B + (st) * 9216)

__global__ void __launch_bounds__(512) vectors_tc(const float* __restrict__ x,
                                                  float* __restrict__ out) {
    extern __shared__ char vsm[];
    float* Xs = (float*)(vsm + VS_XS);
    const int t = threadIdx.x;
    const int lane = t & 31, warp = t >> 5;
    const int wm = warp & 1, wn = warp >> 1;       // 2 x 8
    const int row0 = blockIdx.x * 64;

    uint32_t sb;
    asm("{ .reg .u64 u; cvta.to.shared.u64 u, %1; cvt.u32.u64 %0, u; }"
        : "=r"(sb) : "l"(vsm));

    for (int i = t; i < 64 * 48; i += 512) {
        int r = i / 48, c4 = (i - r * 48) << 2;
        *(float4*)&Xs[r * 196 + c4] =
            *(const float4*)&x[(size_t)(row0 + r) * XDIM + 128 + c4];
    }
    __syncthreads();

    const int kk2 = lane * 2;
    const int mg = warp * 4;

    auto build_A = [&](int c, int st) {
        char* a0p = vsm + VA_OFF(st, 0);
        char* a1p = vsm + VA_OFF(st, 1);
        char* a2p = vsm + VA_OFF(st, 2);
        int kg = c * 64 + kk2;
        uint32_t pk = __ldg((const uint32_t*)&g_pa[kg]);
        int u0 = (pk >> 8) & 255, v0 = pk & 255;
        int u1 = pk >> 24,       v1 = (pk >> 16) & 255;
#pragma unroll
        for (int j = 0; j < 4; j++) {
            int m = mg + j;
            const float* Xr = Xs + m * 196;
            const float* pu = Xr + 3 * u0; const float* pv = Xr + 3 * v0;
            float ax = pu[0], ay = pu[1], az = pu[2];
            float bx = pv[0], by = pv[1], bz = pv[2];
            float c00 = ay * bz - az * by;
            float c01 = az * bx - ax * bz;
            float c02 = ax * by - ay * bx;
            pu = Xr + 3 * u1; pv = Xr + 3 * v1;
            ax = pu[0]; ay = pu[1]; az = pu[2];
            bx = pv[0]; by = pv[1]; bz = pv[2];
            float c10 = ay * bz - az * by;
            float c11 = az * bx - ax * bz;
            float c12 = ax * by - ay * bx;
            int doff = m * (V_AS * 2) + kk2 * 2;
            *(uint32_t*)(a0p + doff) = pack_f16x2(c00, c10);
            *(uint32_t*)(a1p + doff) = pack_f16x2(c01, c11);
            *(uint32_t*)(a2p + doff) = pack_f16x2(c02, c12);
        }
    };
    auto fetch_B = [&](int c, int st) {
        const uint32_t bb = sb + VB_OFF(st);
        int r = t >> 3, cc = (t & 7) * 8;
        uint32_t doff = (uint32_t)(r * (V_BS * 2) + cc * 2);
        cp16(bb + doff, g_WVA + (size_t)(c * 64 + r) * NVD + cc);
        asm volatile("cp.async.commit_group;" ::: "memory");
    };

    float acc[2][3][4];
#pragma unroll
    for (int mt = 0; mt < 2; mt++)
#pragma unroll
        for (int cp = 0; cp < 3; cp++)
#pragma unroll
            for (int q = 0; q < 4; q++) acc[mt][cp][q] = 0.0f;

    const uint32_t a_eoff = (uint32_t)((wm * 32 + (lane & 15)) * V_AS +
                                       (lane >> 4) * 8) * 2;
    const uint32_t b_eoff = (uint32_t)((lane & 15) * V_BS + wn * 8) * 2;

    fetch_B(0, 0);
    build_A(0, 0);
    asm volatile("cp.async.wait_group 0;" ::: "memory");
    __syncthreads();

    for (int i = 0; i < NCHV; i++) {
        const int s = i & 1;
        if (i + 1 < NCHV) {
            fetch_B(i + 1, s ^ 1);
            build_A(i + 1, s ^ 1);
        }

#pragma unroll
        for (int ks = 0; ks < 4; ks++) {
            uint32_t b[2];
            uint32_t eo_b = b_eoff + (uint32_t)(ks * 16 * V_BS) * 2;
            ldsm_x2t(b, sb + VB_OFF(s) + eo_b);
#pragma unroll
            for (int cp = 0; cp < 3; cp++) {
#pragma unroll
                for (int mt = 0; mt < 2; mt++) {
                    uint32_t a[4];
                    uint32_t eo = a_eoff + (uint32_t)(mt * 16 * V_AS + ks * 16) * 2;
                    ldsm_x4(a, sb + VA_OFF(s, cp) + eo);
                    mma_f16(acc[mt][cp], a, b);
                }
            }
        }

        if (i + 1 < NCHV) {
            asm volatile("cp.async.wait_group 0;" ::: "memory");
            __syncthreads();
        }
    }

    // epilogue: + v011 from transposed fp16 Z (contiguous reads), gate, store
#pragma unroll
    for (int mt = 0; mt < 2; mt++) {
#pragma unroll
        for (int qp = 0; qp < 2; qp++) {
            int rloc = wm * 32 + mt * 16 + (lane >> 2) + qp * 8;
            int rr = row0 + rloc;
            int cc = wn * 8 + (lane & 3) * 2;
            float v0[3], v1[3];
#pragma unroll
            for (int cp = 0; cp < 3; cp++) {
                v0[cp] = acc[mt][cp][qp * 2];
                v1[cp] = acc[mt][cp][qp * 2 + 1];
            }
            const float* Xr = Xs + rloc * 196;
            // rows cc and cc+1 of Zt: 64 contiguous halves each (8 uint4)
            const uint4* z0q = (const uint4*)(g_Zh + (size_t)rr * 4096 + cc * 64);
            const uint4* z1q = z0q + 8;
#pragma unroll
            for (int q = 0; q < 8; q++) {
                uint4 za = z0q[q], zb = z1q[q];
                uint32_t wa[4] = {za.x, za.y, za.z, za.w};
                uint32_t wb[4] = {zb.x, zb.y, zb.z, zb.w};
                const float* Xn = Xr + q * 24;
#pragma unroll
                for (int h = 0; h < 4; h++) {
                    float2 z0 = h2f(wa[h]);
                    float2 z1 = h2f(wb[h]);
                    const float* Xp = Xn + h * 6;
                    v0[0] += Xp[0] * z0.x + Xp[3] * z0.y;
                    v0[1] += Xp[1] * z0.x + Xp[4] * z0.y;
                    v0[2] += Xp[2] * z0.x + Xp[5] * z0.y;
                    v1[0] += Xp[0] * z1.x + Xp[3] * z1.y;
                    v1[1] += Xp[1] * z1.x + Xp[4] * z1.y;
                    v1[2] += Xp[2] * z1.x + Xp[5] * z1.y;
                }
            }
            float g0 = g_G[rr * 64 + cc];
            float g1 = g_G[rr * 64 + cc + 1];
            float* orow = out + (size_t)rr * XDIM + 128;
#pragma unroll
            for (int k = 0; k < 3; k++) {
                orow[cc * 3 + k]       = v0[k] * g0;
                orow[(cc + 1) * 3 + k] = v1[k] * g1;
            }
        }
    }
}

// ---------------------------------------------------------------------------
extern "C" void kernel_launch(void* const* d_in, const int* in_sizes, int n_in,
                              void* d_out, int out_size) {
    const float* x = 0;
    const float* w000 = 0;
    const float* w110 = 0;
    const float* w011 = 0;
    const float* w111 = 0;
    for (int i = 0; i < n_in; i++) {
        switch (in_sizes[i]) {
            case BATCH * XDIM:       x    = (const float*)d_in[i]; break;
            case NN0 * NN0 * NSV:    w000 = (const float*)d_in[i]; break;
            case NN1 * NN1 * NSV:    w110 = (const float*)d_in[i]; break;
            case NN0 * NN1 * NVD:    w011 = (const float*)d_in[i]; break;
            case NN1 * NN1 * NVD:    w111 = (const float*)d_in[i]; break;
            default: break;
        }
    }
    if (!x)    x    = (const float*)d_in[0];
    if (!w000) w000 = (const float*)d_in[1];
    if (!w110) w110 = (const float*)d_in[2];
    if (!w011) w011 = (const float*)d_in[3];
    if (!w111) w111 = (const float*)d_in[4];
    float* out = (float*)d_out;

    cudaFuncSetAttribute(scalars_tc12,
                         cudaFuncAttributeMaxDynamicSharedMemorySize, TC_SMEM);
    cudaFuncSetAttribute(g3_tc,
                         cudaFuncAttributeMaxDynamicSharedMemorySize, G3T_SMEM);
    cudaFuncSetAttribute(vectors_tc,
                         cudaFuncAttributeMaxDynamicSharedMemorySize, VS_SMEM);

    build_pairs<<<(KSC_PAD + 255) / 256, 256>>>();
    build_wsc<<<KSC_PAD, NSV>>>(w000, w110);
    build_wva<<<NPA_PAD, NVD>>>(w111);
    build_w3<<<NN0, 256>>>(w011);
    g3_tc<<<dim3(BATCH / 64, 4096 / 128), 256, G3T_SMEM>>>(x);
    scalars_tc12<<<BATCH / 64, 512, TC_SMEM>>>(x, out);
    vectors_tc<<<BATCH / 64, 512, VS_SMEM>>>(x, out);
}